// round 6
// baseline (speedup 1.0000x reference)
#include <cuda_runtime.h>
#include <cuda_bf16.h>
#include <cstdint>
#include <math.h>

// ---------------- problem constants ----------------
constexpr int Bq   = 64;     // batch
constexpr int NS   = 50;     // sentences per doc
constexpr int LS   = 60;     // sentence length
constexpr int LQ   = 32;     // question length
constexpr int D    = 300;    // embedding dim
constexpr int F    = 256;    // conv filters
constexpr int FS   = 3;      // filter size
constexpr int Vv   = 100000; // vocab
constexpr int QROWS = Bq * LQ;        // 2048
constexpr int SROWS = Bq * NS * LS;   // 192000
constexpr int LT    = NS * LS;        // 3000

// ---------------- device scratch (no allocs allowed) ----------------
__device__ float g_qe[QROWS * D];          // question embeddings
__device__ float g_qn[QROWS];              // |qe|
__device__ float g_se[SROWS * D];          // sentence embeddings (230 MB)
__device__ float g_sn[SROWS];              // |se|
__device__ float g_qc[QROWS * F];          // conv(question)
__device__ float g_qcn[QROWS];
__device__ float g_sc[SROWS * F];          // conv(sentences) (197 MB)
__device__ float g_scn[SROWS];
__device__ float g_simins[Bq * NS * LQ * LS];  // [b][n][q][l]
__device__ float g_simsen[Bq * NS * LQ * LS];
__device__ float g_sentrel[Bq * NS];

// ---------------- gather + norm ----------------
__global__ void gather_norm_kernel(const float* __restrict__ embeds,
                                   const int* __restrict__ tokens,
                                   int nrows, int which) {
    int warp = (blockIdx.x * blockDim.x + threadIdx.x) >> 5;
    int lane = threadIdx.x & 31;
    if (warp >= nrows) return;
    float* dst = which ? g_se : g_qe;
    float* nrm = which ? g_sn : g_qn;
    int tok = tokens[warp];
    const float* src = embeds + (size_t)tok * D;
    float* drow = dst + (size_t)warp * D;
    float ss = 0.0f;
    for (int i = lane; i < D; i += 32) {
        float v = src[i];
        drow[i] = v;
        ss += v * v;
    }
    #pragma unroll
    for (int o = 16; o; o >>= 1) ss += __shfl_xor_sync(0xffffffffu, ss, o);
    if (lane == 0) nrm[warp] = sqrtf(ss);
}

// ============================================================================
// conv as GEMM on tensor cores (split-bf16 emulated fp32):
//   out[r,f] = sum_{t<3, l+t<SEG} X[r+t,:] . filt[f,t,:]
// Block tile 128x128, 8 warps (4M x 2N), warp tile 32x64, mma m16n8k16 bf16.
// a = a_hi + a_lo (bf16 split); D = Ahi*Bhi + Ahi*Blo + Alo*Bhi (fp32 accum).
// ============================================================================

__device__ __forceinline__ void mma_bf16(float& c0, float& c1, float& c2, float& c3,
                                         uint32_t a0, uint32_t a1, uint32_t a2, uint32_t a3,
                                         uint32_t b0, uint32_t b1) {
    asm volatile("mma.sync.aligned.m16n8k16.row.col.f32.bf16.bf16.f32 "
                 "{%0,%1,%2,%3},{%4,%5,%6,%7},{%8,%9},{%0,%1,%2,%3};"
                 : "+f"(c0), "+f"(c1), "+f"(c2), "+f"(c3)
                 : "r"(a0), "r"(a1), "r"(a2), "r"(a3), "r"(b0), "r"(b1));
}

// SMEM row stride: 18 bf16 (36 B = 9 banks; gcd(9,32)=1 -> conflict-friendly)
constexpr int SMS = 18;
constexpr int KCHUNKS = 19;           // ceil(300/16) per tap
constexpr int NCHUNK  = FS * KCHUNKS; // 57

template<int SEG>
__global__ void __launch_bounds__(256) conv_mma_kernel(const float* __restrict__ filt,
                                                       int R, int which) {
    const float* X  = which ? g_se : g_qe;
    float*      out = which ? g_sc : g_qc;

    __shared__ __align__(16) __nv_bfloat16 AsHi[128 * SMS];
    __shared__ __align__(16) __nv_bfloat16 AsLo[128 * SMS];
    __shared__ __align__(16) __nv_bfloat16 BsHi[128 * SMS];
    __shared__ __align__(16) __nv_bfloat16 BsLo[128 * SMS];

    const int tid  = threadIdx.x;
    const int lane = tid & 31;
    const int wid  = tid >> 5;
    const int wm   = (wid & 3) * 32;   // warp M offset (4 warps in M)
    const int wn   = (wid >> 2) * 64;  // warp N offset (2 warps in N)
    const int g    = lane >> 2;        // group id 0..7
    const int tig  = lane & 3;         // thread-in-group 0..3

    const int rbase = blockIdx.x * 128;
    const int fbase = blockIdx.y * 128;

    // loader role: each thread loads row (tid>>1), k-half ((tid&1)*8)
    const int arow  = tid >> 1;
    const int khalf = (tid & 1) * 8;
    const int gr    = rbase + arow;     // global X row
    const int lpos  = gr % SEG;         // position within segment
    const int gf    = fbase + arow;     // global filter row (always < 256)

    float acc[2][8][4];
    #pragma unroll
    for (int i = 0; i < 2; ++i)
        #pragma unroll
        for (int j = 0; j < 8; ++j)
            #pragma unroll
            for (int v = 0; v < 4; ++v) acc[i][j][v] = 0.0f;

    float fa[8], fb[8];

    // ---- chunk loader: chunk c -> tap t, k-offset kc ----
    auto load_chunk = [&](int c) {
        int t  = (c >= 2 * KCHUNKS) ? 2 : (c >= KCHUNKS ? 1 : 0);
        int kc = (c - t * KCHUNKS) * 16;
        int k0 = kc + khalf;
        bool full = (k0 + 7 < D);
        bool aval = (lpos + t) < SEG;   // forward conv window inside segment

        const float* ap = X + (size_t)(gr + t) * D + k0;
        if (aval && full) {
            float4 v0 = *(const float4*)ap;
            float4 v1 = *(const float4*)(ap + 4);
            fa[0]=v0.x; fa[1]=v0.y; fa[2]=v0.z; fa[3]=v0.w;
            fa[4]=v1.x; fa[5]=v1.y; fa[6]=v1.z; fa[7]=v1.w;
        } else {
            #pragma unroll
            for (int e = 0; e < 8; ++e)
                fa[e] = (aval && (k0 + e < D)) ? ap[e] : 0.0f;
        }

        const float* bp = filt + (size_t)gf * (FS * D) + t * D + k0;
        if (full) {
            float4 v0 = *(const float4*)bp;
            float4 v1 = *(const float4*)(bp + 4);
            fb[0]=v0.x; fb[1]=v0.y; fb[2]=v0.z; fb[3]=v0.w;
            fb[4]=v1.x; fb[5]=v1.y; fb[6]=v1.z; fb[7]=v1.w;
        } else {
            #pragma unroll
            for (int e = 0; e < 8; ++e)
                fb[e] = (k0 + e < D) ? bp[e] : 0.0f;
        }
    };

    // ---- store to smem with hi/lo split ----
    auto sts_chunk = [&]() {
        #pragma unroll
        for (int e = 0; e < 8; e += 2) {
            int idx = arow * SMS + khalf + e;
            __nv_bfloat16 h0 = __float2bfloat16(fa[e]);
            __nv_bfloat16 h1 = __float2bfloat16(fa[e + 1]);
            __nv_bfloat16 l0 = __float2bfloat16(fa[e]     - __bfloat162float(h0));
            __nv_bfloat16 l1 = __float2bfloat16(fa[e + 1] - __bfloat162float(h1));
            *(__nv_bfloat162*)&AsHi[idx] = __halves2bfloat162(h0, h1);
            *(__nv_bfloat162*)&AsLo[idx] = __halves2bfloat162(l0, l1);
            __nv_bfloat16 p0 = __float2bfloat16(fb[e]);
            __nv_bfloat16 p1 = __float2bfloat16(fb[e + 1]);
            __nv_bfloat16 q0 = __float2bfloat16(fb[e]     - __bfloat162float(p0));
            __nv_bfloat16 q1 = __float2bfloat16(fb[e + 1] - __bfloat162float(p1));
            *(__nv_bfloat162*)&BsHi[idx] = __halves2bfloat162(p0, p1);
            *(__nv_bfloat162*)&BsLo[idx] = __halves2bfloat162(q0, q1);
        }
    };

    const uint32_t* AH = (const uint32_t*)AsHi;
    const uint32_t* AL = (const uint32_t*)AsLo;
    const uint32_t* BH = (const uint32_t*)BsHi;
    const uint32_t* BL = (const uint32_t*)BsLo;
    constexpr int RS = SMS / 2;   // row stride in u32 units = 9

    load_chunk(0);
    for (int c = 0; c < NCHUNK; ++c) {
        sts_chunk();
        __syncthreads();
        if (c + 1 < NCHUNK) load_chunk(c + 1);   // overlap LDG with compute

        uint32_t ah[2][4], al[2][4];
        #pragma unroll
        for (int i = 0; i < 2; ++i) {
            int r0 = (wm + i * 16 + g) * RS + tig;
            int r8 = r0 + 8 * RS;
            ah[i][0] = AH[r0];     ah[i][1] = AH[r8];
            ah[i][2] = AH[r0 + 4]; ah[i][3] = AH[r8 + 4];
            al[i][0] = AL[r0];     al[i][1] = AL[r8];
            al[i][2] = AL[r0 + 4]; al[i][3] = AL[r8 + 4];
        }
        #pragma unroll
        for (int j = 0; j < 8; ++j) {
            int rb = (wn + j * 8 + g) * RS + tig;
            uint32_t bh0 = BH[rb], bh1 = BH[rb + 4];
            uint32_t bl0 = BL[rb], bl1 = BL[rb + 4];
            #pragma unroll
            for (int i = 0; i < 2; ++i) {
                float* cc = acc[i][j];
                mma_bf16(cc[0], cc[1], cc[2], cc[3],
                         ah[i][0], ah[i][1], ah[i][2], ah[i][3], bh0, bh1);
                mma_bf16(cc[0], cc[1], cc[2], cc[3],
                         ah[i][0], ah[i][1], ah[i][2], ah[i][3], bl0, bl1);
                mma_bf16(cc[0], cc[1], cc[2], cc[3],
                         al[i][0], al[i][1], al[i][2], al[i][3], bh0, bh1);
            }
        }
        __syncthreads();
    }

    // ---- epilogue: rows are multiples of 128 (R % 128 == 0), no bounds ----
    #pragma unroll
    for (int i = 0; i < 2; ++i) {
        int r0 = rbase + wm + i * 16 + g;
        #pragma unroll
        for (int j = 0; j < 8; ++j) {
            int col = fbase + wn + j * 8 + tig * 2;
            float* o0 = out + (size_t)r0 * F + col;
            *(float2*)o0 = make_float2(acc[i][j][0], acc[i][j][1]);
            *(float2*)(o0 + (size_t)8 * F) = make_float2(acc[i][j][2], acc[i][j][3]);
        }
    }
}

// ---------------- row norms over F=256 ----------------
__global__ void rownorm_kernel(int R, int which) {
    const float* X = which ? g_sc : g_qc;
    float*     nrm = which ? g_scn : g_qcn;
    int warp = (blockIdx.x * blockDim.x + threadIdx.x) >> 5;
    int lane = threadIdx.x & 31;
    if (warp >= R) return;
    const float* row = X + (size_t)warp * F;
    float4 a = *(const float4*)&row[lane * 4];
    float4 b = *(const float4*)&row[128 + lane * 4];
    float ss = a.x * a.x + a.y * a.y + a.z * a.z + a.w * a.w
             + b.x * b.x + b.y * b.y + b.z * b.z + b.w * b.w;
    #pragma unroll
    for (int o = 16; o; o >>= 1) ss += __shfl_xor_sync(0xffffffffu, ss, o);
    if (lane == 0) nrm[warp] = sqrtf(ss);
}

// ---------------- cosine sim: per (b, l-chunk of 512): 32 q x 512 l dots over KD
template<int KD, int KC, int WHICH>
__global__ void __launch_bounds__(256) sim_kernel() {
    const float* Q  = WHICH ? g_qc  : g_qe;
    const float* S  = WHICH ? g_sc  : g_se;
    const float* qn = WHICH ? g_qcn : g_qn;
    const float* sn = WHICH ? g_scn : g_sn;
    float*      sim = WHICH ? g_simsen : g_simins;

    constexpr int SROW_F4 = KC / 4;
    constexpr int CHUNKS  = KD / KC;
    __shared__ float Qs[KC * 32];
    __shared__ float Ss[KC * 516];

    int b     = blockIdx.y;
    int lbase = blockIdx.x * 512;
    int tid   = threadIdx.x;
    int tx = tid & 31, ty = tid >> 5;

    const float* Qb = Q + (size_t)b * LQ * KD;
    const float* Sb = S + (size_t)b * LT * KD;

    float acc[4][16];
    #pragma unroll
    for (int i = 0; i < 4; ++i)
        #pragma unroll
        for (int j = 0; j < 16; ++j) acc[i][j] = 0.0f;

    for (int ch = 0; ch < CHUNKS; ++ch) {
        int k0 = ch * KC;
        __syncthreads();
        if (tid < 32 * SROW_F4) {
            int q = tid / SROW_F4, cc = tid % SROW_F4;
            float4 v = *(const float4*)&Qb[(size_t)q * KD + k0 + cc * 4];
            Qs[(cc * 4 + 0) * 32 + q] = v.x;
            Qs[(cc * 4 + 1) * 32 + q] = v.y;
            Qs[(cc * 4 + 2) * 32 + q] = v.z;
            Qs[(cc * 4 + 3) * 32 + q] = v.w;
        }
        #pragma unroll
        for (int i = 0; i < 2 * SROW_F4; ++i) {
            int flat = tid + 256 * i;
            int lo = flat / SROW_F4, cc = flat % SROW_F4;
            int gl = lbase + lo;
            float4 v = make_float4(0.f, 0.f, 0.f, 0.f);
            if (gl < LT) v = *(const float4*)&Sb[(size_t)gl * KD + k0 + cc * 4];
            Ss[(cc * 4 + 0) * 516 + lo] = v.x;
            Ss[(cc * 4 + 1) * 516 + lo] = v.y;
            Ss[(cc * 4 + 2) * 516 + lo] = v.z;
            Ss[(cc * 4 + 3) * 516 + lo] = v.w;
        }
        __syncthreads();
        #pragma unroll
        for (int kk = 0; kk < KC; ++kk) {
            float4 qv = *(const float4*)&Qs[kk * 32 + ty * 4];
            float qa[4] = {qv.x, qv.y, qv.z, qv.w};
            #pragma unroll
            for (int jj = 0; jj < 4; ++jj) {
                float4 sv = *(const float4*)&Ss[kk * 516 + jj * 128 + tx * 4];
                float sa[4] = {sv.x, sv.y, sv.z, sv.w};
                #pragma unroll
                for (int qq = 0; qq < 4; ++qq)
                    #pragma unroll
                    for (int ll = 0; ll < 4; ++ll)
                        acc[qq][jj * 4 + ll] += qa[qq] * sa[ll];
            }
        }
    }

    float qnv[4];
    #pragma unroll
    for (int qq = 0; qq < 4; ++qq) qnv[qq] = qn[b * LQ + ty * 4 + qq];

    #pragma unroll
    for (int jj = 0; jj < 4; ++jj)
        #pragma unroll
        for (int ll = 0; ll < 4; ++ll) {
            int gl = lbase + jj * 128 + tx * 4 + ll;
            if (gl < LT) {
                float snv = sn[b * LT + gl];
                int n = gl / LS, l = gl % LS;
                #pragma unroll
                for (int qq = 0; qq < 4; ++qq) {
                    size_t oidx = ((((size_t)b * NS + n) * LQ) + (ty * 4 + qq)) * LS + l;
                    sim[oidx] = acc[qq][jj * 4 + ll] / (qnv[qq] * snv);
                }
            }
        }
}

// ---------------- top-k pooling + per-q linear + sigmoid + mean over q ----------------
__device__ __forceinline__ void insert5(float* t, float v) {
    if (v > t[4]) {
        t[4] = v;
        #pragma unroll
        for (int i = 4; i > 0; --i) {
            if (t[i] > t[i - 1]) { float tmp = t[i - 1]; t[i - 1] = t[i]; t[i] = tmp; }
        }
    }
}

__global__ void pool_kernel(const int* __restrict__ question,
                            const int* __restrict__ sentences,
                            const float* __restrict__ W,
                            const float* __restrict__ bias,
                            float* __restrict__ out_sent) {
    int bn = blockIdx.x;     // b*NS + n
    int b  = bn / NS;
    int q  = threadIdx.x;    // 0..31
    bool qm = question[b * LQ + q] > 0;

    const float* si   = g_simins + ((size_t)bn * LQ + q) * LS;
    const float* ssen = g_simsen + ((size_t)bn * LQ + q) * LS;
    const int*   sent = sentences + (size_t)bn * LS;

    float ti[5] = {-INFINITY, -INFINITY, -INFINITY, -INFINITY, -INFINITY};
    float tc[5] = {-INFINITY, -INFINITY, -INFINITY, -INFINITY, -INFINITY};
    int cnt = 0;
    const float thr = (float)(1.0 - 1e-5);

    for (int l = 0; l < LS; ++l) {
        float m  = (qm && sent[l] > 0) ? 1.0f : 0.0f;
        float vi = si[l];
        if (vi >= thr) ++cnt;                 // oh channel uses UNMASKED sim
        insert5(ti, vi * m);
        insert5(tc, ssen[l] * m);
    }
    float insMean = (ti[0] + ti[1] + ti[2] + ti[3] + ti[4]) * 0.2f;
    float senMean = (tc[0] + tc[1] + tc[2] + tc[3] + tc[4]) * 0.2f;
    float ohMax   = (cnt > 0) ? 1.0f : 0.0f;
    float ohMean  = fminf((float)cnt, 5.0f) * 0.2f;

    float z = W[0] * ti[0] + W[1] * insMean + W[2] * tc[0] + W[3] * senMean
            + W[4] * ohMax + W[5] * ohMean + bias[0];
    float p = 1.0f / (1.0f + expf(-z));

    #pragma unroll
    for (int o = 16; o; o >>= 1) p += __shfl_xor_sync(0xffffffffu, p, o);
    if (q == 0) {
        float sr = p * (1.0f / (float)LQ);
        g_sentrel[bn] = sr;
        if (out_sent) out_sent[bn] = sr;
    }
}

// ---------------- doc max + BCE losses ----------------
__global__ void final_kernel(const int* __restrict__ tsents,
                             const int* __restrict__ tdocs,
                             float* __restrict__ out_loss,
                             float* __restrict__ out_doc) {
    __shared__ float red[256];
    __shared__ float docs_s[Bq];
    int tid = threadIdx.x;
    const float eps = 1e-7f;
    const float hi  = (float)(1.0 - 1e-7);

    float s1 = 0.0f;
    for (int i = tid; i < Bq * NS; i += 256) {
        float p = fminf(fmaxf(g_sentrel[i], eps), hi);
        float t = (float)tsents[i];
        s1 += t * logf(p) + (1.0f - t) * log1pf(-p);
    }
    red[tid] = s1;
    __syncthreads();
    for (int s = 128; s > 0; s >>= 1) {
        if (tid < s) red[tid] += red[tid + s];
        __syncthreads();
    }
    float bce1 = -red[0] / (float)(Bq * NS);
    __syncthreads();

    if (tid < Bq) {
        float m = -INFINITY;
        for (int n = 0; n < NS; ++n) m = fmaxf(m, g_sentrel[tid * NS + n]);
        docs_s[tid] = m;
        if (out_doc) out_doc[tid] = m;
    }
    __syncthreads();

    float s2 = 0.0f;
    if (tid < Bq) {
        float p = fminf(fmaxf(docs_s[tid], eps), hi);
        float t = (float)tdocs[tid];
        s2 = t * logf(p) + (1.0f - t) * log1pf(-p);
    }
    red[tid] = s2;
    __syncthreads();
    for (int s = 128; s > 0; s >>= 1) {
        if (tid < s) red[tid] += red[tid + s];
        __syncthreads();
    }
    if (tid == 0) {
        float bce2 = -red[0] / (float)Bq;
        out_loss[0] = 0.5f * (bce1 + bce2);
    }
}

// ---------------- host ----------------
extern "C" void kernel_launch(void* const* d_in, const int* in_sizes, int n_in,
                              void* d_out, int out_size) {
    const int *sentences = nullptr, *question = nullptr, *tsents = nullptr, *tdocs = nullptr;
    const float *embeds = nullptr, *filters = nullptr, *W = nullptr, *bias = nullptr;

    for (int i = 0; i < n_in; ++i) {
        switch (in_sizes[i]) {
            case SROWS:        sentences = (const int*)d_in[i];  break; // 192000
            case QROWS:        question  = (const int*)d_in[i];  break; // 2048
            case Bq * NS:      tsents    = (const int*)d_in[i];  break; // 3200
            case Bq:           tdocs     = (const int*)d_in[i];  break; // 64
            case Vv * D:       embeds    = (const float*)d_in[i]; break;
            case F * FS * D:   filters   = (const float*)d_in[i]; break; // 230400
            case 6:            W         = (const float*)d_in[i]; break;
            case 1:            bias      = (const float*)d_in[i]; break;
            default: break;
        }
    }

    float* out = (float*)d_out;
    float* out_sent = (out_size >= 1 + Bq * NS)      ? out + 1            : nullptr;
    float* out_doc  = (out_size >= 1 + Bq * NS + Bq) ? out + 1 + Bq * NS  : nullptr;

    // 1-2: gather embeddings + L2 norms
    gather_norm_kernel<<<(QROWS * 32 + 255) / 256, 256>>>(embeds, question, QROWS, 0);
    gather_norm_kernel<<<(SROWS * 32 + 255) / 256, 256>>>(embeds, sentences, SROWS, 1);

    // 3-4: forward conv (zero-pad at segment end) as split-bf16 tensor-core GEMM
    conv_mma_kernel<LQ><<<dim3(QROWS / 128, F / 128), 256>>>(filters, QROWS, 0);
    conv_mma_kernel<LS><<<dim3(SROWS / 128, F / 128), 256>>>(filters, SROWS, 1);

    // 5-6: conv-output norms
    rownorm_kernel<<<(QROWS * 32 + 255) / 256, 256>>>(QROWS, 0);
    rownorm_kernel<<<(SROWS * 32 + 255) / 256, 256>>>(SROWS, 1);

    // 7-8: cosine similarity matrices
    sim_kernel<300, 12, 0><<<dim3((LT + 511) / 512, Bq), 256>>>();
    sim_kernel<256, 16, 1><<<dim3((LT + 511) / 512, Bq), 256>>>();

    // 9: top-k pooling + linear + sigmoid + mean over q
    pool_kernel<<<Bq * NS, 32>>>(question, sentences, W, bias, out_sent);

    // 10: doc max + BCE
    final_kernel<<<1, 256>>>(tsents, tdocs, out, out_doc);
}

// round 7
// speedup vs baseline: 1.0054x; 1.0054x over previous
#include <cuda_runtime.h>
#include <cuda_bf16.h>
#include <cstdint>
#include <math.h>

// ---------------- problem constants ----------------
constexpr int Bq   = 64;     // batch
constexpr int NS   = 50;     // sentences per doc
constexpr int LS   = 60;     // sentence length
constexpr int LQ   = 32;     // question length
constexpr int D    = 300;    // embedding dim
constexpr int F    = 256;    // conv filters
constexpr int FS   = 3;      // filter size
constexpr int Vv   = 100000; // vocab
constexpr int QROWS = Bq * LQ;        // 2048
constexpr int SROWS = Bq * NS * LS;   // 192000
constexpr int LT    = NS * LS;        // 3000

// ---------------- device scratch (no allocs allowed) ----------------
__device__ float g_qe[QROWS * D];          // question embeddings
__device__ float g_qn[QROWS];              // |qe|
__device__ float g_se[SROWS * D];          // sentence embeddings (230 MB)
__device__ float g_sn[SROWS];              // |se|
__device__ float g_qc[QROWS * F];          // conv(question)
__device__ float g_qcn[QROWS];
__device__ float g_sc[SROWS * F];          // conv(sentences) (197 MB)
__device__ float g_scn[SROWS];
__device__ float g_simins[Bq * NS * LQ * LS];  // [b][n][q][l]
__device__ float g_simsen[Bq * NS * LQ * LS];
__device__ float g_sentrel[Bq * NS];

// ---------------- gather + norm ----------------
__global__ void gather_norm_kernel(const float* __restrict__ embeds,
                                   const int* __restrict__ tokens,
                                   int nrows, int which) {
    int warp = (blockIdx.x * blockDim.x + threadIdx.x) >> 5;
    int lane = threadIdx.x & 31;
    if (warp >= nrows) return;
    float* dst = which ? g_se : g_qe;
    float* nrm = which ? g_sn : g_qn;
    int tok = tokens[warp];
    const float* src = embeds + (size_t)tok * D;
    float* drow = dst + (size_t)warp * D;
    float ss = 0.0f;
    for (int i = lane; i < D; i += 32) {
        float v = src[i];
        drow[i] = v;
        ss += v * v;
    }
    #pragma unroll
    for (int o = 16; o; o >>= 1) ss += __shfl_xor_sync(0xffffffffu, ss, o);
    if (lane == 0) nrm[warp] = sqrtf(ss);
}

// ============================================================================
// conv as GEMM on tensor cores (split-bf16 emulated fp32):
//   out[r,f] = sum_{t<3, l+t<SEG} X[r+t,:] . filt[f,t,:]
// Block tile 128x128, 8 warps (4M x 2N), warp tile 32x64, mma m16n8k16 bf16.
// a = a_hi + a_lo (bf16 split); D = Ahi*Bhi + Ahi*Blo + Alo*Bhi (fp32 accum).
// ============================================================================

__device__ __forceinline__ void mma_bf16(float& c0, float& c1, float& c2, float& c3,
                                         uint32_t a0, uint32_t a1, uint32_t a2, uint32_t a3,
                                         uint32_t b0, uint32_t b1) {
    asm volatile("mma.sync.aligned.m16n8k16.row.col.f32.bf16.bf16.f32 "
                 "{%0,%1,%2,%3},{%4,%5,%6,%7},{%8,%9},{%0,%1,%2,%3};"
                 : "+f"(c0), "+f"(c1), "+f"(c2), "+f"(c3)
                 : "r"(a0), "r"(a1), "r"(a2), "r"(a3), "r"(b0), "r"(b1));
}

// SMEM row stride: 18 bf16 (36 B = 9 banks; gcd(9,32)=1 -> conflict-friendly)
constexpr int SMS = 18;
constexpr int KCHUNKS = 19;           // ceil(300/16) per tap
constexpr int NCHUNK  = FS * KCHUNKS; // 57

template<int SEG>
__global__ void __launch_bounds__(256) conv_mma_kernel(const float* __restrict__ filt,
                                                       int R, int which) {
    const float* X  = which ? g_se : g_qe;
    float*      out = which ? g_sc : g_qc;

    __shared__ __align__(16) __nv_bfloat16 AsHi[128 * SMS];
    __shared__ __align__(16) __nv_bfloat16 AsLo[128 * SMS];
    __shared__ __align__(16) __nv_bfloat16 BsHi[128 * SMS];
    __shared__ __align__(16) __nv_bfloat16 BsLo[128 * SMS];

    const int tid  = threadIdx.x;
    const int lane = tid & 31;
    const int wid  = tid >> 5;
    const int wm   = (wid & 3) * 32;   // warp M offset (4 warps in M)
    const int wn   = (wid >> 2) * 64;  // warp N offset (2 warps in N)
    const int g    = lane >> 2;        // group id 0..7
    const int tig  = lane & 3;         // thread-in-group 0..3

    const int rbase = blockIdx.x * 128;
    const int fbase = blockIdx.y * 128;

    // loader role: each thread loads row (tid>>1), k-half ((tid&1)*8)
    const int arow  = tid >> 1;
    const int khalf = (tid & 1) * 8;
    const int gr    = rbase + arow;     // global X row
    const int lpos  = gr % SEG;         // position within segment
    const int gf    = fbase + arow;     // global filter row (always < 256)

    float acc[2][8][4];
    #pragma unroll
    for (int i = 0; i < 2; ++i)
        #pragma unroll
        for (int j = 0; j < 8; ++j)
            #pragma unroll
            for (int v = 0; v < 4; ++v) acc[i][j][v] = 0.0f;

    float fa[8], fb[8];

    // ---- chunk loader: chunk c -> tap t, k-offset kc ----
    auto load_chunk = [&](int c) {
        int t  = (c >= 2 * KCHUNKS) ? 2 : (c >= KCHUNKS ? 1 : 0);
        int kc = (c - t * KCHUNKS) * 16;
        int k0 = kc + khalf;
        bool full = (k0 + 7 < D);
        bool aval = (lpos + t) < SEG;   // forward conv window inside segment

        const float* ap = X + (size_t)(gr + t) * D + k0;
        if (aval && full) {
            float4 v0 = *(const float4*)ap;
            float4 v1 = *(const float4*)(ap + 4);
            fa[0]=v0.x; fa[1]=v0.y; fa[2]=v0.z; fa[3]=v0.w;
            fa[4]=v1.x; fa[5]=v1.y; fa[6]=v1.z; fa[7]=v1.w;
        } else {
            #pragma unroll
            for (int e = 0; e < 8; ++e)
                fa[e] = (aval && (k0 + e < D)) ? ap[e] : 0.0f;
        }

        const float* bp = filt + (size_t)gf * (FS * D) + t * D + k0;
        if (full) {
            float4 v0 = *(const float4*)bp;
            float4 v1 = *(const float4*)(bp + 4);
            fb[0]=v0.x; fb[1]=v0.y; fb[2]=v0.z; fb[3]=v0.w;
            fb[4]=v1.x; fb[5]=v1.y; fb[6]=v1.z; fb[7]=v1.w;
        } else {
            #pragma unroll
            for (int e = 0; e < 8; ++e)
                fb[e] = (k0 + e < D) ? bp[e] : 0.0f;
        }
    };

    // ---- store to smem with hi/lo split ----
    auto sts_chunk = [&]() {
        #pragma unroll
        for (int e = 0; e < 8; e += 2) {
            int idx = arow * SMS + khalf + e;
            __nv_bfloat16 h0 = __float2bfloat16(fa[e]);
            __nv_bfloat16 h1 = __float2bfloat16(fa[e + 1]);
            __nv_bfloat16 l0 = __float2bfloat16(fa[e]     - __bfloat162float(h0));
            __nv_bfloat16 l1 = __float2bfloat16(fa[e + 1] - __bfloat162float(h1));
            *(__nv_bfloat162*)&AsHi[idx] = __halves2bfloat162(h0, h1);
            *(__nv_bfloat162*)&AsLo[idx] = __halves2bfloat162(l0, l1);
            __nv_bfloat16 p0 = __float2bfloat16(fb[e]);
            __nv_bfloat16 p1 = __float2bfloat16(fb[e + 1]);
            __nv_bfloat16 q0 = __float2bfloat16(fb[e]     - __bfloat162float(p0));
            __nv_bfloat16 q1 = __float2bfloat16(fb[e + 1] - __bfloat162float(p1));
            *(__nv_bfloat162*)&BsHi[idx] = __halves2bfloat162(p0, p1);
            *(__nv_bfloat162*)&BsLo[idx] = __halves2bfloat162(q0, q1);
        }
    };

    const uint32_t* AH = (const uint32_t*)AsHi;
    const uint32_t* AL = (const uint32_t*)AsLo;
    const uint32_t* BH = (const uint32_t*)BsHi;
    const uint32_t* BL = (const uint32_t*)BsLo;
    constexpr int RS = SMS / 2;   // row stride in u32 units = 9

    load_chunk(0);
    for (int c = 0; c < NCHUNK; ++c) {
        sts_chunk();
        __syncthreads();
        if (c + 1 < NCHUNK) load_chunk(c + 1);   // overlap LDG with compute

        uint32_t ah[2][4], al[2][4];
        #pragma unroll
        for (int i = 0; i < 2; ++i) {
            int r0 = (wm + i * 16 + g) * RS + tig;
            int r8 = r0 + 8 * RS;
            ah[i][0] = AH[r0];     ah[i][1] = AH[r8];
            ah[i][2] = AH[r0 + 4]; ah[i][3] = AH[r8 + 4];
            al[i][0] = AL[r0];     al[i][1] = AL[r8];
            al[i][2] = AL[r0 + 4]; al[i][3] = AL[r8 + 4];
        }
        #pragma unroll
        for (int j = 0; j < 8; ++j) {
            int rb = (wn + j * 8 + g) * RS + tig;
            uint32_t bh0 = BH[rb], bh1 = BH[rb + 4];
            uint32_t bl0 = BL[rb], bl1 = BL[rb + 4];
            #pragma unroll
            for (int i = 0; i < 2; ++i) {
                float* cc = acc[i][j];
                mma_bf16(cc[0], cc[1], cc[2], cc[3],
                         ah[i][0], ah[i][1], ah[i][2], ah[i][3], bh0, bh1);
                mma_bf16(cc[0], cc[1], cc[2], cc[3],
                         ah[i][0], ah[i][1], ah[i][2], ah[i][3], bl0, bl1);
                mma_bf16(cc[0], cc[1], cc[2], cc[3],
                         al[i][0], al[i][1], al[i][2], al[i][3], bh0, bh1);
            }
        }
        __syncthreads();
    }

    // ---- epilogue: rows are multiples of 128 (R % 128 == 0), no bounds ----
    #pragma unroll
    for (int i = 0; i < 2; ++i) {
        int r0 = rbase + wm + i * 16 + g;
        #pragma unroll
        for (int j = 0; j < 8; ++j) {
            int col = fbase + wn + j * 8 + tig * 2;
            float* o0 = out + (size_t)r0 * F + col;
            *(float2*)o0 = make_float2(acc[i][j][0], acc[i][j][1]);
            *(float2*)(o0 + (size_t)8 * F) = make_float2(acc[i][j][2], acc[i][j][3]);
        }
    }
}

// ---------------- row norms over F=256 ----------------
__global__ void rownorm_kernel(int R, int which) {
    const float* X = which ? g_sc : g_qc;
    float*     nrm = which ? g_scn : g_qcn;
    int warp = (blockIdx.x * blockDim.x + threadIdx.x) >> 5;
    int lane = threadIdx.x & 31;
    if (warp >= R) return;
    const float* row = X + (size_t)warp * F;
    float4 a = *(const float4*)&row[lane * 4];
    float4 b = *(const float4*)&row[128 + lane * 4];
    float ss = a.x * a.x + a.y * a.y + a.z * a.z + a.w * a.w
             + b.x * b.x + b.y * b.y + b.z * b.z + b.w * b.w;
    #pragma unroll
    for (int o = 16; o; o >>= 1) ss += __shfl_xor_sync(0xffffffffu, ss, o);
    if (lane == 0) nrm[warp] = sqrtf(ss);
}

// ---------------- cosine sim: per (b, l-chunk of 512): 32 q x 512 l dots over KD
template<int KD, int KC, int WHICH>
__global__ void __launch_bounds__(256) sim_kernel() {
    const float* Q  = WHICH ? g_qc  : g_qe;
    const float* S  = WHICH ? g_sc  : g_se;
    const float* qn = WHICH ? g_qcn : g_qn;
    const float* sn = WHICH ? g_scn : g_sn;
    float*      sim = WHICH ? g_simsen : g_simins;

    constexpr int SROW_F4 = KC / 4;
    constexpr int CHUNKS  = KD / KC;
    __shared__ float Qs[KC * 32];
    __shared__ float Ss[KC * 516];

    int b     = blockIdx.y;
    int lbase = blockIdx.x * 512;
    int tid   = threadIdx.x;
    int tx = tid & 31, ty = tid >> 5;

    const float* Qb = Q + (size_t)b * LQ * KD;
    const float* Sb = S + (size_t)b * LT * KD;

    float acc[4][16];
    #pragma unroll
    for (int i = 0; i < 4; ++i)
        #pragma unroll
        for (int j = 0; j < 16; ++j) acc[i][j] = 0.0f;

    for (int ch = 0; ch < CHUNKS; ++ch) {
        int k0 = ch * KC;
        __syncthreads();
        if (tid < 32 * SROW_F4) {
            int q = tid / SROW_F4, cc = tid % SROW_F4;
            float4 v = *(const float4*)&Qb[(size_t)q * KD + k0 + cc * 4];
            Qs[(cc * 4 + 0) * 32 + q] = v.x;
            Qs[(cc * 4 + 1) * 32 + q] = v.y;
            Qs[(cc * 4 + 2) * 32 + q] = v.z;
            Qs[(cc * 4 + 3) * 32 + q] = v.w;
        }
        #pragma unroll
        for (int i = 0; i < 2 * SROW_F4; ++i) {
            int flat = tid + 256 * i;
            int lo = flat / SROW_F4, cc = flat % SROW_F4;
            int gl = lbase + lo;
            float4 v = make_float4(0.f, 0.f, 0.f, 0.f);
            if (gl < LT) v = *(const float4*)&Sb[(size_t)gl * KD + k0 + cc * 4];
            Ss[(cc * 4 + 0) * 516 + lo] = v.x;
            Ss[(cc * 4 + 1) * 516 + lo] = v.y;
            Ss[(cc * 4 + 2) * 516 + lo] = v.z;
            Ss[(cc * 4 + 3) * 516 + lo] = v.w;
        }
        __syncthreads();
        #pragma unroll
        for (int kk = 0; kk < KC; ++kk) {
            float4 qv = *(const float4*)&Qs[kk * 32 + ty * 4];
            float qa[4] = {qv.x, qv.y, qv.z, qv.w};
            #pragma unroll
            for (int jj = 0; jj < 4; ++jj) {
                float4 sv = *(const float4*)&Ss[kk * 516 + jj * 128 + tx * 4];
                float sa[4] = {sv.x, sv.y, sv.z, sv.w};
                #pragma unroll
                for (int qq = 0; qq < 4; ++qq)
                    #pragma unroll
                    for (int ll = 0; ll < 4; ++ll)
                        acc[qq][jj * 4 + ll] += qa[qq] * sa[ll];
            }
        }
    }

    float qnv[4];
    #pragma unroll
    for (int qq = 0; qq < 4; ++qq) qnv[qq] = qn[b * LQ + ty * 4 + qq];

    #pragma unroll
    for (int jj = 0; jj < 4; ++jj)
        #pragma unroll
        for (int ll = 0; ll < 4; ++ll) {
            int gl = lbase + jj * 128 + tx * 4 + ll;
            if (gl < LT) {
                float snv = sn[b * LT + gl];
                int n = gl / LS, l = gl % LS;
                #pragma unroll
                for (int qq = 0; qq < 4; ++qq) {
                    size_t oidx = ((((size_t)b * NS + n) * LQ) + (ty * 4 + qq)) * LS + l;
                    sim[oidx] = acc[qq][jj * 4 + ll] / (qnv[qq] * snv);
                }
            }
        }
}

// ---------------- top-k pooling + per-q linear + sigmoid + mean over q ----------------
__device__ __forceinline__ void insert5(float* t, float v) {
    if (v > t[4]) {
        t[4] = v;
        #pragma unroll
        for (int i = 4; i > 0; --i) {
            if (t[i] > t[i - 1]) { float tmp = t[i - 1]; t[i - 1] = t[i]; t[i] = tmp; }
        }
    }
}

__global__ void pool_kernel(const int* __restrict__ question,
                            const int* __restrict__ sentences,
                            const float* __restrict__ W,
                            const float* __restrict__ bias,
                            float* __restrict__ out_sent) {
    int bn = blockIdx.x;     // b*NS + n
    int b  = bn / NS;
    int q  = threadIdx.x;    // 0..31
    bool qm = question[b * LQ + q] > 0;

    const float* si   = g_simins + ((size_t)bn * LQ + q) * LS;
    const float* ssen = g_simsen + ((size_t)bn * LQ + q) * LS;
    const int*   sent = sentences + (size_t)bn * LS;

    float ti[5] = {-INFINITY, -INFINITY, -INFINITY, -INFINITY, -INFINITY};
    float tc[5] = {-INFINITY, -INFINITY, -INFINITY, -INFINITY, -INFINITY};
    int cnt = 0;
    const float thr = (float)(1.0 - 1e-5);

    for (int l = 0; l < LS; ++l) {
        float m  = (qm && sent[l] > 0) ? 1.0f : 0.0f;
        float vi = si[l];
        if (vi >= thr) ++cnt;                 // oh channel uses UNMASKED sim
        insert5(ti, vi * m);
        insert5(tc, ssen[l] * m);
    }
    float insMean = (ti[0] + ti[1] + ti[2] + ti[3] + ti[4]) * 0.2f;
    float senMean = (tc[0] + tc[1] + tc[2] + tc[3] + tc[4]) * 0.2f;
    float ohMax   = (cnt > 0) ? 1.0f : 0.0f;
    float ohMean  = fminf((float)cnt, 5.0f) * 0.2f;

    float z = W[0] * ti[0] + W[1] * insMean + W[2] * tc[0] + W[3] * senMean
            + W[4] * ohMax + W[5] * ohMean + bias[0];
    float p = 1.0f / (1.0f + expf(-z));

    #pragma unroll
    for (int o = 16; o; o >>= 1) p += __shfl_xor_sync(0xffffffffu, p, o);
    if (q == 0) {
        float sr = p * (1.0f / (float)LQ);
        g_sentrel[bn] = sr;
        if (out_sent) out_sent[bn] = sr;
    }
}

// ---------------- doc max + BCE losses ----------------
__global__ void final_kernel(const int* __restrict__ tsents,
                             const int* __restrict__ tdocs,
                             float* __restrict__ out_loss,
                             float* __restrict__ out_doc) {
    __shared__ float red[256];
    __shared__ float docs_s[Bq];
    int tid = threadIdx.x;
    const float eps = 1e-7f;
    const float hi  = (float)(1.0 - 1e-7);

    float s1 = 0.0f;
    for (int i = tid; i < Bq * NS; i += 256) {
        float p = fminf(fmaxf(g_sentrel[i], eps), hi);
        float t = (float)tsents[i];
        s1 += t * logf(p) + (1.0f - t) * log1pf(-p);
    }
    red[tid] = s1;
    __syncthreads();
    for (int s = 128; s > 0; s >>= 1) {
        if (tid < s) red[tid] += red[tid + s];
        __syncthreads();
    }
    float bce1 = -red[0] / (float)(Bq * NS);
    __syncthreads();

    if (tid < Bq) {
        float m = -INFINITY;
        for (int n = 0; n < NS; ++n) m = fmaxf(m, g_sentrel[tid * NS + n]);
        docs_s[tid] = m;
        if (out_doc) out_doc[tid] = m;
    }
    __syncthreads();

    float s2 = 0.0f;
    if (tid < Bq) {
        float p = fminf(fmaxf(docs_s[tid], eps), hi);
        float t = (float)tdocs[tid];
        s2 = t * logf(p) + (1.0f - t) * log1pf(-p);
    }
    red[tid] = s2;
    __syncthreads();
    for (int s = 128; s > 0; s >>= 1) {
        if (tid < s) red[tid] += red[tid + s];
        __syncthreads();
    }
    if (tid == 0) {
        float bce2 = -red[0] / (float)Bq;
        out_loss[0] = 0.5f * (bce1 + bce2);
    }
}

// ---------------- host ----------------
extern "C" void kernel_launch(void* const* d_in, const int* in_sizes, int n_in,
                              void* d_out, int out_size) {
    const int *sentences = nullptr, *question = nullptr, *tsents = nullptr, *tdocs = nullptr;
    const float *embeds = nullptr, *filters = nullptr, *W = nullptr, *bias = nullptr;

    for (int i = 0; i < n_in; ++i) {
        switch (in_sizes[i]) {
            case SROWS:        sentences = (const int*)d_in[i];  break; // 192000
            case QROWS:        question  = (const int*)d_in[i];  break; // 2048
            case Bq * NS:      tsents    = (const int*)d_in[i];  break; // 3200
            case Bq:           tdocs     = (const int*)d_in[i];  break; // 64
            case Vv * D:       embeds    = (const float*)d_in[i]; break;
            case F * FS * D:   filters   = (const float*)d_in[i]; break; // 230400
            case 6:            W         = (const float*)d_in[i]; break;
            case 1:            bias      = (const float*)d_in[i]; break;
            default: break;
        }
    }

    float* out = (float*)d_out;
    float* out_sent = (out_size >= 1 + Bq * NS)      ? out + 1            : nullptr;
    float* out_doc  = (out_size >= 1 + Bq * NS + Bq) ? out + 1 + Bq * NS  : nullptr;

    // 1-2: gather embeddings + L2 norms
    gather_norm_kernel<<<(QROWS * 32 + 255) / 256, 256>>>(embeds, question, QROWS, 0);
    gather_norm_kernel<<<(SROWS * 32 + 255) / 256, 256>>>(embeds, sentences, SROWS, 1);

    // 3-4: forward conv (zero-pad at segment end) as split-bf16 tensor-core GEMM
    conv_mma_kernel<LQ><<<dim3(QROWS / 128, F / 128), 256>>>(filters, QROWS, 0);
    conv_mma_kernel<LS><<<dim3(SROWS / 128, F / 128), 256>>>(filters, SROWS, 1);

    // 5-6: conv-output norms
    rownorm_kernel<<<(QROWS * 32 + 255) / 256, 256>>>(QROWS, 0);
    rownorm_kernel<<<(SROWS * 32 + 255) / 256, 256>>>(SROWS, 1);

    // 7-8: cosine similarity matrices
    sim_kernel<300, 12, 0><<<dim3((LT + 511) / 512, Bq), 256>>>();
    sim_kernel<256, 16, 1><<<dim3((LT + 511) / 512, Bq), 256>>>();

    // 9: top-k pooling + linear + sigmoid + mean over q
    pool_kernel<<<Bq * NS, 32>>>(question, sentences, W, bias, out_sent);

    // 10: doc max + BCE
    final_kernel<<<1, 256>>>(tsents, tdocs, out, out_doc);
}

// round 8
// speedup vs baseline: 1.8213x; 1.8115x over previous
#include <cuda_runtime.h>
#include <cuda_bf16.h>
#include <cstdint>
#include <math.h>

// ---------------- problem constants ----------------
constexpr int Bq   = 64;     // batch
constexpr int NS   = 50;     // sentences per doc
constexpr int LS   = 60;     // sentence length
constexpr int LQ   = 32;     // question length
constexpr int D    = 300;    // embedding dim
constexpr int DP   = 304;    // padded embedding dim (16-elem multiple)
constexpr int F    = 256;    // conv filters
constexpr int FS   = 3;      // filter size
constexpr int Vv   = 100000; // vocab
constexpr int QROWS = Bq * LQ;        // 2048
constexpr int SROWS = Bq * NS * LS;   // 192000
constexpr int LT    = NS * LS;        // 3000

constexpr int KCH  = DP / 16;        // 19 k16-chunks per tap
constexpr int NCHK = FS * KCH;       // 57

// ---------------- device scratch (no allocs allowed) ----------------
__device__ float g_qe[QROWS * D];          // question embeddings (fp32, for sim_ins)
__device__ float g_qn[QROWS];              // |qe|
__device__ float g_se[SROWS * D];          // sentence embeddings (fp32)
__device__ float g_sn[SROWS];              // |se|
__device__ __nv_bfloat16 g_qe_bf[(QROWS + 2) * DP]; // bf16 copy for conv (padded; pad stays zero)
__device__ __nv_bfloat16 g_se_bf[(SROWS + 2) * DP];
__device__ __nv_bfloat16 g_filt_bf[F * FS * DP];    // bf16 filters, k padded to 304
__device__ float g_qc[QROWS * F];          // conv(question)
__device__ float g_qcn[QROWS];
__device__ float g_sc[SROWS * F];          // conv(sentences)
__device__ float g_scn[SROWS];
__device__ float g_simins[Bq * NS * LQ * LS];  // [b][n][q][l]
__device__ float g_simsen[Bq * NS * LQ * LS];
__device__ float g_sentrel[Bq * NS];

// ---------------- gather + norm (+ bf16 copy) ----------------
__global__ void gather_norm_kernel(const float* __restrict__ embeds,
                                   const int* __restrict__ tokens,
                                   int nrows, int which) {
    int warp = (blockIdx.x * blockDim.x + threadIdx.x) >> 5;
    int lane = threadIdx.x & 31;
    if (warp >= nrows) return;
    float* dst = which ? g_se : g_qe;
    float* nrm = which ? g_sn : g_qn;
    __nv_bfloat16* dbf = which ? g_se_bf : g_qe_bf;
    int tok = tokens[warp];
    const float* src = embeds + (size_t)tok * D;
    float* drow = dst + (size_t)warp * D;
    __nv_bfloat16* brow = dbf + (size_t)warp * DP;
    float ss = 0.0f;
    for (int i = lane; i < D; i += 32) {
        float v = src[i];
        drow[i] = v;
        brow[i] = __float2bfloat16(v);
        ss += v * v;
    }
    #pragma unroll
    for (int o = 16; o; o >>= 1) ss += __shfl_xor_sync(0xffffffffu, ss, o);
    if (lane == 0) nrm[warp] = sqrtf(ss);
}

// ---------------- filter fp32 -> bf16 (k padded to DP; pad stays zero) ----------------
__global__ void filt_convert_kernel(const float* __restrict__ filt) {
    int idx = blockIdx.x * blockDim.x + threadIdx.x;  // over F*FS*D
    if (idx >= F * FS * D) return;
    int f = idx / (FS * D);
    int r = idx % (FS * D);
    int t = r / D;
    int k = r % D;
    g_filt_bf[((size_t)f * FS + t) * DP + k] = __float2bfloat16(filt[idx]);
}

// ============================================================================
// conv as GEMM on tensor cores (single-pass bf16):
//   out[r,f] = sum_{t<3, l+t<SEG} X[r+t,:] . filt[f,t,:]
// Block tile 128x128, 8 warps (4M x 2N), warp tile 32x64, mma m16n8k16 bf16.
// SMEM: 32B rows (16 bf16), 16B halves XOR-swizzled (h ^ ((row>>2)&1)) ->
// conflict-free ldmatrix.x4 for both k-halves.
// ============================================================================

__device__ __forceinline__ void mma_bf16(float& c0, float& c1, float& c2, float& c3,
                                         uint32_t a0, uint32_t a1, uint32_t a2, uint32_t a3,
                                         uint32_t b0, uint32_t b1) {
    asm volatile("mma.sync.aligned.m16n8k16.row.col.f32.bf16.bf16.f32 "
                 "{%0,%1,%2,%3},{%4,%5,%6,%7},{%8,%9},{%0,%1,%2,%3};"
                 : "+f"(c0), "+f"(c1), "+f"(c2), "+f"(c3)
                 : "r"(a0), "r"(a1), "r"(a2), "r"(a3), "r"(b0), "r"(b1));
}

__device__ __forceinline__ void ldsm4(uint32_t& r0, uint32_t& r1, uint32_t& r2, uint32_t& r3,
                                      uint32_t addr) {
    asm volatile("ldmatrix.sync.aligned.m8n8.x4.shared.b16 {%0,%1,%2,%3}, [%4];"
                 : "=r"(r0), "=r"(r1), "=r"(r2), "=r"(r3) : "r"(addr));
}

template<int SEG>
__global__ void __launch_bounds__(256) conv_mma_kernel(int R, int which) {
    const __nv_bfloat16* X = which ? g_se_bf : g_qe_bf;
    float* out = which ? g_sc : g_qc;

    __shared__ __align__(16) uint4 As4[256];   // 128 rows x 2 16B slots
    __shared__ __align__(16) uint4 Bs4[256];

    const int tid  = threadIdx.x;
    const int lane = tid & 31;
    const int wid  = tid >> 5;
    const int wm   = (wid & 3) * 32;   // warp M offset
    const int wn   = (wid >> 2) * 64;  // warp N offset

    const int rbase = blockIdx.x * 128;
    const int fbase = blockIdx.y * 128;

    // loader role: row = tid>>1, 16B half h = tid&1
    const int arow = tid >> 1;
    const int h    = tid & 1;
    const int gr   = rbase + arow;      // global X row
    const int lpos = gr % SEG;          // position within segment
    const int gf   = fbase + arow;      // filter row (< 256)
    const int slot = 2 * arow + (h ^ ((arow >> 2) & 1));  // swizzled 16B slot

    // precompute ldmatrix addresses (constant across chunks)
    uint32_t sbA = (uint32_t)__cvta_generic_to_shared(As4);
    uint32_t sbB = (uint32_t)__cvta_generic_to_shared(Bs4);
    const int m  = lane >> 3;
    const int rr = lane & 7;
    uint32_t aaddr[2], baddr[4];
    #pragma unroll
    for (int i = 0; i < 2; ++i) {
        int rowA = wm + i * 16 + (m & 1) * 8 + rr;
        int hp   = (m >> 1) ^ ((rowA >> 2) & 1);
        aaddr[i] = sbA + (uint32_t)(rowA * 32 + hp * 16);
    }
    #pragma unroll
    for (int jp = 0; jp < 4; ++jp) {
        int rowB = wn + (jp * 2 + (m >> 1)) * 8 + rr;
        int hp   = (m & 1) ^ ((rowB >> 2) & 1);
        baddr[jp] = sbB + (uint32_t)(rowB * 32 + hp * 16);
    }

    float acc[2][8][4];
    #pragma unroll
    for (int i = 0; i < 2; ++i)
        #pragma unroll
        for (int j = 0; j < 8; ++j)
            #pragma unroll
            for (int v = 0; v < 4; ++v) acc[i][j][v] = 0.0f;

    uint4 va, vb;
    auto load_chunk = [&](int c) {
        int t  = (c >= 2 * KCH) ? 2 : (c >= KCH ? 1 : 0);
        int kc = (c - t * KCH) * 16;
        bool aval = (lpos + t) < SEG;   // forward conv window inside segment
        va = make_uint4(0, 0, 0, 0);
        if (aval) va = *(const uint4*)&X[(size_t)(gr + t) * DP + kc + h * 8];
        vb = *(const uint4*)&g_filt_bf[((size_t)gf * FS + t) * DP + kc + h * 8];
    };

    load_chunk(0);
    for (int c = 0; c < NCHK; ++c) {
        As4[slot] = va;
        Bs4[slot] = vb;
        __syncthreads();
        if (c + 1 < NCHK) load_chunk(c + 1);   // overlap LDG with compute

        uint32_t a[2][4], bb[8][2];
        #pragma unroll
        for (int i = 0; i < 2; ++i)
            ldsm4(a[i][0], a[i][1], a[i][2], a[i][3], aaddr[i]);
        #pragma unroll
        for (int jp = 0; jp < 4; ++jp)
            ldsm4(bb[2 * jp][0], bb[2 * jp][1], bb[2 * jp + 1][0], bb[2 * jp + 1][1],
                  baddr[jp]);

        #pragma unroll
        for (int j = 0; j < 8; ++j)
            #pragma unroll
            for (int i = 0; i < 2; ++i)
                mma_bf16(acc[i][j][0], acc[i][j][1], acc[i][j][2], acc[i][j][3],
                         a[i][0], a[i][1], a[i][2], a[i][3], bb[j][0], bb[j][1]);
        __syncthreads();
    }

    // ---- epilogue: R % 128 == 0, F tiles exact ----
    const int g   = lane >> 2;
    const int tig = lane & 3;
    #pragma unroll
    for (int i = 0; i < 2; ++i) {
        int r0 = rbase + wm + i * 16 + g;
        #pragma unroll
        for (int j = 0; j < 8; ++j) {
            int col = fbase + wn + j * 8 + tig * 2;
            float* o0 = out + (size_t)r0 * F + col;
            *(float2*)o0 = make_float2(acc[i][j][0], acc[i][j][1]);
            *(float2*)(o0 + (size_t)8 * F) = make_float2(acc[i][j][2], acc[i][j][3]);
        }
    }
}

// ---------------- row norms over F=256 ----------------
__global__ void rownorm_kernel(int R, int which) {
    const float* X = which ? g_sc : g_qc;
    float*     nrm = which ? g_scn : g_qcn;
    int warp = (blockIdx.x * blockDim.x + threadIdx.x) >> 5;
    int lane = threadIdx.x & 31;
    if (warp >= R) return;
    const float* row = X + (size_t)warp * F;
    float4 a = *(const float4*)&row[lane * 4];
    float4 b = *(const float4*)&row[128 + lane * 4];
    float ss = a.x * a.x + a.y * a.y + a.z * a.z + a.w * a.w
             + b.x * b.x + b.y * b.y + b.z * b.z + b.w * b.w;
    #pragma unroll
    for (int o = 16; o; o >>= 1) ss += __shfl_xor_sync(0xffffffffu, ss, o);
    if (lane == 0) nrm[warp] = sqrtf(ss);
}

// ---------------- cosine sim: per (b, l-chunk of 512): 32 q x 512 l dots over KD
template<int KD, int KC, int WHICH>
__global__ void __launch_bounds__(256) sim_kernel() {
    const float* Q  = WHICH ? g_qc  : g_qe;
    const float* S  = WHICH ? g_sc  : g_se;
    const float* qn = WHICH ? g_qcn : g_qn;
    const float* sn = WHICH ? g_scn : g_sn;
    float*      sim = WHICH ? g_simsen : g_simins;

    constexpr int SROW_F4 = KC / 4;
    constexpr int CHUNKS  = KD / KC;
    __shared__ float Qs[KC * 32];
    __shared__ float Ss[KC * 516];

    int b     = blockIdx.y;
    int lbase = blockIdx.x * 512;
    int tid   = threadIdx.x;
    int tx = tid & 31, ty = tid >> 5;

    const float* Qb = Q + (size_t)b * LQ * KD;
    const float* Sb = S + (size_t)b * LT * KD;

    float acc[4][16];
    #pragma unroll
    for (int i = 0; i < 4; ++i)
        #pragma unroll
        for (int j = 0; j < 16; ++j) acc[i][j] = 0.0f;

    for (int ch = 0; ch < CHUNKS; ++ch) {
        int k0 = ch * KC;
        __syncthreads();
        if (tid < 32 * SROW_F4) {
            int q = tid / SROW_F4, cc = tid % SROW_F4;
            float4 v = *(const float4*)&Qb[(size_t)q * KD + k0 + cc * 4];
            Qs[(cc * 4 + 0) * 32 + q] = v.x;
            Qs[(cc * 4 + 1) * 32 + q] = v.y;
            Qs[(cc * 4 + 2) * 32 + q] = v.z;
            Qs[(cc * 4 + 3) * 32 + q] = v.w;
        }
        #pragma unroll
        for (int i = 0; i < 2 * SROW_F4; ++i) {
            int flat = tid + 256 * i;
            int lo = flat / SROW_F4, cc = flat % SROW_F4;
            int gl = lbase + lo;
            float4 v = make_float4(0.f, 0.f, 0.f, 0.f);
            if (gl < LT) v = *(const float4*)&Sb[(size_t)gl * KD + k0 + cc * 4];
            Ss[(cc * 4 + 0) * 516 + lo] = v.x;
            Ss[(cc * 4 + 1) * 516 + lo] = v.y;
            Ss[(cc * 4 + 2) * 516 + lo] = v.z;
            Ss[(cc * 4 + 3) * 516 + lo] = v.w;
        }
        __syncthreads();
        #pragma unroll
        for (int kk = 0; kk < KC; ++kk) {
            float4 qv = *(const float4*)&Qs[kk * 32 + ty * 4];
            float qa[4] = {qv.x, qv.y, qv.z, qv.w};
            #pragma unroll
            for (int jj = 0; jj < 4; ++jj) {
                float4 sv = *(const float4*)&Ss[kk * 516 + jj * 128 + tx * 4];
                float sa[4] = {sv.x, sv.y, sv.z, sv.w};
                #pragma unroll
                for (int qq = 0; qq < 4; ++qq)
                    #pragma unroll
                    for (int ll = 0; ll < 4; ++ll)
                        acc[qq][jj * 4 + ll] += qa[qq] * sa[ll];
            }
        }
    }

    float qnv[4];
    #pragma unroll
    for (int qq = 0; qq < 4; ++qq) qnv[qq] = qn[b * LQ + ty * 4 + qq];

    #pragma unroll
    for (int jj = 0; jj < 4; ++jj)
        #pragma unroll
        for (int ll = 0; ll < 4; ++ll) {
            int gl = lbase + jj * 128 + tx * 4 + ll;
            if (gl < LT) {
                float snv = sn[b * LT + gl];
                int n = gl / LS, l = gl % LS;
                #pragma unroll
                for (int qq = 0; qq < 4; ++qq) {
                    size_t oidx = ((((size_t)b * NS + n) * LQ) + (ty * 4 + qq)) * LS + l;
                    sim[oidx] = acc[qq][jj * 4 + ll] / (qnv[qq] * snv);
                }
            }
        }
}

// ---------------- top-k pooling + per-q linear + sigmoid + mean over q ----------------
__device__ __forceinline__ void insert5(float* t, float v) {
    if (v > t[4]) {
        t[4] = v;
        #pragma unroll
        for (int i = 4; i > 0; --i) {
            if (t[i] > t[i - 1]) { float tmp = t[i - 1]; t[i - 1] = t[i]; t[i] = tmp; }
        }
    }
}

__global__ void pool_kernel(const int* __restrict__ question,
                            const int* __restrict__ sentences,
                            const float* __restrict__ W,
                            const float* __restrict__ bias,
                            float* __restrict__ out_sent) {
    int bn = blockIdx.x;     // b*NS + n
    int b  = bn / NS;
    int q  = threadIdx.x;    // 0..31
    bool qm = question[b * LQ + q] > 0;

    const float* si   = g_simins + ((size_t)bn * LQ + q) * LS;
    const float* ssen = g_simsen + ((size_t)bn * LQ + q) * LS;
    const int*   sent = sentences + (size_t)bn * LS;

    float ti[5] = {-INFINITY, -INFINITY, -INFINITY, -INFINITY, -INFINITY};
    float tc[5] = {-INFINITY, -INFINITY, -INFINITY, -INFINITY, -INFINITY};
    int cnt = 0;
    const float thr = (float)(1.0 - 1e-5);

    for (int l = 0; l < LS; ++l) {
        float m  = (qm && sent[l] > 0) ? 1.0f : 0.0f;
        float vi = si[l];
        if (vi >= thr) ++cnt;                 // oh channel uses UNMASKED sim
        insert5(ti, vi * m);
        insert5(tc, ssen[l] * m);
    }
    float insMean = (ti[0] + ti[1] + ti[2] + ti[3] + ti[4]) * 0.2f;
    float senMean = (tc[0] + tc[1] + tc[2] + tc[3] + tc[4]) * 0.2f;
    float ohMax   = (cnt > 0) ? 1.0f : 0.0f;
    float ohMean  = fminf((float)cnt, 5.0f) * 0.2f;

    float z = W[0] * ti[0] + W[1] * insMean + W[2] * tc[0] + W[3] * senMean
            + W[4] * ohMax + W[5] * ohMean + bias[0];
    float p = 1.0f / (1.0f + expf(-z));

    #pragma unroll
    for (int o = 16; o; o >>= 1) p += __shfl_xor_sync(0xffffffffu, p, o);
    if (q == 0) {
        float sr = p * (1.0f / (float)LQ);
        g_sentrel[bn] = sr;
        if (out_sent) out_sent[bn] = sr;
    }
}

// ---------------- doc max + BCE losses ----------------
__global__ void final_kernel(const int* __restrict__ tsents,
                             const int* __restrict__ tdocs,
                             float* __restrict__ out_loss,
                             float* __restrict__ out_doc) {
    __shared__ float red[256];
    __shared__ float docs_s[Bq];
    int tid = threadIdx.x;
    const float eps = 1e-7f;
    const float hi  = (float)(1.0 - 1e-7);

    float s1 = 0.0f;
    for (int i = tid; i < Bq * NS; i += 256) {
        float p = fminf(fmaxf(g_sentrel[i], eps), hi);
        float t = (float)tsents[i];
        s1 += t * logf(p) + (1.0f - t) * log1pf(-p);
    }
    red[tid] = s1;
    __syncthreads();
    for (int s = 128; s > 0; s >>= 1) {
        if (tid < s) red[tid] += red[tid + s];
        __syncthreads();
    }
    float bce1 = -red[0] / (float)(Bq * NS);
    __syncthreads();

    if (tid < Bq) {
        float m = -INFINITY;
        for (int n = 0; n < NS; ++n) m = fmaxf(m, g_sentrel[tid * NS + n]);
        docs_s[tid] = m;
        if (out_doc) out_doc[tid] = m;
    }
    __syncthreads();

    float s2 = 0.0f;
    if (tid < Bq) {
        float p = fminf(fmaxf(docs_s[tid], eps), hi);
        float t = (float)tdocs[tid];
        s2 = t * logf(p) + (1.0f - t) * log1pf(-p);
    }
    red[tid] = s2;
    __syncthreads();
    for (int s = 128; s > 0; s >>= 1) {
        if (tid < s) red[tid] += red[tid + s];
        __syncthreads();
    }
    if (tid == 0) {
        float bce2 = -red[0] / (float)Bq;
        out_loss[0] = 0.5f * (bce1 + bce2);
    }
}

// ---------------- host ----------------
extern "C" void kernel_launch(void* const* d_in, const int* in_sizes, int n_in,
                              void* d_out, int out_size) {
    const int *sentences = nullptr, *question = nullptr, *tsents = nullptr, *tdocs = nullptr;
    const float *embeds = nullptr, *filters = nullptr, *W = nullptr, *bias = nullptr;

    for (int i = 0; i < n_in; ++i) {
        switch (in_sizes[i]) {
            case SROWS:        sentences = (const int*)d_in[i];  break; // 192000
            case QROWS:        question  = (const int*)d_in[i];  break; // 2048
            case Bq * NS:      tsents    = (const int*)d_in[i];  break; // 3200
            case Bq:           tdocs     = (const int*)d_in[i];  break; // 64
            case Vv * D:       embeds    = (const float*)d_in[i]; break;
            case F * FS * D:   filters   = (const float*)d_in[i]; break; // 230400
            case 6:            W         = (const float*)d_in[i]; break;
            case 1:            bias      = (const float*)d_in[i]; break;
            default: break;
        }
    }

    float* out = (float*)d_out;
    float* out_sent = (out_size >= 1 + Bq * NS)      ? out + 1            : nullptr;
    float* out_doc  = (out_size >= 1 + Bq * NS + Bq) ? out + 1 + Bq * NS  : nullptr;

    // 0: filters -> bf16 (padded)
    filt_convert_kernel<<<(F * FS * D + 255) / 256, 256>>>(filters);

    // 1-2: gather embeddings (fp32 + bf16 copies) + L2 norms
    gather_norm_kernel<<<(QROWS * 32 + 255) / 256, 256>>>(embeds, question, QROWS, 0);
    gather_norm_kernel<<<(SROWS * 32 + 255) / 256, 256>>>(embeds, sentences, SROWS, 1);

    // 3-4: forward conv (zero-pad at segment end) as single-pass bf16 tensor-core GEMM
    conv_mma_kernel<LQ><<<dim3(QROWS / 128, F / 128), 256>>>(QROWS, 0);
    conv_mma_kernel<LS><<<dim3(SROWS / 128, F / 128), 256>>>(SROWS, 1);

    // 5-6: conv-output norms
    rownorm_kernel<<<(QROWS * 32 + 255) / 256, 256>>>(QROWS, 0);
    rownorm_kernel<<<(SROWS * 32 + 255) / 256, 256>>>(SROWS, 1);

    // 7-8: cosine similarity matrices
    sim_kernel<300, 12, 0><<<dim3((LT + 511) / 512, Bq), 256>>>();
    sim_kernel<256, 16, 1><<<dim3((LT + 511) / 512, Bq), 256>>>();

    // 9: top-k pooling + linear + sigmoid + mean over q
    pool_kernel<<<Bq * NS, 32>>>(question, sentences, W, bias, out_sent);

    // 10: doc max + BCE
    final_kernel<<<1, 256>>>(tsents, tdocs, out, out_doc);
}

// round 9
// speedup vs baseline: 2.5154x; 1.3811x over previous
#include <cuda_runtime.h>
#include <cuda_bf16.h>
#include <cstdint>
#include <math.h>

// ---------------- problem constants ----------------
constexpr int Bq   = 64;     // batch
constexpr int NS   = 50;     // sentences per doc
constexpr int LS   = 60;     // sentence length
constexpr int LQ   = 32;     // question length
constexpr int D    = 300;    // embedding dim
constexpr int DP   = 320;    // padded embedding dim (32-elem multiple)
constexpr int F    = 256;    // conv filters
constexpr int FS   = 3;      // filter size
constexpr int Vv   = 100000; // vocab
constexpr int QROWS = Bq * LQ;        // 2048
constexpr int SROWS = Bq * NS * LS;   // 192000
constexpr int LT    = NS * LS;        // 3000

constexpr int STPT = DP / 32;   // 10 stages (32 k each) per tap
constexpr int NST  = FS * STPT; // 30 conv stages

// ---------------- device scratch (no allocs; __device__ globals zero-init) ----------------
__device__ __nv_bfloat16 g_qe_bf[(QROWS + 2) * DP];  // bf16 question embeds (pads stay 0)
__device__ __nv_bfloat16 g_se_bf[(SROWS + 2) * DP];  // bf16 sentence embeds
__device__ __nv_bfloat16 g_filt_bf[F * FS * DP];     // bf16 filters, k padded
__device__ float g_qn[QROWS];            // |qe_bf|
__device__ float g_sn[SROWS];            // |se_bf|
__device__ __nv_bfloat16 g_qc_bf[QROWS * F];   // conv(question) bf16
__device__ __nv_bfloat16 g_sc_bf[SROWS * F];   // conv(sentences) bf16
__device__ float g_qcn[QROWS];
__device__ float g_scn[SROWS];
__device__ float g_simins[Bq * NS * LQ * LS];  // [b][n][q][l] fp32 (threshold needs precision)
__device__ float g_simsen[Bq * NS * LQ * LS];
__device__ float g_sentrel[Bq * NS];

// ---------------- asm helpers ----------------
__device__ __forceinline__ void mma_bf16(float* c,
                                         uint32_t a0, uint32_t a1, uint32_t a2, uint32_t a3,
                                         uint32_t b0, uint32_t b1) {
    asm volatile("mma.sync.aligned.m16n8k16.row.col.f32.bf16.bf16.f32 "
                 "{%0,%1,%2,%3},{%4,%5,%6,%7},{%8,%9},{%0,%1,%2,%3};"
                 : "+f"(c[0]), "+f"(c[1]), "+f"(c[2]), "+f"(c[3])
                 : "r"(a0), "r"(a1), "r"(a2), "r"(a3), "r"(b0), "r"(b1));
}
__device__ __forceinline__ void ldsm4(uint32_t& r0, uint32_t& r1, uint32_t& r2, uint32_t& r3,
                                      uint32_t addr) {
    asm volatile("ldmatrix.sync.aligned.m8n8.x4.shared.b16 {%0,%1,%2,%3}, [%4];"
                 : "=r"(r0), "=r"(r1), "=r"(r2), "=r"(r3) : "r"(addr));
}
__device__ __forceinline__ void cp_async16(uint32_t dst, const void* src, uint32_t srcsz) {
    asm volatile("cp.async.ca.shared.global [%0], [%1], 16, %2;"
                 :: "r"(dst), "l"(src), "r"(srcsz));
}
__device__ __forceinline__ void cp_commit() { asm volatile("cp.async.commit_group;"); }
__device__ __forceinline__ void cp_wait0()  { asm volatile("cp.async.wait_group 0;"); }

// ---------------- gather -> bf16 + norm (from bf16 values) ----------------
__global__ void gather_norm_kernel(const float* __restrict__ embeds,
                                   const int* __restrict__ tokens,
                                   int nrows, int which) {
    int warp = (blockIdx.x * blockDim.x + threadIdx.x) >> 5;
    int lane = threadIdx.x & 31;
    if (warp >= nrows) return;
    __nv_bfloat16* dbf = which ? g_se_bf : g_qe_bf;
    float*         nrm = which ? g_sn    : g_qn;
    int tok = tokens[warp];
    const float* src = embeds + (size_t)tok * D;
    __nv_bfloat16* brow = dbf + (size_t)warp * DP;
    float ss = 0.0f;
    for (int i = lane; i < D; i += 32) {
        __nv_bfloat16 bv = __float2bfloat16(src[i]);
        brow[i] = bv;
        float vb = __bfloat162float(bv);
        ss += vb * vb;
    }
    #pragma unroll
    for (int o = 16; o; o >>= 1) ss += __shfl_xor_sync(0xffffffffu, ss, o);
    if (lane == 0) nrm[warp] = sqrtf(ss);
}

// ---------------- filter fp32 -> bf16 (k padded; pad stays zero) ----------------
__global__ void filt_convert_kernel(const float* __restrict__ filt) {
    int idx = blockIdx.x * blockDim.x + threadIdx.x;  // over F*FS*D
    if (idx >= F * FS * D) return;
    int f = idx / (FS * D);
    int r = idx % (FS * D);
    int t = r / D;
    int k = r % D;
    g_filt_bf[((size_t)f * FS + t) * DP + k] = __float2bfloat16(filt[idx]);
}

// ============================================================================
// conv as GEMM (bf16 HMMA, cp.async double-buffered, 32k stages):
//   out[r,f] = sum_{t<3, l+t<SEG} X[r+t,:] . filt[f,t,:]
// Block tile 128x128, 8 warps (4M x 2N). SMEM rows: 64B (4 x 16B slots),
// slot swizzle phys = sl ^ ((row>>1)&3) -> conflict-free ldmatrix.
// ============================================================================
template<int SEG>
__global__ void __launch_bounds__(256) conv_mma_kernel(int which) {
    const __nv_bfloat16* X = which ? g_se_bf : g_qe_bf;
    __nv_bfloat16* out = which ? g_sc_bf : g_qc_bf;

    __shared__ __align__(16) uint8_t sm[32768];  // A: 2x8KB @0, B: 2x8KB @16384
    uint32_t sb = (uint32_t)__cvta_generic_to_shared(sm);

    const int tid  = threadIdx.x;
    const int lane = tid & 31;
    const int wid  = tid >> 5;
    const int wm   = (wid & 3) * 32;
    const int wn   = (wid >> 2) * 64;
    const int m    = lane >> 3;
    const int rr   = lane & 7;

    const int rbase = blockIdx.x * 128;
    const int fbase = blockIdx.y * 128;

    // loader role: row = tid>>1, two 16B slots h = (tid&1)*2 + {0,1}
    const int arow  = tid >> 1;
    const int hbase = (tid & 1) * 2;
    const int gr    = rbase + arow;
    const int lpos  = gr % SEG;
    const int gf    = fbase + arow;
    const int swz   = (arow >> 1) & 3;

    float acc[2][8][4];
    #pragma unroll
    for (int i = 0; i < 2; ++i)
        #pragma unroll
        for (int j = 0; j < 8; ++j)
            #pragma unroll
            for (int v = 0; v < 4; ++v) acc[i][j][v] = 0.0f;

    auto issue = [&](int s, int buf) {
        int tap = s / STPT;
        int kc  = (s % STPT) * 32;
        uint32_t asz = ((lpos + tap) < SEG) ? 16u : 0u;
        const __nv_bfloat16* ap = X + (size_t)(gr + tap) * DP + kc;
        const __nv_bfloat16* bp = g_filt_bf + ((size_t)gf * FS + tap) * DP + kc;
        #pragma unroll
        for (int e = 0; e < 2; ++e) {
            int h = hbase + e;
            int phys = h ^ swz;
            uint32_t da = sb + buf * 8192 + arow * 64 + phys * 16;
            uint32_t db = da + 16384;
            cp_async16(da, ap + h * 8, asz);
            cp_async16(db, bp + h * 8, 16u);
        }
    };

    issue(0, 0);
    cp_commit();

    for (int s = 0; s < NST; ++s) {
        cp_wait0();
        __syncthreads();
        if (s + 1 < NST) { issue(s + 1, (s + 1) & 1); cp_commit(); }
        int buf = s & 1;
        uint32_t abase = sb + buf * 8192;
        uint32_t bbase = abase + 16384;

        #pragma unroll
        for (int c = 0; c < 2; ++c) {
            uint32_t a[2][4];
            #pragma unroll
            for (int i = 0; i < 2; ++i) {
                int rowA = wm + i * 16 + (m & 1) * 8 + rr;
                int phys = (2 * c + (m >> 1)) ^ ((rowA >> 1) & 3);
                ldsm4(a[i][0], a[i][1], a[i][2], a[i][3],
                      abase + (uint32_t)(rowA * 64 + phys * 16));
            }
            uint32_t bbv[8][2];
            #pragma unroll
            for (int jp = 0; jp < 4; ++jp) {
                int rowB = wn + (jp * 2 + (m >> 1)) * 8 + rr;
                int phys = (2 * c + (m & 1)) ^ ((rowB >> 1) & 3);
                ldsm4(bbv[2 * jp][0], bbv[2 * jp][1], bbv[2 * jp + 1][0], bbv[2 * jp + 1][1],
                      bbase + (uint32_t)(rowB * 64 + phys * 16));
            }
            #pragma unroll
            for (int j = 0; j < 8; ++j)
                #pragma unroll
                for (int i = 0; i < 2; ++i)
                    mma_bf16(acc[i][j], a[i][0], a[i][1], a[i][2], a[i][3],
                             bbv[j][0], bbv[j][1]);
        }
        __syncthreads();
    }

    // ---- epilogue: bf16 output ----
    const int g   = lane >> 2;
    const int tig = lane & 3;
    #pragma unroll
    for (int i = 0; i < 2; ++i) {
        int r0 = rbase + wm + i * 16 + g;
        #pragma unroll
        for (int j = 0; j < 8; ++j) {
            int col = fbase + wn + j * 8 + tig * 2;
            __nv_bfloat16* o0 = out + (size_t)r0 * F + col;
            *(__nv_bfloat162*)o0 =
                __halves2bfloat162(__float2bfloat16(acc[i][j][0]), __float2bfloat16(acc[i][j][1]));
            *(__nv_bfloat162*)(o0 + (size_t)8 * F) =
                __halves2bfloat162(__float2bfloat16(acc[i][j][2]), __float2bfloat16(acc[i][j][3]));
        }
    }
}

// ---------------- row norms over F=256 (bf16 input) ----------------
__global__ void rownorm_kernel(int R, int which) {
    const __nv_bfloat16* X = which ? g_sc_bf : g_qc_bf;
    float* nrm = which ? g_scn : g_qcn;
    int warp = (blockIdx.x * blockDim.x + threadIdx.x) >> 5;
    int lane = threadIdx.x & 31;
    if (warp >= R) return;
    const __nv_bfloat16* row = X + (size_t)warp * F;
    uint4 u = *(const uint4*)&row[lane * 8];
    float ss = 0.0f;
    uint32_t w[4] = {u.x, u.y, u.z, u.w};
    #pragma unroll
    for (int i = 0; i < 4; ++i) {
        float2 p = __bfloat1622float2(*(__nv_bfloat162*)&w[i]);
        ss += p.x * p.x + p.y * p.y;
    }
    #pragma unroll
    for (int o = 16; o; o >>= 1) ss += __shfl_xor_sync(0xffffffffu, ss, o);
    if (lane == 0) nrm[warp] = sqrtf(ss);
}

// ============================================================================
// cosine sim on tensor cores: per (l-tile 128, b): num[l][q] = S[l,:].Q[q,:]
// Q (32 x KT) resident in SMEM (odd-slot stride), S streamed 32k/stage (cp.async,
// double buffer, conv-style swizzle). 8 warps x 16 l-rows. Output fp32 normalized.
// ============================================================================
template<int KT, int WHICH>
__global__ void __launch_bounds__(256) sim_mma_kernel() {
    constexpr int QS   = KT + 8;        // Q smem row stride (odd 16B-slot count)
    constexpr int STG  = KT / 32;       // stages
    constexpr int SSTR = WHICH ? F : DP;  // global S row stride
    constexpr int QSTR = WHICH ? F : DP;  // global Q row stride

    const __nv_bfloat16* Qg = WHICH ? g_qc_bf : g_qe_bf;
    const __nv_bfloat16* Sg = WHICH ? g_sc_bf : g_se_bf;
    const float* qnG = WHICH ? g_qcn : g_qn;
    const float* snG = WHICH ? g_scn : g_sn;
    float* sim = WHICH ? g_simsen : g_simins;

    __shared__ __align__(16) uint8_t sS[16384];          // S pipe: 2 x 8KB
    __shared__ __align__(16) __nv_bfloat16 Qs[32 * QS];
    __shared__ float qns[LQ];

    const int b     = blockIdx.y;
    const int lbase = blockIdx.x * 128;
    const int tid   = threadIdx.x;
    const int lane  = tid & 31;
    const int wid   = tid >> 5;
    const int m     = lane >> 3;
    const int rr    = lane & 7;

    uint32_t sbS = (uint32_t)__cvta_generic_to_shared(sS);
    uint32_t sbQ = (uint32_t)__cvta_generic_to_shared(Qs);

    const __nv_bfloat16* Qbg = Qg + (size_t)b * LQ * QSTR;
    const __nv_bfloat16* Sbg = Sg + (size_t)b * LT * SSTR;

    // ---- load Q tile + qn into smem ----
    for (int idx = tid; idx < 32 * (KT / 8); idx += 256) {
        int row = idx / (KT / 8);
        int s8  = idx % (KT / 8);
        *(uint4*)&Qs[row * QS + s8 * 8] = *(const uint4*)&Qbg[(size_t)row * QSTR + s8 * 8];
    }
    if (tid < LQ) qns[tid] = qnG[b * LQ + tid];

    // ---- S stage loader ----
    const int srow  = tid >> 1;
    const int hbase = (tid & 1) * 2;
    const int gl    = lbase + srow;
    const int swz   = (srow >> 1) & 3;
    const uint32_t ssz = (gl < LT) ? 16u : 0u;
    auto issueS = [&](int s, int buf) {
        int kc = s * 32;
        const __nv_bfloat16* sp = Sbg + (size_t)gl * SSTR + kc;
        #pragma unroll
        for (int e = 0; e < 2; ++e) {
            int h = hbase + e;
            int phys = h ^ swz;
            cp_async16(sbS + buf * 8192 + srow * 64 + phys * 16, sp + h * 8, ssz);
        }
    };

    float acc[4][4];
    #pragma unroll
    for (int t = 0; t < 4; ++t)
        #pragma unroll
        for (int v = 0; v < 4; ++v) acc[t][v] = 0.0f;

    issueS(0, 0);
    cp_commit();

    for (int s = 0; s < STG; ++s) {
        cp_wait0();
        __syncthreads();
        if (s + 1 < STG) { issueS(s + 1, (s + 1) & 1); cp_commit(); }
        uint32_t abase = sbS + (s & 1) * 8192;

        #pragma unroll
        for (int c = 0; c < 2; ++c) {
            uint32_t a[4];
            int rowS = wid * 16 + (m & 1) * 8 + rr;
            int phys = (2 * c + (m >> 1)) ^ ((rowS >> 1) & 3);
            ldsm4(a[0], a[1], a[2], a[3], abase + (uint32_t)(rowS * 64 + phys * 16));

            int cg = s * 2 + c;
            uint32_t qb[4][2];
            #pragma unroll
            for (int jp = 0; jp < 2; ++jp) {
                int rowq = (jp * 2 + (m >> 1)) * 8 + rr;
                uint32_t qaddr = sbQ + (uint32_t)(rowq * (QS * 2) + (cg * 16 + (m & 1) * 8) * 2);
                ldsm4(qb[2 * jp][0], qb[2 * jp][1], qb[2 * jp + 1][0], qb[2 * jp + 1][1], qaddr);
            }
            #pragma unroll
            for (int t = 0; t < 4; ++t)
                mma_bf16(acc[t], a[0], a[1], a[2], a[3], qb[t][0], qb[t][1]);
        }
        __syncthreads();
    }

    // ---- epilogue: normalize & scatter fp32 ----
    const int g   = lane >> 2;
    const int tig = lane & 3;
    int l0 = lbase + wid * 16 + g;
    int l1 = l0 + 8;
    float sn0 = (l0 < LT) ? snG[(size_t)b * LT + l0] : 1.0f;
    float sn1 = (l1 < LT) ? snG[(size_t)b * LT + l1] : 1.0f;
    int n0 = l0 / LS, ll0 = l0 % LS;
    int n1 = l1 / LS, ll1 = l1 % LS;
    #pragma unroll
    for (int t = 0; t < 4; ++t) {
        int q0 = t * 8 + tig * 2;
        float qn0 = qns[q0], qn1 = qns[q0 + 1];
        if (l0 < LT) {
            size_t base = (((size_t)b * NS + n0) * LQ) * LS + ll0;
            sim[base + (size_t)q0 * LS]       = acc[t][0] / (qn0 * sn0);
            sim[base + (size_t)(q0 + 1) * LS] = acc[t][1] / (qn1 * sn0);
        }
        if (l1 < LT) {
            size_t base = (((size_t)b * NS + n1) * LQ) * LS + ll1;
            sim[base + (size_t)q0 * LS]       = acc[t][2] / (qn0 * sn1);
            sim[base + (size_t)(q0 + 1) * LS] = acc[t][3] / (qn1 * sn1);
        }
    }
}

// ---------------- top-k pooling + per-q linear + sigmoid + mean over q ----------------
__device__ __forceinline__ void insert5(float* t, float v) {
    if (v > t[4]) {
        t[4] = v;
        #pragma unroll
        for (int i = 4; i > 0; --i) {
            if (t[i] > t[i - 1]) { float tmp = t[i - 1]; t[i - 1] = t[i]; t[i] = tmp; }
        }
    }
}

__global__ void pool_kernel(const int* __restrict__ question,
                            const int* __restrict__ sentences,
                            const float* __restrict__ W,
                            const float* __restrict__ bias,
                            float* __restrict__ out_sent) {
    int bn = blockIdx.x;     // b*NS + n
    int b  = bn / NS;
    int q  = threadIdx.x;    // 0..31
    bool qm = question[b * LQ + q] > 0;

    const float* si   = g_simins + ((size_t)bn * LQ + q) * LS;
    const float* ssen = g_simsen + ((size_t)bn * LQ + q) * LS;
    const int*   sent = sentences + (size_t)bn * LS;

    float ti[5] = {-INFINITY, -INFINITY, -INFINITY, -INFINITY, -INFINITY};
    float tc[5] = {-INFINITY, -INFINITY, -INFINITY, -INFINITY, -INFINITY};
    int cnt = 0;
    const float thr = (float)(1.0 - 1e-5);

    for (int l = 0; l < LS; ++l) {
        float m  = (qm && sent[l] > 0) ? 1.0f : 0.0f;
        float vi = si[l];
        if (vi >= thr) ++cnt;                 // oh channel uses UNMASKED sim
        insert5(ti, vi * m);
        insert5(tc, ssen[l] * m);
    }
    float insMean = (ti[0] + ti[1] + ti[2] + ti[3] + ti[4]) * 0.2f;
    float senMean = (tc[0] + tc[1] + tc[2] + tc[3] + tc[4]) * 0.2f;
    float ohMax   = (cnt > 0) ? 1.0f : 0.0f;
    float ohMean  = fminf((float)cnt, 5.0f) * 0.2f;

    float z = W[0] * ti[0] + W[1] * insMean + W[2] * tc[0] + W[3] * senMean
            + W[4] * ohMax + W[5] * ohMean + bias[0];
    float p = 1.0f / (1.0f + expf(-z));

    #pragma unroll
    for (int o = 16; o; o >>= 1) p += __shfl_xor_sync(0xffffffffu, p, o);
    if (q == 0) {
        float sr = p * (1.0f / (float)LQ);
        g_sentrel[bn] = sr;
        if (out_sent) out_sent[bn] = sr;
    }
}

// ---------------- doc max + BCE losses ----------------
__global__ void final_kernel(const int* __restrict__ tsents,
                             const int* __restrict__ tdocs,
                             float* __restrict__ out_loss,
                             float* __restrict__ out_doc) {
    __shared__ float red[256];
    __shared__ float docs_s[Bq];
    int tid = threadIdx.x;
    const float eps = 1e-7f;
    const float hi  = (float)(1.0 - 1e-7);

    float s1 = 0.0f;
    for (int i = tid; i < Bq * NS; i += 256) {
        float p = fminf(fmaxf(g_sentrel[i], eps), hi);
        float t = (float)tsents[i];
        s1 += t * logf(p) + (1.0f - t) * log1pf(-p);
    }
    red[tid] = s1;
    __syncthreads();
    for (int s = 128; s > 0; s >>= 1) {
        if (tid < s) red[tid] += red[tid + s];
        __syncthreads();
    }
    float bce1 = -red[0] / (float)(Bq * NS);
    __syncthreads();

    if (tid < Bq) {
        float m = -INFINITY;
        for (int n = 0; n < NS; ++n) m = fmaxf(m, g_sentrel[tid * NS + n]);
        docs_s[tid] = m;
        if (out_doc) out_doc[tid] = m;
    }
    __syncthreads();

    float s2 = 0.0f;
    if (tid < Bq) {
        float p = fminf(fmaxf(docs_s[tid], eps), hi);
        float t = (float)tdocs[tid];
        s2 = t * logf(p) + (1.0f - t) * log1pf(-p);
    }
    red[tid] = s2;
    __syncthreads();
    for (int s = 128; s > 0; s >>= 1) {
        if (tid < s) red[tid] += red[tid + s];
        __syncthreads();
    }
    if (tid == 0) {
        float bce2 = -red[0] / (float)Bq;
        out_loss[0] = 0.5f * (bce1 + bce2);
    }
}

// ---------------- host ----------------
extern "C" void kernel_launch(void* const* d_in, const int* in_sizes, int n_in,
                              void* d_out, int out_size) {
    const int *sentences = nullptr, *question = nullptr, *tsents = nullptr, *tdocs = nullptr;
    const float *embeds = nullptr, *filters = nullptr, *W = nullptr, *bias = nullptr;

    for (int i = 0; i < n_in; ++i) {
        switch (in_sizes[i]) {
            case SROWS:        sentences = (const int*)d_in[i];  break; // 192000
            case QROWS:        question  = (const int*)d_in[i];  break; // 2048
            case Bq * NS:      tsents    = (const int*)d_in[i];  break; // 3200
            case Bq:           tdocs     = (const int*)d_in[i];  break; // 64
            case Vv * D:       embeds    = (const float*)d_in[i]; break;
            case F * FS * D:   filters   = (const float*)d_in[i]; break; // 230400
            case 6:            W         = (const float*)d_in[i]; break;
            case 1:            bias      = (const float*)d_in[i]; break;
            default: break;
        }
    }

    float* out = (float*)d_out;
    float* out_sent = (out_size >= 1 + Bq * NS)      ? out + 1            : nullptr;
    float* out_doc  = (out_size >= 1 + Bq * NS + Bq) ? out + 1 + Bq * NS  : nullptr;

    // 0: filters -> bf16 (padded)
    filt_convert_kernel<<<(F * FS * D + 255) / 256, 256>>>(filters);

    // 1-2: gather embeddings (bf16 only) + norms
    gather_norm_kernel<<<(QROWS * 32 + 255) / 256, 256>>>(embeds, question, QROWS, 0);
    gather_norm_kernel<<<(SROWS * 32 + 255) / 256, 256>>>(embeds, sentences, SROWS, 1);

    // 3-4: forward conv (zero-pad at segment end), cp.async-pipelined bf16 HMMA
    conv_mma_kernel<LQ><<<dim3(QROWS / 128, F / 128), 256>>>(0);
    conv_mma_kernel<LS><<<dim3(SROWS / 128, F / 128), 256>>>(1);

    // 5-6: conv-output norms (bf16 input)
    rownorm_kernel<<<(QROWS * 32 + 255) / 256, 256>>>(QROWS, 0);
    rownorm_kernel<<<(SROWS * 32 + 255) / 256, 256>>>(SROWS, 1);

    // 7-8: cosine similarity matrices on tensor cores
    sim_mma_kernel<DP, 0><<<dim3((LT + 127) / 128, Bq), 256>>>();
    sim_mma_kernel<F,  1><<<dim3((LT + 127) / 128, Bq), 256>>>();

    // 9: top-k pooling + linear + sigmoid + mean over q
    pool_kernel<<<Bq * NS, 32>>>(question, sentences, W, bias, out_sent);

    // 10: doc max + BCE
    final_kernel<<<1, 256>>>(tsents, tdocs, out, out_doc);
}

// round 11
// speedup vs baseline: 2.6610x; 1.0579x over previous
#include <cuda_runtime.h>
#include <cuda_bf16.h>
#include <cuda_fp8.h>
#include <cstdint>
#include <math.h>

// ---------------- problem constants ----------------
constexpr int Bq   = 64;     // batch
constexpr int NS   = 50;     // sentences per doc
constexpr int LS   = 60;     // sentence length
constexpr int LQ   = 32;     // question length
constexpr int D    = 300;    // embedding dim
constexpr int DP   = 320;    // padded embedding dim
constexpr int F    = 256;    // conv filters
constexpr int FS   = 3;      // filter size
constexpr int Vv   = 100000; // vocab
constexpr int QROWS = Bq * LQ;        // 2048
constexpr int SROWS = Bq * NS * LS;   // 192000
constexpr int LT    = NS * LS;        // 3000

constexpr int STK  = 64;            // K elements (fp8) per stage -> 64B rows
constexpr int STPT = DP / STK;      // 5 stages per tap
constexpr int NSTG = FS * STPT;     // 15 stages

// ---------------- device scratch (no allocs; zero-init) ----------------
__device__ __nv_bfloat16 g_qe_bf[(QROWS + 2) * DP];  // bf16 embeds (sim_ins operands)
__device__ __nv_bfloat16 g_se_bf[(SROWS + 2) * DP];
__device__ uint8_t g_qe_f8[(QROWS + 2) * DP];        // e4m3 embeds (conv operands)
__device__ uint8_t g_se_f8[(SROWS + 2) * DP];
__device__ uint8_t g_filt_f8[F * FS * DP];           // e4m3 filters, k padded
__device__ float g_qn[QROWS];
__device__ float g_sn[SROWS];
__device__ __nv_bfloat16 g_qc_bf[QROWS * F];         // conv outputs (bf16, sim_sen operands)
__device__ __nv_bfloat16 g_sc_bf[SROWS * F];
__device__ float g_qcn[QROWS];
__device__ float g_scn[SROWS];
__device__ float g_simins[Bq * NS * LQ * LS];
__device__ float g_simsen[Bq * NS * LQ * LS];
__device__ float g_sentrel[Bq * NS];

// ---------------- asm helpers ----------------
__device__ __forceinline__ void mma_bf16(float* c,
                                         uint32_t a0, uint32_t a1, uint32_t a2, uint32_t a3,
                                         uint32_t b0, uint32_t b1) {
    asm volatile("mma.sync.aligned.m16n8k16.row.col.f32.bf16.bf16.f32 "
                 "{%0,%1,%2,%3},{%4,%5,%6,%7},{%8,%9},{%0,%1,%2,%3};"
                 : "+f"(c[0]), "+f"(c[1]), "+f"(c[2]), "+f"(c[3])
                 : "r"(a0), "r"(a1), "r"(a2), "r"(a3), "r"(b0), "r"(b1));
}
__device__ __forceinline__ void mma_fp8(float* c,
                                        uint32_t a0, uint32_t a1, uint32_t a2, uint32_t a3,
                                        uint32_t b0, uint32_t b1) {
    asm volatile("mma.sync.aligned.m16n8k32.row.col.f32.e4m3.e4m3.f32 "
                 "{%0,%1,%2,%3},{%4,%5,%6,%7},{%8,%9},{%0,%1,%2,%3};"
                 : "+f"(c[0]), "+f"(c[1]), "+f"(c[2]), "+f"(c[3])
                 : "r"(a0), "r"(a1), "r"(a2), "r"(a3), "r"(b0), "r"(b1));
}
__device__ __forceinline__ void ldsm4(uint32_t& r0, uint32_t& r1, uint32_t& r2, uint32_t& r3,
                                      uint32_t addr) {
    asm volatile("ldmatrix.sync.aligned.m8n8.x4.shared.b16 {%0,%1,%2,%3}, [%4];"
                 : "=r"(r0), "=r"(r1), "=r"(r2), "=r"(r3) : "r"(addr));
}
__device__ __forceinline__ void cp_async16(uint32_t dst, const void* src, uint32_t srcsz) {
    asm volatile("cp.async.ca.shared.global [%0], [%1], 16, %2;"
                 :: "r"(dst), "l"(src), "r"(srcsz));
}
__device__ __forceinline__ void cp_commit() { asm volatile("cp.async.commit_group;" ::: "memory"); }

// ---------------- gather -> bf16 + fp8 + norm (norm from bf16 values) ----------------
__global__ void gather_norm_kernel(const float* __restrict__ embeds,
                                   const int* __restrict__ tokens,
                                   int nrows, int which) {
    int warp = (blockIdx.x * blockDim.x + threadIdx.x) >> 5;
    int lane = threadIdx.x & 31;
    if (warp >= nrows) return;
    __nv_bfloat16* dbf = which ? g_se_bf : g_qe_bf;
    uint8_t*       df8 = which ? g_se_f8 : g_qe_f8;
    float*         nrm = which ? g_sn    : g_qn;
    int tok = tokens[warp];
    const float* src = embeds + (size_t)tok * D;
    __nv_bfloat16* brow = dbf + (size_t)warp * DP;
    uint8_t*       frow = df8 + (size_t)warp * DP;
    float ss = 0.0f;
    for (int i = lane; i < D; i += 32) {
        float v = src[i];
        __nv_bfloat16 bv = __float2bfloat16(v);
        brow[i] = bv;
        __nv_fp8_e4m3 f8(v);
        frow[i] = *(uint8_t*)&f8;
        float vb = __bfloat162float(bv);
        ss += vb * vb;
    }
    #pragma unroll
    for (int o = 16; o; o >>= 1) ss += __shfl_xor_sync(0xffffffffu, ss, o);
    if (lane == 0) nrm[warp] = sqrtf(ss);
}

// ---------------- filter fp32 -> e4m3 (k padded; pad stays zero) ----------------
__global__ void filt_convert_kernel(const float* __restrict__ filt) {
    int idx = blockIdx.x * blockDim.x + threadIdx.x;
    if (idx >= F * FS * D) return;
    int f = idx / (FS * D);
    int r = idx % (FS * D);
    int t = r / D;
    int k = r % D;
    __nv_fp8_e4m3 f8(filt[idx]);
    g_filt_f8[((size_t)f * FS + t) * DP + k] = *(uint8_t*)&f8;
}

// ============================================================================
// conv as GEMM (e4m3 MMA m16n8k32, cp.async double-buffered, 64-fp8 stages):
//   out[r,f] = sum_{t<3, l+t<SEG} X[r+t,:] . filt[f,t,:]
// Block tile 128x128, 8 warps (4M x 2N). SMEM rows: 64B (4 x 16B slots),
// slot swizzle phys = sl ^ ((row>>1)&3) -> conflict-free ldmatrix.
// fp8 fragments reuse the b16 ldmatrix pattern (each b16 = 2 packed fp8).
// ============================================================================
template<int SEG>
__global__ void __launch_bounds__(256) conv_mma_kernel(int which) {
    const uint8_t* X = which ? g_se_f8 : g_qe_f8;
    __nv_bfloat16* out = which ? g_sc_bf : g_qc_bf;

    __shared__ __align__(16) uint8_t sm[32768];  // A: 2x8KB @0, B: 2x8KB @16384
    uint32_t sb = (uint32_t)__cvta_generic_to_shared(sm);

    const int tid  = threadIdx.x;
    const int lane = tid & 31;
    const int wid  = tid >> 5;
    const int wm   = (wid & 3) * 32;
    const int wn   = (wid >> 2) * 64;
    const int m    = lane >> 3;
    const int rr   = lane & 7;

    const int rbase = blockIdx.x * 128;
    const int fbase = blockIdx.y * 128;

    // loader role: row = tid>>1, two 16B slots h = (tid&1)*2 + {0,1}
    const int arow  = tid >> 1;
    const int hbase = (tid & 1) * 2;
    const int gr    = rbase + arow;
    const int lpos  = gr % SEG;
    const int gf    = fbase + arow;
    const int swz   = (arow >> 1) & 3;

    float acc[2][8][4];
    #pragma unroll
    for (int i = 0; i < 2; ++i)
        #pragma unroll
        for (int j = 0; j < 8; ++j)
            #pragma unroll
            for (int v = 0; v < 4; ++v) acc[i][j][v] = 0.0f;

    auto issue = [&](int s, int buf) {
        int tap = s / STPT;
        int kc  = (s % STPT) * STK;
        uint32_t asz = ((lpos + tap) < SEG) ? 16u : 0u;
        const uint8_t* ap = X + (size_t)(gr + tap) * DP + kc;
        const uint8_t* bp = g_filt_f8 + ((size_t)gf * FS + tap) * DP + kc;
        #pragma unroll
        for (int e = 0; e < 2; ++e) {
            int h = hbase + e;
            int phys = h ^ swz;
            uint32_t da = sb + buf * 8192 + arow * 64 + phys * 16;
            uint32_t db = da + 16384;
            cp_async16(da, ap + h * 16, asz);
            cp_async16(db, bp + h * 16, 16u);
        }
    };

    issue(0, 0);
    cp_commit();

    for (int s = 0; s < NSTG; ++s) {
        asm volatile("cp.async.wait_group 0;" ::: "memory");
        __syncthreads();
        if (s + 1 < NSTG) { issue(s + 1, (s + 1) & 1); cp_commit(); }
        int buf = s & 1;
        uint32_t abase = sb + buf * 8192;
        uint32_t bbase = abase + 16384;

        #pragma unroll
        for (int c = 0; c < 2; ++c) {          // two k32 chunks per stage
            uint32_t a[2][4];
            #pragma unroll
            for (int i = 0; i < 2; ++i) {
                int rowA = wm + i * 16 + (m & 1) * 8 + rr;
                int phys = (2 * c + (m >> 1)) ^ ((rowA >> 1) & 3);
                ldsm4(a[i][0], a[i][1], a[i][2], a[i][3],
                      abase + (uint32_t)(rowA * 64 + phys * 16));
            }
            uint32_t bbv[8][2];
            #pragma unroll
            for (int jp = 0; jp < 4; ++jp) {
                int rowB = wn + (jp * 2 + (m >> 1)) * 8 + rr;
                int phys = (2 * c + (m & 1)) ^ ((rowB >> 1) & 3);
                ldsm4(bbv[2 * jp][0], bbv[2 * jp][1], bbv[2 * jp + 1][0], bbv[2 * jp + 1][1],
                      bbase + (uint32_t)(rowB * 64 + phys * 16));
            }
            #pragma unroll
            for (int j = 0; j < 8; ++j)
                #pragma unroll
                for (int i = 0; i < 2; ++i)
                    mma_fp8(acc[i][j], a[i][0], a[i][1], a[i][2], a[i][3],
                            bbv[j][0], bbv[j][1]);
        }
        __syncthreads();
    }

    // ---- epilogue: bf16 output ----
    const int g   = lane >> 2;
    const int tig = lane & 3;
    #pragma unroll
    for (int i = 0; i < 2; ++i) {
        int r0 = rbase + wm + i * 16 + g;
        #pragma unroll
        for (int j = 0; j < 8; ++j) {
            int col = fbase + wn + j * 8 + tig * 2;
            __nv_bfloat16* o0 = out + (size_t)r0 * F + col;
            *(__nv_bfloat162*)o0 =
                __halves2bfloat162(__float2bfloat16(acc[i][j][0]), __float2bfloat16(acc[i][j][1]));
            *(__nv_bfloat162*)(o0 + (size_t)8 * F) =
                __halves2bfloat162(__float2bfloat16(acc[i][j][2]), __float2bfloat16(acc[i][j][3]));
        }
    }
}

// ---------------- row norms over F=256 (bf16 input) ----------------
__global__ void rownorm_kernel(int R, int which) {
    const __nv_bfloat16* X = which ? g_sc_bf : g_qc_bf;
    float* nrm = which ? g_scn : g_qcn;
    int warp = (blockIdx.x * blockDim.x + threadIdx.x) >> 5;
    int lane = threadIdx.x & 31;
    if (warp >= R) return;
    const __nv_bfloat16* row = X + (size_t)warp * F;
    uint4 u = *(const uint4*)&row[lane * 8];
    float ss = 0.0f;
    uint32_t w[4] = {u.x, u.y, u.z, u.w};
    #pragma unroll
    for (int i = 0; i < 4; ++i) {
        float2 p = __bfloat1622float2(*(__nv_bfloat162*)&w[i]);
        ss += p.x * p.x + p.y * p.y;
    }
    #pragma unroll
    for (int o = 16; o; o >>= 1) ss += __shfl_xor_sync(0xffffffffu, ss, o);
    if (lane == 0) nrm[warp] = sqrtf(ss);
}

// ============================================================================
// cosine sim on tensor cores (bf16 HMMA; unchanged from R9 passing version)
// ============================================================================
template<int KT, int WHICH>
__global__ void __launch_bounds__(256) sim_mma_kernel() {
    constexpr int QS   = KT + 8;
    constexpr int STG  = KT / 32;
    constexpr int SSTR = WHICH ? F : DP;
    constexpr int QSTR = WHICH ? F : DP;

    const __nv_bfloat16* Qg = WHICH ? g_qc_bf : g_qe_bf;
    const __nv_bfloat16* Sg = WHICH ? g_sc_bf : g_se_bf;
    const float* qnG = WHICH ? g_qcn : g_qn;
    const float* snG = WHICH ? g_scn : g_sn;
    float* sim = WHICH ? g_simsen : g_simins;

    __shared__ __align__(16) uint8_t sS[16384];
    __shared__ __align__(16) __nv_bfloat16 Qs[32 * QS];
    __shared__ float qns[LQ];

    const int b     = blockIdx.y;
    const int lbase = blockIdx.x * 128;
    const int tid   = threadIdx.x;
    const int lane  = tid & 31;
    const int wid   = tid >> 5;
    const int m     = lane >> 3;
    const int rr    = lane & 7;

    uint32_t sbS = (uint32_t)__cvta_generic_to_shared(sS);
    uint32_t sbQ = (uint32_t)__cvta_generic_to_shared(Qs);

    const __nv_bfloat16* Qbg = Qg + (size_t)b * LQ * QSTR;
    const __nv_bfloat16* Sbg = Sg + (size_t)b * LT * SSTR;

    for (int idx = tid; idx < 32 * (KT / 8); idx += 256) {
        int row = idx / (KT / 8);
        int s8  = idx % (KT / 8);
        *(uint4*)&Qs[row * QS + s8 * 8] = *(const uint4*)&Qbg[(size_t)row * QSTR + s8 * 8];
    }
    if (tid < LQ) qns[tid] = qnG[b * LQ + tid];

    const int srow  = tid >> 1;
    const int hbase = (tid & 1) * 2;
    const int gl    = lbase + srow;
    const int swz   = (srow >> 1) & 3;
    const uint32_t ssz = (gl < LT) ? 16u : 0u;
    auto issueS = [&](int s, int buf) {
        int kc = s * 32;
        const __nv_bfloat16* sp = Sbg + (size_t)gl * SSTR + kc;
        #pragma unroll
        for (int e = 0; e < 2; ++e) {
            int h = hbase + e;
            int phys = h ^ swz;
            cp_async16(sbS + buf * 8192 + srow * 64 + phys * 16, sp + h * 8, ssz);
        }
    };

    float acc[4][4];
    #pragma unroll
    for (int t = 0; t < 4; ++t)
        #pragma unroll
        for (int v = 0; v < 4; ++v) acc[t][v] = 0.0f;

    issueS(0, 0);
    cp_commit();

    for (int s = 0; s < STG; ++s) {
        asm volatile("cp.async.wait_group 0;" ::: "memory");
        __syncthreads();
        if (s + 1 < STG) { issueS(s + 1, (s + 1) & 1); cp_commit(); }
        uint32_t abase = sbS + (s & 1) * 8192;

        #pragma unroll
        for (int c = 0; c < 2; ++c) {
            uint32_t a[4];
            int rowS = wid * 16 + (m & 1) * 8 + rr;
            int phys = (2 * c + (m >> 1)) ^ ((rowS >> 1) & 3);
            ldsm4(a[0], a[1], a[2], a[3], abase + (uint32_t)(rowS * 64 + phys * 16));

            int cg = s * 2 + c;
            uint32_t qb[4][2];
            #pragma unroll
            for (int jp = 0; jp < 2; ++jp) {
                int rowq = (jp * 2 + (m >> 1)) * 8 + rr;
                uint32_t qaddr = sbQ + (uint32_t)(rowq * (QS * 2) + (cg * 16 + (m & 1) * 8) * 2);
                ldsm4(qb[2 * jp][0], qb[2 * jp][1], qb[2 * jp + 1][0], qb[2 * jp + 1][1], qaddr);
            }
            #pragma unroll
            for (int t = 0; t < 4; ++t)
                mma_bf16(acc[t], a[0], a[1], a[2], a[3], qb[t][0], qb[t][1]);
        }
        __syncthreads();
    }

    const int g   = lane >> 2;
    const int tig = lane & 3;
    int l0 = lbase + wid * 16 + g;
    int l1 = l0 + 8;
    float sn0 = (l0 < LT) ? snG[(size_t)b * LT + l0] : 1.0f;
    float sn1 = (l1 < LT) ? snG[(size_t)b * LT + l1] : 1.0f;
    int n0 = l0 / LS, ll0 = l0 % LS;
    int n1 = l1 / LS, ll1 = l1 % LS;
    #pragma unroll
    for (int t = 0; t < 4; ++t) {
        int q0 = t * 8 + tig * 2;
        float qn0 = qns[q0], qn1 = qns[q0 + 1];
        if (l0 < LT) {
            size_t base = (((size_t)b * NS + n0) * LQ) * LS + ll0;
            sim[base + (size_t)q0 * LS]       = acc[t][0] / (qn0 * sn0);
            sim[base + (size_t)(q0 + 1) * LS] = acc[t][1] / (qn1 * sn0);
        }
        if (l1 < LT) {
            size_t base = (((size_t)b * NS + n1) * LQ) * LS + ll1;
            sim[base + (size_t)q0 * LS]       = acc[t][2] / (qn0 * sn1);
            sim[base + (size_t)(q0 + 1) * LS] = acc[t][3] / (qn1 * sn1);
        }
    }
}

// ---------------- top-k pooling + per-q linear + sigmoid + mean over q ----------------
__device__ __forceinline__ void insert5(float* t, float v) {
    if (v > t[4]) {
        t[4] = v;
        #pragma unroll
        for (int i = 4; i > 0; --i) {
            if (t[i] > t[i - 1]) { float tmp = t[i - 1]; t[i - 1] = t[i]; t[i] = tmp; }
        }
    }
}

__global__ void pool_kernel(const int* __restrict__ question,
                            const int* __restrict__ sentences,
                            const float* __restrict__ W,
                            const float* __restrict__ bias,
                            float* __restrict__ out_sent) {
    int bn = blockIdx.x;
    int b  = bn / NS;
    int q  = threadIdx.x;
    bool qm = question[b * LQ + q] > 0;

    const float* si   = g_simins + ((size_t)bn * LQ + q) * LS;
    const float* ssen = g_simsen + ((size_t)bn * LQ + q) * LS;
    const int*   sent = sentences + (size_t)bn * LS;

    float ti[5] = {-INFINITY, -INFINITY, -INFINITY, -INFINITY, -INFINITY};
    float tc[5] = {-INFINITY, -INFINITY, -INFINITY, -INFINITY, -INFINITY};
    int cnt = 0;
    const float thr = (float)(1.0 - 1e-5);

    for (int l = 0; l < LS; ++l) {
        float m  = (qm && sent[l] > 0) ? 1.0f : 0.0f;
        float vi = si[l];
        if (vi >= thr) ++cnt;
        insert5(ti, vi * m);
        insert5(tc, ssen[l] * m);
    }
    float insMean = (ti[0] + ti[1] + ti[2] + ti[3] + ti[4]) * 0.2f;
    float senMean = (tc[0] + tc[1] + tc[2] + tc[3] + tc[4]) * 0.2f;
    float ohMax   = (cnt > 0) ? 1.0f : 0.0f;
    float ohMean  = fminf((float)cnt, 5.0f) * 0.2f;

    float z = W[0] * ti[0] + W[1] * insMean + W[2] * tc[0] + W[3] * senMean
            + W[4] * ohMax + W[5] * ohMean + bias[0];
    float p = 1.0f / (1.0f + expf(-z));

    #pragma unroll
    for (int o = 16; o; o >>= 1) p += __shfl_xor_sync(0xffffffffu, p, o);
    if (q == 0) {
        float sr = p * (1.0f / (float)LQ);
        g_sentrel[bn] = sr;
        if (out_sent) out_sent[bn] = sr;
    }
}

// ---------------- doc max + BCE losses ----------------
__global__ void final_kernel(const int* __restrict__ tsents,
                             const int* __restrict__ tdocs,
                             float* __restrict__ out_loss,
                             float* __restrict__ out_doc) {
    __shared__ float red[256];
    __shared__ float docs_s[Bq];
    int tid = threadIdx.x;
    const float eps = 1e-7f;
    const float hi  = (float)(1.0 - 1e-7);

    float s1 = 0.0f;
    for (int i = tid; i < Bq * NS; i += 256) {
        float p = fminf(fmaxf(g_sentrel[i], eps), hi);
        float t = (float)tsents[i];
        s1 += t * logf(p) + (1.0f - t) * log1pf(-p);
    }
    red[tid] = s1;
    __syncthreads();
    for (int s = 128; s > 0; s >>= 1) {
        if (tid < s) red[tid] += red[tid + s];
        __syncthreads();
    }
    float bce1 = -red[0] / (float)(Bq * NS);
    __syncthreads();

    if (tid < Bq) {
        float m = -INFINITY;
        for (int n = 0; n < NS; ++n) m = fmaxf(m, g_sentrel[tid * NS + n]);
        docs_s[tid] = m;
        if (out_doc) out_doc[tid] = m;
    }
    __syncthreads();

    float s2 = 0.0f;
    if (tid < Bq) {
        float p = fminf(fmaxf(docs_s[tid], eps), hi);
        float t = (float)tdocs[tid];
        s2 = t * logf(p) + (1.0f - t) * log1pf(-p);
    }
    red[tid] = s2;
    __syncthreads();
    for (int s = 128; s > 0; s >>= 1) {
        if (tid < s) red[tid] += red[tid + s];
        __syncthreads();
    }
    if (tid == 0) {
        float bce2 = -red[0] / (float)Bq;
        out_loss[0] = 0.5f * (bce1 + bce2);
    }
}

// ---------------- host ----------------
extern "C" void kernel_launch(void* const* d_in, const int* in_sizes, int n_in,
                              void* d_out, int out_size) {
    const int *sentences = nullptr, *question = nullptr, *tsents = nullptr, *tdocs = nullptr;
    const float *embeds = nullptr, *filters = nullptr, *W = nullptr, *bias = nullptr;

    for (int i = 0; i < n_in; ++i) {
        switch (in_sizes[i]) {
            case SROWS:        sentences = (const int*)d_in[i];  break;
            case QROWS:        question  = (const int*)d_in[i];  break;
            case Bq * NS:      tsents    = (const int*)d_in[i];  break;
            case Bq:           tdocs     = (const int*)d_in[i];  break;
            case Vv * D:       embeds    = (const float*)d_in[i]; break;
            case F * FS * D:   filters   = (const float*)d_in[i]; break;
            case 6:            W         = (const float*)d_in[i]; break;
            case 1:            bias      = (const float*)d_in[i]; break;
            default: break;
        }
    }

    float* out = (float*)d_out;
    float* out_sent = (out_size >= 1 + Bq * NS)      ? out + 1            : nullptr;
    float* out_doc  = (out_size >= 1 + Bq * NS + Bq) ? out + 1 + Bq * NS  : nullptr;

    // 0: filters -> e4m3 (padded)
    filt_convert_kernel<<<(F * FS * D + 255) / 256, 256>>>(filters);

    // 1-2: gather embeddings (bf16 + e4m3) + norms
    gather_norm_kernel<<<(QROWS * 32 + 255) / 256, 256>>>(embeds, question, QROWS, 0);
    gather_norm_kernel<<<(SROWS * 32 + 255) / 256, 256>>>(embeds, sentences, SROWS, 1);

    // 3-4: forward conv (zero-pad at segment end), cp.async-pipelined e4m3 MMA
    conv_mma_kernel<LQ><<<dim3(QROWS / 128, F / 128), 256>>>(0);
    conv_mma_kernel<LS><<<dim3(SROWS / 128, F / 128), 256>>>(1);

    // 5-6: conv-output norms
    rownorm_kernel<<<(QROWS * 32 + 255) / 256, 256>>>(QROWS, 0);
    rownorm_kernel<<<(SROWS * 32 + 255) / 256, 256>>>(SROWS, 1);

    // 7-8: cosine similarity matrices (bf16 HMMA)
    sim_mma_kernel<DP, 0><<<dim3((LT + 127) / 128, Bq), 256>>>();
    sim_mma_kernel<F,  1><<<dim3((LT + 127) / 128, Bq), 256>>>();

    // 9: top-k pooling + linear + sigmoid + mean over q
    pool_kernel<<<Bq * NS, 32>>>(question, sentences, W, bias, out_sent);

    // 10: doc max + BCE
    final_kernel<<<1, 256>>>(tsents, tdocs, out, out_doc);
}

// round 12
// speedup vs baseline: 3.0051x; 1.1293x over previous
#include <cuda_runtime.h>
#include <cuda_bf16.h>
#include <cuda_fp8.h>
#include <cstdint>
#include <math.h>

// ---------------- problem constants ----------------
constexpr int Bq   = 64;     // batch
constexpr int NS   = 50;     // sentences per doc
constexpr int LS   = 60;     // sentence length
constexpr int LQ   = 32;     // question length
constexpr int D    = 300;    // embedding dim
constexpr int DP   = 320;    // padded embedding dim
constexpr int F    = 256;    // conv filters
constexpr int FS   = 3;      // filter size
constexpr int Vv   = 100000; // vocab
constexpr int QROWS = Bq * LQ;        // 2048
constexpr int SROWS = Bq * NS * LS;   // 192000
constexpr int LT    = NS * LS;        // 3000

constexpr int STK  = 64;            // K fp8 per conv stage -> 64B rows
constexpr int STPT = DP / STK;      // 5 stages per tap
constexpr int NSTG = FS * STPT;     // 15 stages

// simpool dynamic-smem layout (byte offsets; all 1KB-aligned)
constexpr int OQI   = 0;                       // Q ins tile: 32 x 328 bf16 = 20992B
constexpr int OQC   = 21504;                   // Q conv tile: 32 x 264 bf16 = 16896B
constexpr int OSS   = 39936;                   // S pipe: 2 x 8KB
constexpr int OSB   = 56320;                   // simbuf: 128 x 32 fp32 = 16KB
constexpr int OMISC = 72704;                   // qns(128) qcns(128) zbuf(256) smask(512) qmask(128) W(32)
constexpr int SMEM_SP = 74752;

// ---------------- device scratch (no allocs; zero-init) ----------------
__device__ __nv_bfloat16 g_qe_bf[(QROWS + 2) * DP];
__device__ __nv_bfloat16 g_se_bf[(SROWS + 2) * DP];
__device__ uint8_t g_qe_f8[(QROWS + 2) * DP];
__device__ uint8_t g_se_f8[(SROWS + 2) * DP];
__device__ uint8_t g_filt_f8[F * FS * DP];
__device__ float g_qn[QROWS];
__device__ float g_sn[SROWS];
__device__ __nv_bfloat16 g_qc_bf[QROWS * F];
__device__ __nv_bfloat16 g_sc_bf[SROWS * F];
__device__ float g_qcn[QROWS];
__device__ float g_scn[SROWS];
__device__ float g_sentrel[Bq * NS];

// ---------------- asm helpers ----------------
__device__ __forceinline__ void mma_bf16(float* c,
                                         uint32_t a0, uint32_t a1, uint32_t a2, uint32_t a3,
                                         uint32_t b0, uint32_t b1) {
    asm volatile("mma.sync.aligned.m16n8k16.row.col.f32.bf16.bf16.f32 "
                 "{%0,%1,%2,%3},{%4,%5,%6,%7},{%8,%9},{%0,%1,%2,%3};"
                 : "+f"(c[0]), "+f"(c[1]), "+f"(c[2]), "+f"(c[3])
                 : "r"(a0), "r"(a1), "r"(a2), "r"(a3), "r"(b0), "r"(b1));
}
__device__ __forceinline__ void mma_fp8(float* c,
                                        uint32_t a0, uint32_t a1, uint32_t a2, uint32_t a3,
                                        uint32_t b0, uint32_t b1) {
    asm volatile("mma.sync.aligned.m16n8k32.row.col.f32.e4m3.e4m3.f32 "
                 "{%0,%1,%2,%3},{%4,%5,%6,%7},{%8,%9},{%0,%1,%2,%3};"
                 : "+f"(c[0]), "+f"(c[1]), "+f"(c[2]), "+f"(c[3])
                 : "r"(a0), "r"(a1), "r"(a2), "r"(a3), "r"(b0), "r"(b1));
}
__device__ __forceinline__ void ldsm4(uint32_t& r0, uint32_t& r1, uint32_t& r2, uint32_t& r3,
                                      uint32_t addr) {
    asm volatile("ldmatrix.sync.aligned.m8n8.x4.shared.b16 {%0,%1,%2,%3}, [%4];"
                 : "=r"(r0), "=r"(r1), "=r"(r2), "=r"(r3) : "r"(addr));
}
__device__ __forceinline__ void cp_async16(uint32_t dst, const void* src, uint32_t srcsz) {
    asm volatile("cp.async.ca.shared.global [%0], [%1], 16, %2;"
                 :: "r"(dst), "l"(src), "r"(srcsz));
}
__device__ __forceinline__ void cp_commit() { asm volatile("cp.async.commit_group;" ::: "memory"); }

// ---------------- gather -> bf16 + fp8 + norm (paired/vectorized) ----------------
__global__ void gather_norm_kernel(const float* __restrict__ embeds,
                                   const int* __restrict__ tokens,
                                   int nrows, int which) {
    int warp = (blockIdx.x * blockDim.x + threadIdx.x) >> 5;
    int lane = threadIdx.x & 31;
    if (warp >= nrows) return;
    __nv_bfloat16* dbf = which ? g_se_bf : g_qe_bf;
    uint8_t*       df8 = which ? g_se_f8 : g_qe_f8;
    float*         nrm = which ? g_sn    : g_qn;
    int tok = tokens[warp];
    const float* src = embeds + (size_t)tok * D;
    __nv_bfloat16* brow = dbf + (size_t)warp * DP;
    uint8_t*       frow = df8 + (size_t)warp * DP;
    float ss = 0.0f;
    for (int i = lane * 2; i < D; i += 64) {   // D=300 even -> exact pairs
        float2 v = *(const float2*)&src[i];
        __nv_bfloat16 b0 = __float2bfloat16(v.x);
        __nv_bfloat16 b1 = __float2bfloat16(v.y);
        *(__nv_bfloat162*)&brow[i] = __halves2bfloat162(b0, b1);
        __nv_fp8_e4m3 f0(v.x), f1(v.y);
        uchar2 fc; fc.x = *(uint8_t*)&f0; fc.y = *(uint8_t*)&f1;
        *(uchar2*)&frow[i] = fc;
        float x0 = __bfloat162float(b0), x1 = __bfloat162float(b1);
        ss += x0 * x0 + x1 * x1;
    }
    #pragma unroll
    for (int o = 16; o; o >>= 1) ss += __shfl_xor_sync(0xffffffffu, ss, o);
    if (lane == 0) nrm[warp] = sqrtf(ss);
}

// ---------------- filter fp32 -> e4m3 ----------------
__global__ void filt_convert_kernel(const float* __restrict__ filt) {
    int idx = blockIdx.x * blockDim.x + threadIdx.x;
    if (idx >= F * FS * D) return;
    int f = idx / (FS * D);
    int r = idx % (FS * D);
    int t = r / D;
    int k = r % D;
    __nv_fp8_e4m3 f8(filt[idx]);
    g_filt_f8[((size_t)f * FS + t) * DP + k] = *(uint8_t*)&f8;
}

// ============================================================================
// conv as GEMM (e4m3 MMA m16n8k32, cp.async double-buffered)
// __launch_bounds__(256,2): cap regs at 128 -> 2 CTAs/SM (was 143 regs, 1 CTA)
// ============================================================================
template<int SEG>
__global__ void __launch_bounds__(256, 2) conv_mma_kernel(int which) {
    const uint8_t* X = which ? g_se_f8 : g_qe_f8;
    __nv_bfloat16* out = which ? g_sc_bf : g_qc_bf;

    __shared__ __align__(16) uint8_t sm[32768];
    uint32_t sb = (uint32_t)__cvta_generic_to_shared(sm);

    const int tid  = threadIdx.x;
    const int lane = tid & 31;
    const int wid  = tid >> 5;
    const int wm   = (wid & 3) * 32;
    const int wn   = (wid >> 2) * 64;
    const int m    = lane >> 3;
    const int rr   = lane & 7;

    const int rbase = blockIdx.x * 128;
    const int fbase = blockIdx.y * 128;

    const int arow  = tid >> 1;
    const int hbase = (tid & 1) * 2;
    const int gr    = rbase + arow;
    const int lpos  = gr % SEG;
    const int gf    = fbase + arow;
    const int swz   = (arow >> 1) & 3;

    float acc[2][8][4];
    #pragma unroll
    for (int i = 0; i < 2; ++i)
        #pragma unroll
        for (int j = 0; j < 8; ++j)
            #pragma unroll
            for (int v = 0; v < 4; ++v) acc[i][j][v] = 0.0f;

    auto issue = [&](int s, int buf) {
        int tap = s / STPT;
        int kc  = (s % STPT) * STK;
        uint32_t asz = ((lpos + tap) < SEG) ? 16u : 0u;
        const uint8_t* ap = X + (size_t)(gr + tap) * DP + kc;
        const uint8_t* bp = g_filt_f8 + ((size_t)gf * FS + tap) * DP + kc;
        #pragma unroll
        for (int e = 0; e < 2; ++e) {
            int h = hbase + e;
            int phys = h ^ swz;
            uint32_t da = sb + buf * 8192 + arow * 64 + phys * 16;
            uint32_t db = da + 16384;
            cp_async16(da, ap + h * 16, asz);
            cp_async16(db, bp + h * 16, 16u);
        }
    };

    issue(0, 0);
    cp_commit();

    for (int s = 0; s < NSTG; ++s) {
        asm volatile("cp.async.wait_group 0;" ::: "memory");
        __syncthreads();
        if (s + 1 < NSTG) { issue(s + 1, (s + 1) & 1); cp_commit(); }
        int buf = s & 1;
        uint32_t abase = sb + buf * 8192;
        uint32_t bbase = abase + 16384;

        #pragma unroll
        for (int c = 0; c < 2; ++c) {
            uint32_t a[2][4];
            #pragma unroll
            for (int i = 0; i < 2; ++i) {
                int rowA = wm + i * 16 + (m & 1) * 8 + rr;
                int phys = (2 * c + (m >> 1)) ^ ((rowA >> 1) & 3);
                ldsm4(a[i][0], a[i][1], a[i][2], a[i][3],
                      abase + (uint32_t)(rowA * 64 + phys * 16));
            }
            uint32_t bbv[8][2];
            #pragma unroll
            for (int jp = 0; jp < 4; ++jp) {
                int rowB = wn + (jp * 2 + (m >> 1)) * 8 + rr;
                int phys = (2 * c + (m & 1)) ^ ((rowB >> 1) & 3);
                ldsm4(bbv[2 * jp][0], bbv[2 * jp][1], bbv[2 * jp + 1][0], bbv[2 * jp + 1][1],
                      bbase + (uint32_t)(rowB * 64 + phys * 16));
            }
            #pragma unroll
            for (int j = 0; j < 8; ++j)
                #pragma unroll
                for (int i = 0; i < 2; ++i)
                    mma_fp8(acc[i][j], a[i][0], a[i][1], a[i][2], a[i][3],
                            bbv[j][0], bbv[j][1]);
        }
        __syncthreads();
    }

    const int g   = lane >> 2;
    const int tig = lane & 3;
    #pragma unroll
    for (int i = 0; i < 2; ++i) {
        int r0 = rbase + wm + i * 16 + g;
        #pragma unroll
        for (int j = 0; j < 8; ++j) {
            int col = fbase + wn + j * 8 + tig * 2;
            __nv_bfloat16* o0 = out + (size_t)r0 * F + col;
            *(__nv_bfloat162*)o0 =
                __halves2bfloat162(__float2bfloat16(acc[i][j][0]), __float2bfloat16(acc[i][j][1]));
            *(__nv_bfloat162*)(o0 + (size_t)8 * F) =
                __halves2bfloat162(__float2bfloat16(acc[i][j][2]), __float2bfloat16(acc[i][j][3]));
        }
    }
}

// ---------------- row norms over F=256 (bf16 input) ----------------
__global__ void rownorm_kernel(int R, int which) {
    const __nv_bfloat16* X = which ? g_sc_bf : g_qc_bf;
    float* nrm = which ? g_scn : g_qcn;
    int warp = (blockIdx.x * blockDim.x + threadIdx.x) >> 5;
    int lane = threadIdx.x & 31;
    if (warp >= R) return;
    const __nv_bfloat16* row = X + (size_t)warp * F;
    uint4 u = *(const uint4*)&row[lane * 8];
    float ss = 0.0f;
    uint32_t w[4] = {u.x, u.y, u.z, u.w};
    #pragma unroll
    for (int i = 0; i < 4; ++i) {
        float2 p = __bfloat1622float2(*(__nv_bfloat162*)&w[i]);
        ss += p.x * p.x + p.y * p.y;
    }
    #pragma unroll
    for (int o = 16; o; o >>= 1) ss += __shfl_xor_sync(0xffffffffu, ss, o);
    if (lane == 0) nrm[warp] = sqrtf(ss);
}

// ============================================================================
// fused sim + pool: one block = (2 sentences, 1 batch element).
// Phase A: sim_ins (K=320) -> smem simbuf -> pool; Phase B: sim_sen (K=256)
// -> simbuf -> pool -> sigmoid -> mean over q -> g_sentrel.
// Sim matrices never touch gmem.
// ============================================================================
__device__ __forceinline__ void insert5(float* t, float v) {
    if (v > t[4]) {
        t[4] = v;
        #pragma unroll
        for (int i = 4; i > 0; --i) {
            if (t[i] > t[i - 1]) { float tmp = t[i - 1]; t[i - 1] = t[i]; t[i] = tmp; }
        }
    }
}

// one sim phase: MMA over KT, normalized result -> simbuf (128 rows x 32 q)
template<int KT, int STRIDE>
__device__ __forceinline__ void sim_phase(
    uint32_t sbS, uint32_t sbQ,
    const __nv_bfloat16* __restrict__ S0,  // sentence-0 base (row l stride STRIDE)
    const __nv_bfloat16* __restrict__ S1,
    float* __restrict__ simbuf,
    const float* __restrict__ qns,         // smem, 32
    const float* __restrict__ sn0,         // gmem norms, l-indexed
    const float* __restrict__ sn1,
    int tid)
{
    constexpr int STG = KT / 32;
    constexpr int QS  = KT + 8;            // Q smem row stride (bf16 elems)

    const int lane = tid & 31;
    const int wid  = tid >> 5;
    const int m    = lane >> 3;
    const int rr   = lane & 7;

    const int srow  = tid >> 1;            // 0..127
    const int hbase = (tid & 1) * 2;
    const int sl    = srow & 63;
    const int ssent = srow >> 6;
    const int swz   = (srow >> 1) & 3;
    const uint32_t ssz = (sl < LS) ? 16u : 0u;
    const __nv_bfloat16* srcrow =
        (ssent ? S1 : S0) + (size_t)sl * STRIDE;

    auto issueS = [&](int s, int buf) {
        int kc = s * 32;
        #pragma unroll
        for (int e = 0; e < 2; ++e) {
            int h = hbase + e;
            int phys = h ^ swz;
            cp_async16(sbS + buf * 8192 + srow * 64 + phys * 16, srcrow + kc + h * 8, ssz);
        }
    };

    float acc[4][4];
    #pragma unroll
    for (int t = 0; t < 4; ++t)
        #pragma unroll
        for (int v = 0; v < 4; ++v) acc[t][v] = 0.0f;

    issueS(0, 0);
    cp_commit();

    for (int s = 0; s < STG; ++s) {
        asm volatile("cp.async.wait_group 0;" ::: "memory");
        __syncthreads();
        if (s + 1 < STG) { issueS(s + 1, (s + 1) & 1); cp_commit(); }
        uint32_t abase = sbS + (s & 1) * 8192;

        #pragma unroll
        for (int c = 0; c < 2; ++c) {
            uint32_t a[4];
            int rowS = wid * 16 + (m & 1) * 8 + rr;
            int phys = (2 * c + (m >> 1)) ^ ((rowS >> 1) & 3);
            ldsm4(a[0], a[1], a[2], a[3], abase + (uint32_t)(rowS * 64 + phys * 16));

            int cg = s * 2 + c;
            uint32_t qb[4][2];
            #pragma unroll
            for (int jp = 0; jp < 2; ++jp) {
                int rowq = (jp * 2 + (m >> 1)) * 8 + rr;
                uint32_t qaddr = sbQ + (uint32_t)(rowq * (QS * 2) + (cg * 16 + (m & 1) * 8) * 2);
                ldsm4(qb[2 * jp][0], qb[2 * jp][1], qb[2 * jp + 1][0], qb[2 * jp + 1][1], qaddr);
            }
            #pragma unroll
            for (int t = 0; t < 4; ++t)
                mma_bf16(acc[t], a[0], a[1], a[2], a[3], qb[t][0], qb[t][1]);
        }
        __syncthreads();
    }

    // normalized write to simbuf (skip pad rows l>=60)
    const int g   = lane >> 2;
    const int tig = lane & 3;
    int l0 = wid * 16 + g;
    int l1 = l0 + 8;
    int li0 = l0 & 63, li1 = l1 & 63;
    float n0 = (li0 < LS) ? ((l0 >> 6) ? sn1[li0] : sn0[li0]) : 1.0f;
    float n1 = (li1 < LS) ? ((l1 >> 6) ? sn1[li1] : sn0[li1]) : 1.0f;
    #pragma unroll
    for (int t = 0; t < 4; ++t) {
        int q0 = t * 8 + tig * 2;
        float i0 = 1.0f / (qns[q0] * n0), i1 = 1.0f / (qns[q0 + 1] * n0);
        float i2 = 1.0f / (qns[q0] * n1), i3 = 1.0f / (qns[q0 + 1] * n1);
        if (li0 < LS) {
            simbuf[l0 * 32 + q0]     = acc[t][0] * i0;
            simbuf[l0 * 32 + q0 + 1] = acc[t][1] * i1;
        }
        if (li1 < LS) {
            simbuf[l1 * 32 + q0]     = acc[t][2] * i2;
            simbuf[l1 * 32 + q0 + 1] = acc[t][3] * i3;
        }
    }
}

__global__ void __launch_bounds__(256) simpool_kernel(
    const int* __restrict__ question,
    const int* __restrict__ sentences,
    const float* __restrict__ Wg,
    const float* __restrict__ biasg,
    float* __restrict__ out_sent)
{
    extern __shared__ __align__(16) uint8_t dyn[];
    __nv_bfloat16* Qi = (__nv_bfloat16*)(dyn + OQI);
    __nv_bfloat16* Qc = (__nv_bfloat16*)(dyn + OQC);
    float* simbuf = (float*)(dyn + OSB);
    float* qns  = (float*)(dyn + OMISC);
    float* qcns = (float*)(dyn + OMISC + 128);
    float* zbuf = (float*)(dyn + OMISC + 256);
    int*   smk  = (int*)(dyn + OMISC + 512);     // 128 ints: sentence-token mask
    int*   qmk  = (int*)(dyn + OMISC + 1024);    // 32 ints
    float* Wc   = (float*)(dyn + OMISC + 1152);  // 7 floats
    uint32_t sbS = (uint32_t)__cvta_generic_to_shared(dyn + OSS);
    uint32_t sbQi = (uint32_t)__cvta_generic_to_shared(Qi);
    uint32_t sbQc = (uint32_t)__cvta_generic_to_shared(Qc);

    const int tid = threadIdx.x;
    const int b   = blockIdx.y;
    const int n0  = blockIdx.x * 2;   // sentences n0, n0+1

    // ---- load Q tiles, norms, masks, weights ----
    constexpr int QSI = DP + 8, QSC = F + 8;
    const __nv_bfloat16* Qig = g_qe_bf + (size_t)b * LQ * DP;
    const __nv_bfloat16* Qcg = g_qc_bf + (size_t)b * LQ * F;
    for (int idx = tid; idx < 32 * (DP / 8); idx += 256) {
        int row = idx / (DP / 8), s8 = idx % (DP / 8);
        *(uint4*)&Qi[row * QSI + s8 * 8] = *(const uint4*)&Qig[(size_t)row * DP + s8 * 8];
    }
    for (int idx = tid; idx < 32 * (F / 8); idx += 256) {
        int row = idx / (F / 8), s8 = idx % (F / 8);
        *(uint4*)&Qc[row * QSC + s8 * 8] = *(const uint4*)&Qcg[(size_t)row * F + s8 * 8];
    }
    if (tid < 32) {
        qns[tid]  = g_qn[b * LQ + tid];
        qcns[tid] = g_qcn[b * LQ + tid];
        qmk[tid]  = question[b * LQ + tid] > 0;
    }
    for (int idx = tid; idx < 128; idx += 256) {
        int sent = idx >> 6, l = idx & 63;
        smk[idx] = (l < LS) ? (sentences[((size_t)b * NS + n0 + sent) * LS + l] > 0) : 0;
    }
    if (tid < 7) Wc[tid] = (tid < 6) ? Wg[tid] : biasg[0];
    __syncthreads();

    const float* sn0i = g_sn  + (size_t)b * LT + (size_t)n0 * LS;
    const float* sn1i = sn0i + LS;
    const float* sn0c = g_scn + (size_t)b * LT + (size_t)n0 * LS;
    const float* sn1c = sn0c + LS;
    const __nv_bfloat16* S0i = g_se_bf + ((size_t)b * LT + (size_t)n0 * LS) * DP;
    const __nv_bfloat16* S0c = g_sc_bf + ((size_t)b * LT + (size_t)n0 * LS) * F;

    const float thr = (float)(1.0 - 1e-5);

    // ---- phase A: sim_ins ----
    sim_phase<DP, DP>(sbS, sbQi, S0i, S0i + (size_t)LS * DP, simbuf, qns, sn0i, sn1i, tid);
    __syncthreads();
    if (tid < 64) {
        int sent = tid >> 5, q = tid & 31;
        bool qm = qmk[q] != 0;
        float ti[5] = {-INFINITY, -INFINITY, -INFINITY, -INFINITY, -INFINITY};
        int cnt = 0;
        const float* col = simbuf + sent * 64 * 32 + q;
        const int* sm = smk + sent * 64;
        for (int l = 0; l < LS; ++l) {
            float v = col[l * 32];
            if (v >= thr) ++cnt;                  // oh channel: UNMASKED sim
            float mv = (qm && sm[l]) ? v : 0.0f;
            insert5(ti, mv);
        }
        float insMean = (ti[0] + ti[1] + ti[2] + ti[3] + ti[4]) * 0.2f;
        float ohMax   = (cnt > 0) ? 1.0f : 0.0f;
        float ohMean  = fminf((float)cnt, 5.0f) * 0.2f;
        zbuf[tid] = Wc[0] * ti[0] + Wc[1] * insMean + Wc[4] * ohMax + Wc[5] * ohMean;
    }
    __syncthreads();

    // ---- phase B: sim_sen ----
    sim_phase<F, F>(sbS, sbQc, S0c, S0c + (size_t)LS * F, simbuf, qcns, sn0c, sn1c, tid);
    __syncthreads();
    if (tid < 64) {
        int sent = tid >> 5, q = tid & 31;
        bool qm = qmk[q] != 0;
        float tc[5] = {-INFINITY, -INFINITY, -INFINITY, -INFINITY, -INFINITY};
        const float* col = simbuf + sent * 64 * 32 + q;
        const int* sm = smk + sent * 64;
        for (int l = 0; l < LS; ++l) {
            float v = col[l * 32];
            float mv = (qm && sm[l]) ? v : 0.0f;
            insert5(tc, mv);
        }
        float senMean = (tc[0] + tc[1] + tc[2] + tc[3] + tc[4]) * 0.2f;
        float z = zbuf[tid] + Wc[2] * tc[0] + Wc[3] * senMean + Wc[6];
        float p = 1.0f / (1.0f + expf(-z));
        #pragma unroll
        for (int o = 16; o; o >>= 1) p += __shfl_xor_sync(0xffffffffu, p, o);
        if (q == 0) {
            float sr = p * (1.0f / (float)LQ);
            int bn = b * NS + n0 + sent;
            g_sentrel[bn] = sr;
            if (out_sent) out_sent[bn] = sr;
        }
    }
}

// ---------------- doc max + BCE losses ----------------
__global__ void final_kernel(const int* __restrict__ tsents,
                             const int* __restrict__ tdocs,
                             float* __restrict__ out_loss,
                             float* __restrict__ out_doc) {
    __shared__ float red[256];
    __shared__ float docs_s[Bq];
    int tid = threadIdx.x;
    const float eps = 1e-7f;
    const float hi  = (float)(1.0 - 1e-7);

    float s1 = 0.0f;
    for (int i = tid; i < Bq * NS; i += 256) {
        float p = fminf(fmaxf(g_sentrel[i], eps), hi);
        float t = (float)tsents[i];
        s1 += t * logf(p) + (1.0f - t) * log1pf(-p);
    }
    red[tid] = s1;
    __syncthreads();
    for (int s = 128; s > 0; s >>= 1) {
        if (tid < s) red[tid] += red[tid + s];
        __syncthreads();
    }
    float bce1 = -red[0] / (float)(Bq * NS);
    __syncthreads();

    if (tid < Bq) {
        float m = -INFINITY;
        for (int n = 0; n < NS; ++n) m = fmaxf(m, g_sentrel[tid * NS + n]);
        docs_s[tid] = m;
        if (out_doc) out_doc[tid] = m;
    }
    __syncthreads();

    float s2 = 0.0f;
    if (tid < Bq) {
        float p = fminf(fmaxf(docs_s[tid], eps), hi);
        float t = (float)tdocs[tid];
        s2 = t * logf(p) + (1.0f - t) * log1pf(-p);
    }
    red[tid] = s2;
    __syncthreads();
    for (int s = 128; s > 0; s >>= 1) {
        if (tid < s) red[tid] += red[tid + s];
        __syncthreads();
    }
    if (tid == 0) {
        float bce2 = -red[0] / (float)Bq;
        out_loss[0] = 0.5f * (bce1 + bce2);
    }
}

// ---------------- host ----------------
extern "C" void kernel_launch(void* const* d_in, const int* in_sizes, int n_in,
                              void* d_out, int out_size) {
    const int *sentences = nullptr, *question = nullptr, *tsents = nullptr, *tdocs = nullptr;
    const float *embeds = nullptr, *filters = nullptr, *W = nullptr, *bias = nullptr;

    for (int i = 0; i < n_in; ++i) {
        switch (in_sizes[i]) {
            case SROWS:        sentences = (const int*)d_in[i];  break;
            case QROWS:        question  = (const int*)d_in[i];  break;
            case Bq * NS:      tsents    = (const int*)d_in[i];  break;
            case Bq:           tdocs     = (const int*)d_in[i];  break;
            case Vv * D:       embeds    = (const float*)d_in[i]; break;
            case F * FS * D:   filters   = (const float*)d_in[i]; break;
            case 6:            W         = (const float*)d_in[i]; break;
            case 1:            bias      = (const float*)d_in[i]; break;
            default: break;
        }
    }

    float* out = (float*)d_out;
    float* out_sent = (out_size >= 1 + Bq * NS)      ? out + 1            : nullptr;
    float* out_doc  = (out_size >= 1 + Bq * NS + Bq) ? out + 1 + Bq * NS  : nullptr;

    cudaFuncSetAttribute(simpool_kernel, cudaFuncAttributeMaxDynamicSharedMemorySize, SMEM_SP);

    // 0: filters -> e4m3
    filt_convert_kernel<<<(F * FS * D + 255) / 256, 256>>>(filters);

    // 1-2: gather embeddings (bf16 + e4m3) + norms
    gather_norm_kernel<<<(QROWS * 32 + 255) / 256, 256>>>(embeds, question, QROWS, 0);
    gather_norm_kernel<<<(SROWS * 32 + 255) / 256, 256>>>(embeds, sentences, SROWS, 1);

    // 3-4: forward conv (e4m3 MMA, 2 CTAs/SM)
    conv_mma_kernel<LQ><<<dim3(QROWS / 128, F / 128), 256>>>(0);
    conv_mma_kernel<LS><<<dim3(SROWS / 128, F / 128), 256>>>(1);

    // 5-6: conv-output norms
    rownorm_kernel<<<(QROWS * 32 + 255) / 256, 256>>>(QROWS, 0);
    rownorm_kernel<<<(SROWS * 32 + 255) / 256, 256>>>(SROWS, 1);

    // 7: fused sim + pool (sims stay in smem)
    simpool_kernel<<<dim3(NS / 2, Bq), 256, SMEM_SP>>>(question, sentences, W, bias, out_sent);

    // 8: doc max + BCE
    final_kernel<<<1, 256>>>(tsents, tdocs, out, out_doc);
}

// round 13
// speedup vs baseline: 3.3136x; 1.1027x over previous
#include <cuda_runtime.h>
#include <cuda_bf16.h>
#include <cuda_fp8.h>
#include <cstdint>
#include <math.h>

// ---------------- problem constants ----------------
constexpr int Bq   = 64;     // batch
constexpr int NS   = 50;     // sentences per doc
constexpr int LS   = 60;     // sentence length
constexpr int LQ   = 32;     // question length
constexpr int D    = 300;    // embedding dim
constexpr int DP   = 320;    // padded embedding dim
constexpr int F    = 256;    // conv filters
constexpr int FS   = 3;      // filter size
constexpr int Vv   = 100000; // vocab
constexpr int QROWS = Bq * LQ;        // 2048
constexpr int SROWS = Bq * NS * LS;   // 192000
constexpr int LT    = NS * LS;        // 3000

constexpr int STK  = 64;            // K fp8 per conv stage -> 64B rows
constexpr int STPT = DP / STK;      // 5 stages per tap
constexpr int NSTG = FS * STPT;     // 15 stages

constexpr int STILES = SROWS / 128; // 1500 sentence conv tiles
constexpr int QTILES = QROWS / 128; // 16 question conv tiles

// simpool dynamic-smem layout (byte offsets)
constexpr int OQI   = 0;                       // Q ins tile: 32 x 328 bf16
constexpr int OQC   = 21504;                   // Q conv tile: 32 x 264 bf16
constexpr int OSS   = 39936;                   // S pipe: 2 x 8KB
constexpr int OSB   = 56320;                   // simbuf: 128 x 32 fp32 = 16KB
constexpr int OMISC = 72704;                   // qns qcns zbuf smask qmask W
constexpr int SMEM_SP = 74752;

// ---------------- device scratch (no allocs; zero-init at load) ----------------
__device__ __nv_bfloat16 g_qe_bf[(QROWS + 2) * DP];
__device__ __nv_bfloat16 g_se_bf[(SROWS + 2) * DP];
__device__ uint8_t g_qe_f8[(QROWS + 2) * DP];
__device__ uint8_t g_se_f8[(SROWS + 2) * DP];
__device__ uint8_t g_filt_f8[F * FS * DP];
__device__ float g_qn[QROWS];
__device__ float g_sn[SROWS];
__device__ __nv_bfloat16 g_qc_bf[QROWS * F];
__device__ __nv_bfloat16 g_sc_bf[SROWS * F];
__device__ float g_qcn2[QROWS];   // sumsq of conv(question) rows (atomically built)
__device__ float g_scn2[SROWS];   // sumsq of conv(sentences) rows
__device__ float g_sentrel[Bq * NS];

// ---------------- asm helpers ----------------
__device__ __forceinline__ void mma_bf16(float* c,
                                         uint32_t a0, uint32_t a1, uint32_t a2, uint32_t a3,
                                         uint32_t b0, uint32_t b1) {
    asm volatile("mma.sync.aligned.m16n8k16.row.col.f32.bf16.bf16.f32 "
                 "{%0,%1,%2,%3},{%4,%5,%6,%7},{%8,%9},{%0,%1,%2,%3};"
                 : "+f"(c[0]), "+f"(c[1]), "+f"(c[2]), "+f"(c[3])
                 : "r"(a0), "r"(a1), "r"(a2), "r"(a3), "r"(b0), "r"(b1));
}
__device__ __forceinline__ void mma_fp8(float* c,
                                        uint32_t a0, uint32_t a1, uint32_t a2, uint32_t a3,
                                        uint32_t b0, uint32_t b1) {
    asm volatile("mma.sync.aligned.m16n8k32.row.col.f32.e4m3.e4m3.f32 "
                 "{%0,%1,%2,%3},{%4,%5,%6,%7},{%8,%9},{%0,%1,%2,%3};"
                 : "+f"(c[0]), "+f"(c[1]), "+f"(c[2]), "+f"(c[3])
                 : "r"(a0), "r"(a1), "r"(a2), "r"(a3), "r"(b0), "r"(b1));
}
__device__ __forceinline__ void ldsm4(uint32_t& r0, uint32_t& r1, uint32_t& r2, uint32_t& r3,
                                      uint32_t addr) {
    asm volatile("ldmatrix.sync.aligned.m8n8.x4.shared.b16 {%0,%1,%2,%3}, [%4];"
                 : "=r"(r0), "=r"(r1), "=r"(r2), "=r"(r3) : "r"(addr));
}
__device__ __forceinline__ void cp_async16(uint32_t dst, const void* src, uint32_t srcsz) {
    asm volatile("cp.async.ca.shared.global [%0], [%1], 16, %2;"
                 :: "r"(dst), "l"(src), "r"(srcsz));
}
__device__ __forceinline__ void cp_commit() { asm volatile("cp.async.commit_group;" ::: "memory"); }

// ---------------- zero the sumsq accumulators (every launch; graphs replay) ----
__global__ void zero_cn2_kernel() {
    int i = blockIdx.x * blockDim.x + threadIdx.x;
    if (i < SROWS) g_scn2[i] = 0.0f;
    if (i < QROWS) g_qcn2[i] = 0.0f;
}

// ---------------- gather -> bf16 + fp8 + norm (paired/vectorized) ----------------
__global__ void gather_norm_kernel(const float* __restrict__ embeds,
                                   const int* __restrict__ tokens,
                                   int nrows, int which) {
    int warp = (blockIdx.x * blockDim.x + threadIdx.x) >> 5;
    int lane = threadIdx.x & 31;
    if (warp >= nrows) return;
    __nv_bfloat16* dbf = which ? g_se_bf : g_qe_bf;
    uint8_t*       df8 = which ? g_se_f8 : g_qe_f8;
    float*         nrm = which ? g_sn    : g_qn;
    int tok = tokens[warp];
    const float* src = embeds + (size_t)tok * D;
    __nv_bfloat16* brow = dbf + (size_t)warp * DP;
    uint8_t*       frow = df8 + (size_t)warp * DP;
    float ss = 0.0f;
    for (int i = lane * 2; i < D; i += 64) {
        float2 v = *(const float2*)&src[i];
        __nv_bfloat16 b0 = __float2bfloat16(v.x);
        __nv_bfloat16 b1 = __float2bfloat16(v.y);
        *(__nv_bfloat162*)&brow[i] = __halves2bfloat162(b0, b1);
        __nv_fp8_e4m3 f0(v.x), f1(v.y);
        uchar2 fc; fc.x = *(uint8_t*)&f0; fc.y = *(uint8_t*)&f1;
        *(uchar2*)&frow[i] = fc;
        float x0 = __bfloat162float(b0), x1 = __bfloat162float(b1);
        ss += x0 * x0 + x1 * x1;
    }
    #pragma unroll
    for (int o = 16; o; o >>= 1) ss += __shfl_xor_sync(0xffffffffu, ss, o);
    if (lane == 0) nrm[warp] = sqrtf(ss);
}

// ---------------- filter fp32 -> e4m3 ----------------
__global__ void filt_convert_kernel(const float* __restrict__ filt) {
    int idx = blockIdx.x * blockDim.x + threadIdx.x;
    if (idx >= F * FS * D) return;
    int f = idx / (FS * D);
    int r = idx % (FS * D);
    int t = r / D;
    int k = r % D;
    __nv_fp8_e4m3 f8(filt[idx]);
    g_filt_f8[((size_t)f * FS + t) * DP + k] = *(uint8_t*)&f8;
}

// ============================================================================
// unified conv (sentences + question in ONE launch; question blocks overlap
// the sentence-conv tail instead of serializing). e4m3 MMA m16n8k32,
// cp.async double-buffered, 2 CTAs/SM. Epilogue also accumulates per-row
// sumsq of the bf16-rounded outputs into g_*cn2 (replaces rownorm kernels).
// ============================================================================
__global__ void __launch_bounds__(256, 2) conv_mma_kernel() {
    const int bx  = blockIdx.x;
    const bool isq = (bx >= STILES);
    const uint8_t* X   = isq ? g_qe_f8 : g_se_f8;
    __nv_bfloat16* out = isq ? g_qc_bf : g_sc_bf;
    float* cn2         = isq ? g_qcn2  : g_scn2;
    const int seg      = isq ? LQ : LS;
    const int rbase    = (isq ? (bx - STILES) : bx) * 128;

    __shared__ __align__(16) uint8_t sm[32768];
    uint32_t sb = (uint32_t)__cvta_generic_to_shared(sm);

    const int tid  = threadIdx.x;
    const int lane = tid & 31;
    const int wid  = tid >> 5;
    const int wm   = (wid & 3) * 32;
    const int wn   = (wid >> 2) * 64;
    const int m    = lane >> 3;
    const int rr   = lane & 7;

    const int fbase = blockIdx.y * 128;

    const int arow  = tid >> 1;
    const int hbase = (tid & 1) * 2;
    const int gr    = rbase + arow;
    const int lpos  = gr % seg;
    const int gf    = fbase + arow;
    const int swz   = (arow >> 1) & 3;

    float acc[2][8][4];
    #pragma unroll
    for (int i = 0; i < 2; ++i)
        #pragma unroll
        for (int j = 0; j < 8; ++j)
            #pragma unroll
            for (int v = 0; v < 4; ++v) acc[i][j][v] = 0.0f;

    auto issue = [&](int s, int buf) {
        int tap = s / STPT;
        int kc  = (s % STPT) * STK;
        uint32_t asz = ((lpos + tap) < seg) ? 16u : 0u;
        const uint8_t* ap = X + (size_t)(gr + tap) * DP + kc;
        const uint8_t* bp = g_filt_f8 + ((size_t)gf * FS + tap) * DP + kc;
        #pragma unroll
        for (int e = 0; e < 2; ++e) {
            int h = hbase + e;
            int phys = h ^ swz;
            uint32_t da = sb + buf * 8192 + arow * 64 + phys * 16;
            uint32_t db = da + 16384;
            cp_async16(da, ap + h * 16, asz);
            cp_async16(db, bp + h * 16, 16u);
        }
    };

    issue(0, 0);
    cp_commit();

    for (int s = 0; s < NSTG; ++s) {
        asm volatile("cp.async.wait_group 0;" ::: "memory");
        __syncthreads();
        if (s + 1 < NSTG) { issue(s + 1, (s + 1) & 1); cp_commit(); }
        int buf = s & 1;
        uint32_t abase = sb + buf * 8192;
        uint32_t bbase = abase + 16384;

        #pragma unroll
        for (int c = 0; c < 2; ++c) {
            uint32_t a[2][4];
            #pragma unroll
            for (int i = 0; i < 2; ++i) {
                int rowA = wm + i * 16 + (m & 1) * 8 + rr;
                int phys = (2 * c + (m >> 1)) ^ ((rowA >> 1) & 3);
                ldsm4(a[i][0], a[i][1], a[i][2], a[i][3],
                      abase + (uint32_t)(rowA * 64 + phys * 16));
            }
            uint32_t bbv[8][2];
            #pragma unroll
            for (int jp = 0; jp < 4; ++jp) {
                int rowB = wn + (jp * 2 + (m >> 1)) * 8 + rr;
                int phys = (2 * c + (m & 1)) ^ ((rowB >> 1) & 3);
                ldsm4(bbv[2 * jp][0], bbv[2 * jp][1], bbv[2 * jp + 1][0], bbv[2 * jp + 1][1],
                      bbase + (uint32_t)(rowB * 64 + phys * 16));
            }
            #pragma unroll
            for (int j = 0; j < 8; ++j)
                #pragma unroll
                for (int i = 0; i < 2; ++i)
                    mma_fp8(acc[i][j], a[i][0], a[i][1], a[i][2], a[i][3],
                            bbv[j][0], bbv[j][1]);
        }
        __syncthreads();
    }

    // ---- epilogue: bf16 store + per-row sumsq (of the ROUNDED values) ----
    const int g   = lane >> 2;
    const int tig = lane & 3;
    #pragma unroll
    for (int i = 0; i < 2; ++i) {
        int r0 = rbase + wm + i * 16 + g;
        float sq0 = 0.0f, sq8 = 0.0f;
        #pragma unroll
        for (int j = 0; j < 8; ++j) {
            int col = fbase + wn + j * 8 + tig * 2;
            __nv_bfloat16 h0 = __float2bfloat16(acc[i][j][0]);
            __nv_bfloat16 h1 = __float2bfloat16(acc[i][j][1]);
            __nv_bfloat16 h2 = __float2bfloat16(acc[i][j][2]);
            __nv_bfloat16 h3 = __float2bfloat16(acc[i][j][3]);
            __nv_bfloat16* o0 = out + (size_t)r0 * F + col;
            *(__nv_bfloat162*)o0 = __halves2bfloat162(h0, h1);
            *(__nv_bfloat162*)(o0 + (size_t)8 * F) = __halves2bfloat162(h2, h3);
            float f0 = __bfloat162float(h0), f1 = __bfloat162float(h1);
            float f2 = __bfloat162float(h2), f3 = __bfloat162float(h3);
            sq0 += f0 * f0 + f1 * f1;
            sq8 += f2 * f2 + f3 * f3;
        }
        // reduce across the 4 tig lanes (consecutive lanes g*4+tig)
        sq0 += __shfl_xor_sync(0xffffffffu, sq0, 1);
        sq0 += __shfl_xor_sync(0xffffffffu, sq0, 2);
        sq8 += __shfl_xor_sync(0xffffffffu, sq8, 1);
        sq8 += __shfl_xor_sync(0xffffffffu, sq8, 2);
        if (tig == 0) {
            atomicAdd(&cn2[r0], sq0);
            atomicAdd(&cn2[r0 + 8], sq8);
        }
    }
}

// ============================================================================
// fused sim + pool (unchanged structure; conv norms now arrive as sumsq)
// ============================================================================
__device__ __forceinline__ void insert5(float* t, float v) {
    if (v > t[4]) {
        t[4] = v;
        #pragma unroll
        for (int i = 4; i > 0; --i) {
            if (t[i] > t[i - 1]) { float tmp = t[i - 1]; t[i - 1] = t[i]; t[i] = tmp; }
        }
    }
}

// one sim phase: MMA over KT, normalized result -> simbuf (128 rows x 32 q)
// SQN: sentence-norm array holds sumsq (apply sqrtf) instead of norm
template<int KT, int STRIDE, bool SQN>
__device__ __forceinline__ void sim_phase(
    uint32_t sbS, uint32_t sbQ,
    const __nv_bfloat16* __restrict__ S0,
    const __nv_bfloat16* __restrict__ S1,
    float* __restrict__ simbuf,
    const float* __restrict__ qns,
    const float* __restrict__ sn0,
    const float* __restrict__ sn1,
    int tid)
{
    constexpr int STG = KT / 32;
    constexpr int QS  = KT + 8;

    const int lane = tid & 31;
    const int wid  = tid >> 5;
    const int m    = lane >> 3;
    const int rr   = lane & 7;

    const int srow  = tid >> 1;
    const int hbase = (tid & 1) * 2;
    const int sl    = srow & 63;
    const int ssent = srow >> 6;
    const int swz   = (srow >> 1) & 3;
    const uint32_t ssz = (sl < LS) ? 16u : 0u;
    const __nv_bfloat16* srcrow = (ssent ? S1 : S0) + (size_t)sl * STRIDE;

    auto issueS = [&](int s, int buf) {
        int kc = s * 32;
        #pragma unroll
        for (int e = 0; e < 2; ++e) {
            int h = hbase + e;
            int phys = h ^ swz;
            cp_async16(sbS + buf * 8192 + srow * 64 + phys * 16, srcrow + kc + h * 8, ssz);
        }
    };

    float acc[4][4];
    #pragma unroll
    for (int t = 0; t < 4; ++t)
        #pragma unroll
        for (int v = 0; v < 4; ++v) acc[t][v] = 0.0f;

    issueS(0, 0);
    cp_commit();

    for (int s = 0; s < STG; ++s) {
        asm volatile("cp.async.wait_group 0;" ::: "memory");
        __syncthreads();
        if (s + 1 < STG) { issueS(s + 1, (s + 1) & 1); cp_commit(); }
        uint32_t abase = sbS + (s & 1) * 8192;

        #pragma unroll
        for (int c = 0; c < 2; ++c) {
            uint32_t a[4];
            int rowS = wid * 16 + (m & 1) * 8 + rr;
            int phys = (2 * c + (m >> 1)) ^ ((rowS >> 1) & 3);
            ldsm4(a[0], a[1], a[2], a[3], abase + (uint32_t)(rowS * 64 + phys * 16));

            int cg = s * 2 + c;
            uint32_t qb[4][2];
            #pragma unroll
            for (int jp = 0; jp < 2; ++jp) {
                int rowq = (jp * 2 + (m >> 1)) * 8 + rr;
                uint32_t qaddr = sbQ + (uint32_t)(rowq * (QS * 2) + (cg * 16 + (m & 1) * 8) * 2);
                ldsm4(qb[2 * jp][0], qb[2 * jp][1], qb[2 * jp + 1][0], qb[2 * jp + 1][1], qaddr);
            }
            #pragma unroll
            for (int t = 0; t < 4; ++t)
                mma_bf16(acc[t], a[0], a[1], a[2], a[3], qb[t][0], qb[t][1]);
        }
        __syncthreads();
    }

    const int g   = lane >> 2;
    const int tig = lane & 3;
    int l0 = wid * 16 + g;
    int l1 = l0 + 8;
    int li0 = l0 & 63, li1 = l1 & 63;
    float r0 = (li0 < LS) ? ((l0 >> 6) ? sn1[li0] : sn0[li0]) : 1.0f;
    float r1 = (li1 < LS) ? ((l1 >> 6) ? sn1[li1] : sn0[li1]) : 1.0f;
    float n0 = SQN ? sqrtf(r0) : r0;
    float n1 = SQN ? sqrtf(r1) : r1;
    #pragma unroll
    for (int t = 0; t < 4; ++t) {
        int q0 = t * 8 + tig * 2;
        float i0 = 1.0f / (qns[q0] * n0), i1 = 1.0f / (qns[q0 + 1] * n0);
        float i2 = 1.0f / (qns[q0] * n1), i3 = 1.0f / (qns[q0 + 1] * n1);
        if (li0 < LS) {
            simbuf[l0 * 32 + q0]     = acc[t][0] * i0;
            simbuf[l0 * 32 + q0 + 1] = acc[t][1] * i1;
        }
        if (li1 < LS) {
            simbuf[l1 * 32 + q0]     = acc[t][2] * i2;
            simbuf[l1 * 32 + q0 + 1] = acc[t][3] * i3;
        }
    }
}

__global__ void __launch_bounds__(256) simpool_kernel(
    const int* __restrict__ question,
    const int* __restrict__ sentences,
    const float* __restrict__ Wg,
    const float* __restrict__ biasg,
    float* __restrict__ out_sent)
{
    extern __shared__ __align__(16) uint8_t dyn[];
    __nv_bfloat16* Qi = (__nv_bfloat16*)(dyn + OQI);
    __nv_bfloat16* Qc = (__nv_bfloat16*)(dyn + OQC);
    float* simbuf = (float*)(dyn + OSB);
    float* qns  = (float*)(dyn + OMISC);
    float* qcns = (float*)(dyn + OMISC + 128);
    float* zbuf = (float*)(dyn + OMISC + 256);
    int*   smk  = (int*)(dyn + OMISC + 512);
    int*   qmk  = (int*)(dyn + OMISC + 1024);
    float* Wc   = (float*)(dyn + OMISC + 1152);
    uint32_t sbS  = (uint32_t)__cvta_generic_to_shared(dyn + OSS);
    uint32_t sbQi = (uint32_t)__cvta_generic_to_shared(Qi);
    uint32_t sbQc = (uint32_t)__cvta_generic_to_shared(Qc);

    const int tid = threadIdx.x;
    const int b   = blockIdx.y;
    const int n0  = blockIdx.x * 2;

    constexpr int QSI = DP + 8, QSC = F + 8;
    const __nv_bfloat16* Qig = g_qe_bf + (size_t)b * LQ * DP;
    const __nv_bfloat16* Qcg = g_qc_bf + (size_t)b * LQ * F;
    for (int idx = tid; idx < 32 * (DP / 8); idx += 256) {
        int row = idx / (DP / 8), s8 = idx % (DP / 8);
        *(uint4*)&Qi[row * QSI + s8 * 8] = *(const uint4*)&Qig[(size_t)row * DP + s8 * 8];
    }
    for (int idx = tid; idx < 32 * (F / 8); idx += 256) {
        int row = idx / (F / 8), s8 = idx % (F / 8);
        *(uint4*)&Qc[row * QSC + s8 * 8] = *(const uint4*)&Qcg[(size_t)row * F + s8 * 8];
    }
    if (tid < 32) {
        qns[tid]  = g_qn[b * LQ + tid];
        qcns[tid] = sqrtf(g_qcn2[b * LQ + tid]);
        qmk[tid]  = question[b * LQ + tid] > 0;
    }
    for (int idx = tid; idx < 128; idx += 256) {
        int sent = idx >> 6, l = idx & 63;
        smk[idx] = (l < LS) ? (sentences[((size_t)b * NS + n0 + sent) * LS + l] > 0) : 0;
    }
    if (tid < 7) Wc[tid] = (tid < 6) ? Wg[tid] : biasg[0];
    __syncthreads();

    const float* sn0i = g_sn   + (size_t)b * LT + (size_t)n0 * LS;
    const float* sn1i = sn0i + LS;
    const float* sn0c = g_scn2 + (size_t)b * LT + (size_t)n0 * LS;
    const float* sn1c = sn0c + LS;
    const __nv_bfloat16* S0i = g_se_bf + ((size_t)b * LT + (size_t)n0 * LS) * DP;
    const __nv_bfloat16* S0c = g_sc_bf + ((size_t)b * LT + (size_t)n0 * LS) * F;

    const float thr = (float)(1.0 - 1e-5);

    // ---- phase A: sim_ins (norm arrays hold true norms) ----
    sim_phase<DP, DP, false>(sbS, sbQi, S0i, S0i + (size_t)LS * DP, simbuf, qns, sn0i, sn1i, tid);
    __syncthreads();
    if (tid < 64) {
        int sent = tid >> 5, q = tid & 31;
        bool qm = qmk[q] != 0;
        float ti[5] = {-INFINITY, -INFINITY, -INFINITY, -INFINITY, -INFINITY};
        int cnt = 0;
        const float* col = simbuf + sent * 64 * 32 + q;
        const int* sm = smk + sent * 64;
        for (int l = 0; l < LS; ++l) {
            float v = col[l * 32];
            if (v >= thr) ++cnt;                  // oh channel: UNMASKED sim
            float mv = (qm && sm[l]) ? v : 0.0f;
            insert5(ti, mv);
        }
        float insMean = (ti[0] + ti[1] + ti[2] + ti[3] + ti[4]) * 0.2f;
        float ohMax   = (cnt > 0) ? 1.0f : 0.0f;
        float ohMean  = fminf((float)cnt, 5.0f) * 0.2f;
        zbuf[tid] = Wc[0] * ti[0] + Wc[1] * insMean + Wc[4] * ohMax + Wc[5] * ohMean;
    }
    __syncthreads();

    // ---- phase B: sim_sen (norm arrays hold sumsq -> sqrt inside) ----
    sim_phase<F, F, true>(sbS, sbQc, S0c, S0c + (size_t)LS * F, simbuf, qcns, sn0c, sn1c, tid);
    __syncthreads();
    if (tid < 64) {
        int sent = tid >> 5, q = tid & 31;
        bool qm = qmk[q] != 0;
        float tc[5] = {-INFINITY, -INFINITY, -INFINITY, -INFINITY, -INFINITY};
        const float* col = simbuf + sent * 64 * 32 + q;
        const int* sm = smk + sent * 64;
        for (int l = 0; l < LS; ++l) {
            float v = col[l * 32];
            float mv = (qm && sm[l]) ? v : 0.0f;
            insert5(tc, mv);
        }
        float senMean = (tc[0] + tc[1] + tc[2] + tc[3] + tc[4]) * 0.2f;
        float z = zbuf[tid] + Wc[2] * tc[0] + Wc[3] * senMean + Wc[6];
        float p = 1.0f / (1.0f + expf(-z));
        #pragma unroll
        for (int o = 16; o; o >>= 1) p += __shfl_xor_sync(0xffffffffu, p, o);
        if (q == 0) {
            float sr = p * (1.0f / (float)LQ);
            int bn = b * NS + n0 + sent;
            g_sentrel[bn] = sr;
            if (out_sent) out_sent[bn] = sr;
        }
    }
}

// ---------------- doc max + BCE losses ----------------
__global__ void final_kernel(const int* __restrict__ tsents,
                             const int* __restrict__ tdocs,
                             float* __restrict__ out_loss,
                             float* __restrict__ out_doc) {
    __shared__ float red[256];
    __shared__ float docs_s[Bq];
    int tid = threadIdx.x;
    const float eps = 1e-7f;
    const float hi  = (float)(1.0 - 1e-7);

    float s1 = 0.0f;
    for (int i = tid; i < Bq * NS; i += 256) {
        float p = fminf(fmaxf(g_sentrel[i], eps), hi);
        float t = (float)tsents[i];
        s1 += t * logf(p) + (1.0f - t) * log1pf(-p);
    }
    red[tid] = s1;
    __syncthreads();
    for (int s = 128; s > 0; s >>= 1) {
        if (tid < s) red[tid] += red[tid + s];
        __syncthreads();
    }
    float bce1 = -red[0] / (float)(Bq * NS);
    __syncthreads();

    if (tid < Bq) {
        float m = -INFINITY;
        for (int n = 0; n < NS; ++n) m = fmaxf(m, g_sentrel[tid * NS + n]);
        docs_s[tid] = m;
        if (out_doc) out_doc[tid] = m;
    }
    __syncthreads();

    float s2 = 0.0f;
    if (tid < Bq) {
        float p = fminf(fmaxf(docs_s[tid], eps), hi);
        float t = (float)tdocs[tid];
        s2 = t * logf(p) + (1.0f - t) * log1pf(-p);
    }
    red[tid] = s2;
    __syncthreads();
    for (int s = 128; s > 0; s >>= 1) {
        if (tid < s) red[tid] += red[tid + s];
        __syncthreads();
    }
    if (tid == 0) {
        float bce2 = -red[0] / (float)Bq;
        out_loss[0] = 0.5f * (bce1 + bce2);
    }
}

// ---------------- host ----------------
extern "C" void kernel_launch(void* const* d_in, const int* in_sizes, int n_in,
                              void* d_out, int out_size) {
    const int *sentences = nullptr, *question = nullptr, *tsents = nullptr, *tdocs = nullptr;
    const float *embeds = nullptr, *filters = nullptr, *W = nullptr, *bias = nullptr;

    for (int i = 0; i < n_in; ++i) {
        switch (in_sizes[i]) {
            case SROWS:        sentences = (const int*)d_in[i];  break;
            case QROWS:        question  = (const int*)d_in[i];  break;
            case Bq * NS:      tsents    = (const int*)d_in[i];  break;
            case Bq:           tdocs     = (const int*)d_in[i];  break;
            case Vv * D:       embeds    = (const float*)d_in[i]; break;
            case F * FS * D:   filters   = (const float*)d_in[i]; break;
            case 6:            W         = (const float*)d_in[i]; break;
            case 1:            bias      = (const float*)d_in[i]; break;
            default: break;
        }
    }

    float* out = (float*)d_out;
    float* out_sent = (out_size >= 1 + Bq * NS)      ? out + 1            : nullptr;
    float* out_doc  = (out_size >= 1 + Bq * NS + Bq) ? out + 1 + Bq * NS  : nullptr;

    cudaFuncSetAttribute(simpool_kernel, cudaFuncAttributeMaxDynamicSharedMemorySize, SMEM_SP);

    // 0: zero sumsq accumulators (graph replays need this every launch)
    zero_cn2_kernel<<<(SROWS + 255) / 256, 256>>>();

    // 1: filters -> e4m3
    filt_convert_kernel<<<(F * FS * D + 255) / 256, 256>>>(filters);

    // 2-3: gather embeddings (bf16 + e4m3) + norms
    gather_norm_kernel<<<(QROWS * 32 + 255) / 256, 256>>>(embeds, question, QROWS, 0);
    gather_norm_kernel<<<(SROWS * 32 + 255) / 256, 256>>>(embeds, sentences, SROWS, 1);

    // 4: unified conv (sentences + question in one launch) + fused row sumsq
    conv_mma_kernel<<<dim3(STILES + QTILES, F / 128), 256>>>();

    // 5: fused sim + pool (sims stay in smem)
    simpool_kernel<<<dim3(NS / 2, Bq), 256, SMEM_SP>>>(question, sentences, W, bias, out_sent);

    // 6: doc max + BCE
    final_kernel<<<1, 256>>>(tsents, tdocs, out, out_doc);
}

// round 14
// speedup vs baseline: 3.4437x; 1.0392x over previous
#include <cuda_runtime.h>
#include <cuda_bf16.h>
#include <cuda_fp8.h>
#include <cstdint>
#include <math.h>

// ---------------- problem constants ----------------
constexpr int Bq   = 64;     // batch
constexpr int NS   = 50;     // sentences per doc
constexpr int LS   = 60;     // sentence length
constexpr int LQ   = 32;     // question length
constexpr int D    = 300;    // embedding dim
constexpr int DP   = 320;    // padded embedding dim
constexpr int F    = 256;    // conv filters
constexpr int FS   = 3;      // filter size
constexpr int Vv   = 100000; // vocab
constexpr int QROWS = Bq * LQ;        // 2048
constexpr int SROWS = Bq * NS * LS;   // 192000
constexpr int LT    = NS * LS;        // 3000

constexpr int STK  = 64;            // K fp8 per conv stage -> 64B rows
constexpr int STPT = DP / STK;      // 5 stages per tap
constexpr int NSTG = FS * STPT;     // 15 stages

constexpr int STILES = SROWS / 128; // 1500 sentence conv tiles
constexpr int QTILES = QROWS / 128; // 16 question conv tiles

// conv dynamic smem: A 3x8KB @0, B 3x8KB @24576
constexpr int SMEM_CONV = 49152;

// simpool dynamic-smem layout (byte offsets)
constexpr int OQI   = 0;        // Q ins tile: 32 x 328 bf16 = 20992
constexpr int OQC   = 20992;    // Q conv tile: 32 x 264 bf16 = 16896 -> 37888
constexpr int OSS   = 38912;    // S pipe: 3 x 8KB -> 63488
constexpr int OSB   = 63488;    // simbuf: 128 x 32 fp32 -> 79872
constexpr int OMISC = 79872;    // qns(128) qcns(128) zbuf(256) smk(512) qmk(128) W(32)
constexpr int SMEM_SP = 81152;

// ---------------- device scratch (no allocs; zero-init at load) ----------------
__device__ __nv_bfloat16 g_qe_bf[(QROWS + 2) * DP];
__device__ __nv_bfloat16 g_se_bf[(SROWS + 2) * DP];
__device__ uint8_t g_qe_f8[(QROWS + 2) * DP];
__device__ uint8_t g_se_f8[(SROWS + 2) * DP];
__device__ uint8_t g_filt_f8[F * FS * DP];
__device__ float g_qn[QROWS];
__device__ float g_sn[SROWS];
__device__ __nv_bfloat16 g_qc_bf[QROWS * F];
__device__ __nv_bfloat16 g_sc_bf[SROWS * F];
__device__ float g_qcn2[QROWS];   // sumsq of conv(question) rows (atomically built)
__device__ float g_scn2[SROWS];   // sumsq of conv(sentences) rows
__device__ float g_sentrel[Bq * NS];

// ---------------- asm helpers ----------------
__device__ __forceinline__ void mma_bf16(float* c,
                                         uint32_t a0, uint32_t a1, uint32_t a2, uint32_t a3,
                                         uint32_t b0, uint32_t b1) {
    asm volatile("mma.sync.aligned.m16n8k16.row.col.f32.bf16.bf16.f32 "
                 "{%0,%1,%2,%3},{%4,%5,%6,%7},{%8,%9},{%0,%1,%2,%3};"
                 : "+f"(c[0]), "+f"(c[1]), "+f"(c[2]), "+f"(c[3])
                 : "r"(a0), "r"(a1), "r"(a2), "r"(a3), "r"(b0), "r"(b1));
}
__device__ __forceinline__ void mma_fp8(float* c,
                                        uint32_t a0, uint32_t a1, uint32_t a2, uint32_t a3,
                                        uint32_t b0, uint32_t b1) {
    asm volatile("mma.sync.aligned.m16n8k32.row.col.f32.e4m3.e4m3.f32 "
                 "{%0,%1,%2,%3},{%4,%5,%6,%7},{%8,%9},{%0,%1,%2,%3};"
                 : "+f"(c[0]), "+f"(c[1]), "+f"(c[2]), "+f"(c[3])
                 : "r"(a0), "r"(a1), "r"(a2), "r"(a3), "r"(b0), "r"(b1));
}
__device__ __forceinline__ void ldsm4(uint32_t& r0, uint32_t& r1, uint32_t& r2, uint32_t& r3,
                                      uint32_t addr) {
    asm volatile("ldmatrix.sync.aligned.m8n8.x4.shared.b16 {%0,%1,%2,%3}, [%4];"
                 : "=r"(r0), "=r"(r1), "=r"(r2), "=r"(r3) : "r"(addr));
}
__device__ __forceinline__ void cp_async16(uint32_t dst, const void* src, uint32_t srcsz) {
    asm volatile("cp.async.ca.shared.global [%0], [%1], 16, %2;"
                 :: "r"(dst), "l"(src), "r"(srcsz));
}
__device__ __forceinline__ void cp_commit() { asm volatile("cp.async.commit_group;" ::: "memory"); }
__device__ __forceinline__ void cp_wait0()  { asm volatile("cp.async.wait_group 0;" ::: "memory"); }
__device__ __forceinline__ void cp_wait1()  { asm volatile("cp.async.wait_group 1;" ::: "memory"); }

// ---------------- zero the sumsq accumulators (every launch; graphs replay) ----
__global__ void zero_cn2_kernel() {
    int i = blockIdx.x * blockDim.x + threadIdx.x;
    if (i < SROWS) g_scn2[i] = 0.0f;
    if (i < QROWS) g_qcn2[i] = 0.0f;
}

// ---------------- unified gather -> bf16 + fp8 + norm (float4 exact) ----------------
__global__ void gather_norm_kernel(const float* __restrict__ embeds,
                                   const int* __restrict__ question,
                                   const int* __restrict__ sentences) {
    int warp = (blockIdx.x * blockDim.x + threadIdx.x) >> 5;
    int lane = threadIdx.x & 31;
    if (warp >= QROWS + SROWS) return;
    bool isq = warp < QROWS;
    int r = isq ? warp : warp - QROWS;
    int tok = isq ? question[r] : sentences[r];
    __nv_bfloat16* brow = (isq ? g_qe_bf : g_se_bf) + (size_t)r * DP;
    uint8_t*       frow = (isq ? g_qe_f8 : g_se_f8) + (size_t)r * DP;
    float*         nrm  = (isq ? g_qn    : g_sn);
    const float* src = embeds + (size_t)tok * D;

    float ss = 0.0f;
    #pragma unroll
    for (int it = 0; it < 3; ++it) {
        int i = lane * 4 + it * 128;
        if (i < D) {                                 // 300 = 32+32+11 exact float4s
            float4 v = *(const float4*)&src[i];
            __nv_bfloat16 b0 = __float2bfloat16(v.x);
            __nv_bfloat16 b1 = __float2bfloat16(v.y);
            __nv_bfloat16 b2 = __float2bfloat16(v.z);
            __nv_bfloat16 b3 = __float2bfloat16(v.w);
            __nv_bfloat162 p01 = __halves2bfloat162(b0, b1);
            __nv_bfloat162 p23 = __halves2bfloat162(b2, b3);
            uint2 pk; pk.x = *(uint32_t*)&p01; pk.y = *(uint32_t*)&p23;
            *(uint2*)&brow[i] = pk;
            __nv_fp8_e4m3 f0(v.x), f1(v.y), f2(v.z), f3(v.w);
            uchar4 fc;
            fc.x = *(uint8_t*)&f0; fc.y = *(uint8_t*)&f1;
            fc.z = *(uint8_t*)&f2; fc.w = *(uint8_t*)&f3;
            *(uchar4*)&frow[i] = fc;
            float x0 = __bfloat162float(b0), x1 = __bfloat162float(b1);
            float x2 = __bfloat162float(b2), x3 = __bfloat162float(b3);
            ss += x0 * x0 + x1 * x1 + x2 * x2 + x3 * x3;
        }
    }
    #pragma unroll
    for (int o = 16; o; o >>= 1) ss += __shfl_xor_sync(0xffffffffu, ss, o);
    if (lane == 0) nrm[r] = sqrtf(ss);
}

// ---------------- filter fp32 -> e4m3 ----------------
__global__ void filt_convert_kernel(const float* __restrict__ filt) {
    int idx = blockIdx.x * blockDim.x + threadIdx.x;
    if (idx >= F * FS * D) return;
    int f = idx / (FS * D);
    int r = idx % (FS * D);
    int t = r / D;
    int k = r % D;
    __nv_fp8_e4m3 f8(filt[idx]);
    g_filt_f8[((size_t)f * FS + t) * DP + k] = *(uint8_t*)&f8;
}

// ============================================================================
// unified conv (sentences + question, one launch). e4m3 MMA m16n8k32,
// 3-deep cp.async pipeline (prefetch distance 2 hides DRAM latency),
// 2 CTAs/SM. Epilogue stores bf16 + accumulates per-row sumsq.
// ============================================================================
__global__ void __launch_bounds__(256, 2) conv_mma_kernel() {
    const int bx  = blockIdx.x;
    const bool isq = (bx >= STILES);
    const uint8_t* X   = isq ? g_qe_f8 : g_se_f8;
    __nv_bfloat16* out = isq ? g_qc_bf : g_sc_bf;
    float* cn2         = isq ? g_qcn2  : g_scn2;
    const int seg      = isq ? LQ : LS;
    const int rbase    = (isq ? (bx - STILES) : bx) * 128;

    extern __shared__ __align__(16) uint8_t sm[];   // A: 3x8KB @0, B: 3x8KB @24576
    uint32_t sb = (uint32_t)__cvta_generic_to_shared(sm);

    const int tid  = threadIdx.x;
    const int lane = tid & 31;
    const int wid  = tid >> 5;
    const int wm   = (wid & 3) * 32;
    const int wn   = (wid >> 2) * 64;
    const int m    = lane >> 3;
    const int rr   = lane & 7;

    const int fbase = blockIdx.y * 128;

    const int arow  = tid >> 1;
    const int hbase = (tid & 1) * 2;
    const int gr    = rbase + arow;
    const int lpos  = gr % seg;
    const int gf    = fbase + arow;
    const int swz   = (arow >> 1) & 3;

    float acc[2][8][4];
    #pragma unroll
    for (int i = 0; i < 2; ++i)
        #pragma unroll
        for (int j = 0; j < 8; ++j)
            #pragma unroll
            for (int v = 0; v < 4; ++v) acc[i][j][v] = 0.0f;

    auto issue = [&](int s, int buf) {
        int tap = s / STPT;
        int kc  = (s % STPT) * STK;
        uint32_t asz = ((lpos + tap) < seg) ? 16u : 0u;
        const uint8_t* ap = X + (size_t)(gr + tap) * DP + kc;
        const uint8_t* bp = g_filt_f8 + ((size_t)gf * FS + tap) * DP + kc;
        #pragma unroll
        for (int e = 0; e < 2; ++e) {
            int h = hbase + e;
            int phys = h ^ swz;
            uint32_t da = sb + buf * 8192 + arow * 64 + phys * 16;
            uint32_t db = da + 24576;
            cp_async16(da, ap + h * 16, asz);
            cp_async16(db, bp + h * 16, 16u);
        }
    };

    issue(0, 0); cp_commit();
    issue(1, 1); cp_commit();

    for (int s = 0; s < NSTG; ++s) {
        if (s + 1 < NSTG) cp_wait1(); else cp_wait0();
        __syncthreads();
        if (s + 2 < NSTG) { issue(s + 2, (s + 2) % 3); cp_commit(); }
        uint32_t abase = sb + (s % 3) * 8192;
        uint32_t bbase = abase + 24576;

        #pragma unroll
        for (int c = 0; c < 2; ++c) {
            uint32_t a[2][4];
            #pragma unroll
            for (int i = 0; i < 2; ++i) {
                int rowA = wm + i * 16 + (m & 1) * 8 + rr;
                int phys = (2 * c + (m >> 1)) ^ ((rowA >> 1) & 3);
                ldsm4(a[i][0], a[i][1], a[i][2], a[i][3],
                      abase + (uint32_t)(rowA * 64 + phys * 16));
            }
            uint32_t bbv[8][2];
            #pragma unroll
            for (int jp = 0; jp < 4; ++jp) {
                int rowB = wn + (jp * 2 + (m >> 1)) * 8 + rr;
                int phys = (2 * c + (m & 1)) ^ ((rowB >> 1) & 3);
                ldsm4(bbv[2 * jp][0], bbv[2 * jp][1], bbv[2 * jp + 1][0], bbv[2 * jp + 1][1],
                      bbase + (uint32_t)(rowB * 64 + phys * 16));
            }
            #pragma unroll
            for (int j = 0; j < 8; ++j)
                #pragma unroll
                for (int i = 0; i < 2; ++i)
                    mma_fp8(acc[i][j], a[i][0], a[i][1], a[i][2], a[i][3],
                            bbv[j][0], bbv[j][1]);
        }
        __syncthreads();
    }

    // ---- epilogue: bf16 store + per-row sumsq (of the ROUNDED values) ----
    const int g   = lane >> 2;
    const int tig = lane & 3;
    #pragma unroll
    for (int i = 0; i < 2; ++i) {
        int r0 = rbase + wm + i * 16 + g;
        float sq0 = 0.0f, sq8 = 0.0f;
        #pragma unroll
        for (int j = 0; j < 8; ++j) {
            int col = fbase + wn + j * 8 + tig * 2;
            __nv_bfloat16 h0 = __float2bfloat16(acc[i][j][0]);
            __nv_bfloat16 h1 = __float2bfloat16(acc[i][j][1]);
            __nv_bfloat16 h2 = __float2bfloat16(acc[i][j][2]);
            __nv_bfloat16 h3 = __float2bfloat16(acc[i][j][3]);
            __nv_bfloat16* o0 = out + (size_t)r0 * F + col;
            *(__nv_bfloat162*)o0 = __halves2bfloat162(h0, h1);
            *(__nv_bfloat162*)(o0 + (size_t)8 * F) = __halves2bfloat162(h2, h3);
            float f0 = __bfloat162float(h0), f1 = __bfloat162float(h1);
            float f2 = __bfloat162float(h2), f3 = __bfloat162float(h3);
            sq0 += f0 * f0 + f1 * f1;
            sq8 += f2 * f2 + f3 * f3;
        }
        sq0 += __shfl_xor_sync(0xffffffffu, sq0, 1);
        sq0 += __shfl_xor_sync(0xffffffffu, sq0, 2);
        sq8 += __shfl_xor_sync(0xffffffffu, sq8, 1);
        sq8 += __shfl_xor_sync(0xffffffffu, sq8, 2);
        if (tig == 0) {
            atomicAdd(&cn2[r0], sq0);
            atomicAdd(&cn2[r0 + 8], sq8);
        }
    }
}

// ============================================================================
// fused sim + pool
// ============================================================================
__device__ __forceinline__ void insert5(float* t, float v) {
    if (v > t[4]) {
        t[4] = v;
        #pragma unroll
        for (int i = 4; i > 0; --i) {
            if (t[i] > t[i - 1]) { float tmp = t[i - 1]; t[i - 1] = t[i]; t[i] = tmp; }
        }
    }
}

// one sim phase: MMA over KT, normalized result -> simbuf (128 rows x 32 q)
// 3-deep cp.async pipeline. SQN: sentence-norm array holds sumsq (apply sqrtf)
template<int KT, int STRIDE, bool SQN>
__device__ __forceinline__ void sim_phase(
    uint32_t sbS, uint32_t sbQ,
    const __nv_bfloat16* __restrict__ S0,
    const __nv_bfloat16* __restrict__ S1,
    float* __restrict__ simbuf,
    const float* __restrict__ qns,
    const float* __restrict__ sn0,
    const float* __restrict__ sn1,
    int tid)
{
    constexpr int STG = KT / 32;
    constexpr int QS  = KT + 8;

    const int lane = tid & 31;
    const int wid  = tid >> 5;
    const int m    = lane >> 3;
    const int rr   = lane & 7;

    const int srow  = tid >> 1;
    const int hbase = (tid & 1) * 2;
    const int sl    = srow & 63;
    const int ssent = srow >> 6;
    const int swz   = (srow >> 1) & 3;
    const uint32_t ssz = (sl < LS) ? 16u : 0u;
    const __nv_bfloat16* srcrow = (ssent ? S1 : S0) + (size_t)sl * STRIDE;

    auto issueS = [&](int s, int buf) {
        int kc = s * 32;
        #pragma unroll
        for (int e = 0; e < 2; ++e) {
            int h = hbase + e;
            int phys = h ^ swz;
            cp_async16(sbS + buf * 8192 + srow * 64 + phys * 16, srcrow + kc + h * 8, ssz);
        }
    };

    float acc[4][4];
    #pragma unroll
    for (int t = 0; t < 4; ++t)
        #pragma unroll
        for (int v = 0; v < 4; ++v) acc[t][v] = 0.0f;

    issueS(0, 0); cp_commit();
    issueS(1, 1); cp_commit();

    for (int s = 0; s < STG; ++s) {
        if (s + 1 < STG) cp_wait1(); else cp_wait0();
        __syncthreads();
        if (s + 2 < STG) { issueS(s + 2, (s + 2) % 3); cp_commit(); }
        uint32_t abase = sbS + (s % 3) * 8192;

        #pragma unroll
        for (int c = 0; c < 2; ++c) {
            uint32_t a[4];
            int rowS = wid * 16 + (m & 1) * 8 + rr;
            int phys = (2 * c + (m >> 1)) ^ ((rowS >> 1) & 3);
            ldsm4(a[0], a[1], a[2], a[3], abase + (uint32_t)(rowS * 64 + phys * 16));

            int cg = s * 2 + c;
            uint32_t qb[4][2];
            #pragma unroll
            for (int jp = 0; jp < 2; ++jp) {
                int rowq = (jp * 2 + (m >> 1)) * 8 + rr;
                uint32_t qaddr = sbQ + (uint32_t)(rowq * (QS * 2) + (cg * 16 + (m & 1) * 8) * 2);
                ldsm4(qb[2 * jp][0], qb[2 * jp][1], qb[2 * jp + 1][0], qb[2 * jp + 1][1], qaddr);
            }
            #pragma unroll
            for (int t = 0; t < 4; ++t)
                mma_bf16(acc[t], a[0], a[1], a[2], a[3], qb[t][0], qb[t][1]);
        }
        __syncthreads();
    }

    const int g   = lane >> 2;
    const int tig = lane & 3;
    int l0 = wid * 16 + g;
    int l1 = l0 + 8;
    int li0 = l0 & 63, li1 = l1 & 63;
    float r0 = (li0 < LS) ? ((l0 >> 6) ? sn1[li0] : sn0[li0]) : 1.0f;
    float r1 = (li1 < LS) ? ((l1 >> 6) ? sn1[li1] : sn0[li1]) : 1.0f;
    float n0 = SQN ? sqrtf(r0) : r0;
    float n1 = SQN ? sqrtf(r1) : r1;
    #pragma unroll
    for (int t = 0; t < 4; ++t) {
        int q0 = t * 8 + tig * 2;
        float i0 = 1.0f / (qns[q0] * n0), i1 = 1.0f / (qns[q0 + 1] * n0);
        float i2 = 1.0f / (qns[q0] * n1), i3 = 1.0f / (qns[q0 + 1] * n1);
        if (li0 < LS) {
            simbuf[l0 * 32 + q0]     = acc[t][0] * i0;
            simbuf[l0 * 32 + q0 + 1] = acc[t][1] * i1;
        }
        if (li1 < LS) {
            simbuf[l1 * 32 + q0]     = acc[t][2] * i2;
            simbuf[l1 * 32 + q0 + 1] = acc[t][3] * i3;
        }
    }
}

__global__ void __launch_bounds__(256, 2) simpool_kernel(
    const int* __restrict__ question,
    const int* __restrict__ sentences,
    const float* __restrict__ Wg,
    const float* __restrict__ biasg,
    float* __restrict__ out_sent)
{
    extern __shared__ __align__(16) uint8_t dyn[];
    __nv_bfloat16* Qi = (__nv_bfloat16*)(dyn + OQI);
    __nv_bfloat16* Qc = (__nv_bfloat16*)(dyn + OQC);
    float* simbuf = (float*)(dyn + OSB);
    float* qns  = (float*)(dyn + OMISC);
    float* qcns = (float*)(dyn + OMISC + 128);
    float* zbuf = (float*)(dyn + OMISC + 256);
    int*   smk  = (int*)(dyn + OMISC + 512);
    int*   qmk  = (int*)(dyn + OMISC + 1024);
    float* Wc   = (float*)(dyn + OMISC + 1152);
    uint32_t sbS  = (uint32_t)__cvta_generic_to_shared(dyn + OSS);
    uint32_t sbQi = (uint32_t)__cvta_generic_to_shared(Qi);
    uint32_t sbQc = (uint32_t)__cvta_generic_to_shared(Qc);

    const int tid = threadIdx.x;
    const int b   = blockIdx.y;
    const int n0  = blockIdx.x * 2;

    constexpr int QSI = DP + 8, QSC = F + 8;
    const __nv_bfloat16* Qig = g_qe_bf + (size_t)b * LQ * DP;
    const __nv_bfloat16* Qcg = g_qc_bf + (size_t)b * LQ * F;
    for (int idx = tid; idx < 32 * (DP / 8); idx += 256) {
        int row = idx / (DP / 8), s8 = idx % (DP / 8);
        *(uint4*)&Qi[row * QSI + s8 * 8] = *(const uint4*)&Qig[(size_t)row * DP + s8 * 8];
    }
    for (int idx = tid; idx < 32 * (F / 8); idx += 256) {
        int row = idx / (F / 8), s8 = idx % (F / 8);
        *(uint4*)&Qc[row * QSC + s8 * 8] = *(const uint4*)&Qcg[(size_t)row * F + s8 * 8];
    }
    if (tid < 32) {
        qns[tid]  = g_qn[b * LQ + tid];
        qcns[tid] = sqrtf(g_qcn2[b * LQ + tid]);
        qmk[tid]  = question[b * LQ + tid] > 0;
    }
    for (int idx = tid; idx < 128; idx += 256) {
        int sent = idx >> 6, l = idx & 63;
        smk[idx] = (l < LS) ? (sentences[((size_t)b * NS + n0 + sent) * LS + l] > 0) : 0;
    }
    if (tid < 7) Wc[tid] = (tid < 6) ? Wg[tid] : biasg[0];
    __syncthreads();

    const float* sn0i = g_sn   + (size_t)b * LT + (size_t)n0 * LS;
    const float* sn1i = sn0i + LS;
    const float* sn0c = g_scn2 + (size_t)b * LT + (size_t)n0 * LS;
    const float* sn1c = sn0c + LS;
    const __nv_bfloat16* S0i = g_se_bf + ((size_t)b * LT + (size_t)n0 * LS) * DP;
    const __nv_bfloat16* S0c = g_sc_bf + ((size_t)b * LT + (size_t)n0 * LS) * F;

    const float thr = (float)(1.0 - 1e-5);

    // pooling role: 64 (sent,q) groups x 4 threads; each thread covers 15 l's
    const int grp = tid >> 2;          // 0..63
    const int sub = tid & 3;
    const int psent = grp >> 5, pq = grp & 31;

    // ---- phase A: sim_ins ----
    sim_phase<DP, DP, false>(sbS, sbQi, S0i, S0i + (size_t)LS * DP, simbuf, qns, sn0i, sn1i, tid);
    __syncthreads();
    {
        bool qm = qmk[pq] != 0;
        const float* col = simbuf + psent * 64 * 32 + pq;
        const int* sm = smk + psent * 64;
        float ti[5] = {-INFINITY, -INFINITY, -INFINITY, -INFINITY, -INFINITY};
        int cnt = 0;
        int lb = sub * 15;
        for (int l = lb; l < lb + 15; ++l) {
            float v = col[l * 32];
            if (v >= thr) ++cnt;                  // oh channel: UNMASKED sim
            float mv = (qm && sm[l]) ? v : 0.0f;
            insert5(ti, mv);
        }
        #pragma unroll
        for (int off = 1; off <= 2; off <<= 1) {
            cnt += __shfl_xor_sync(0xffffffffu, cnt, off);
            float ov[5];
            #pragma unroll
            for (int k = 0; k < 5; ++k) ov[k] = __shfl_xor_sync(0xffffffffu, ti[k], off);
            #pragma unroll
            for (int k = 0; k < 5; ++k) insert5(ti, ov[k]);
        }
        if (sub == 0) {
            float insMean = (ti[0] + ti[1] + ti[2] + ti[3] + ti[4]) * 0.2f;
            float ohMax   = (cnt > 0) ? 1.0f : 0.0f;
            float ohMean  = fminf((float)cnt, 5.0f) * 0.2f;
            zbuf[grp] = Wc[0] * ti[0] + Wc[1] * insMean + Wc[4] * ohMax + Wc[5] * ohMean;
        }
    }
    __syncthreads();

    // ---- phase B: sim_sen ----
    sim_phase<F, F, true>(sbS, sbQc, S0c, S0c + (size_t)LS * F, simbuf, qcns, sn0c, sn1c, tid);
    __syncthreads();
    {
        bool qm = qmk[pq] != 0;
        const float* col = simbuf + psent * 64 * 32 + pq;
        const int* sm = smk + psent * 64;
        float tc[5] = {-INFINITY, -INFINITY, -INFINITY, -INFINITY, -INFINITY};
        int lb = sub * 15;
        for (int l = lb; l < lb + 15; ++l) {
            float v = col[l * 32];
            float mv = (qm && sm[l]) ? v : 0.0f;
            insert5(tc, mv);
        }
        #pragma unroll
        for (int off = 1; off <= 2; off <<= 1) {
            float ov[5];
            #pragma unroll
            for (int k = 0; k < 5; ++k) ov[k] = __shfl_xor_sync(0xffffffffu, tc[k], off);
            #pragma unroll
            for (int k = 0; k < 5; ++k) insert5(tc, ov[k]);
        }
        if (sub == 0) {
            float senMean = (tc[0] + tc[1] + tc[2] + tc[3] + tc[4]) * 0.2f;
            float z = zbuf[grp] + Wc[2] * tc[0] + Wc[3] * senMean + Wc[6];
            zbuf[grp] = 1.0f / (1.0f + expf(-z));   // reuse zbuf as p-buffer
        }
    }
    __syncthreads();
    if (tid < 2) {
        float s = 0.0f;
        for (int q = 0; q < 32; ++q) s += zbuf[tid * 32 + q];
        float sr = s * (1.0f / (float)LQ);
        int bn = b * NS + n0 + tid;
        g_sentrel[bn] = sr;
        if (out_sent) out_sent[bn] = sr;
    }
}

// ---------------- doc max + BCE losses ----------------
__global__ void final_kernel(const int* __restrict__ tsents,
                             const int* __restrict__ tdocs,
                             float* __restrict__ out_loss,
                             float* __restrict__ out_doc) {
    __shared__ float red[256];
    __shared__ float docs_s[Bq];
    int tid = threadIdx.x;
    const float eps = 1e-7f;
    const float hi  = (float)(1.0 - 1e-7);

    float s1 = 0.0f;
    for (int i = tid; i < Bq * NS; i += 256) {
        float p = fminf(fmaxf(g_sentrel[i], eps), hi);
        float t = (float)tsents[i];
        s1 += t * logf(p) + (1.0f - t) * log1pf(-p);
    }
    red[tid] = s1;
    __syncthreads();
    for (int s = 128; s > 0; s >>= 1) {
        if (tid < s) red[tid] += red[tid + s];
        __syncthreads();
    }
    float bce1 = -red[0] / (float)(Bq * NS);
    __syncthreads();

    if (tid < Bq) {
        float m = -INFINITY;
        for (int n = 0; n < NS; ++n) m = fmaxf(m, g_sentrel[tid * NS + n]);
        docs_s[tid] = m;
        if (out_doc) out_doc[tid] = m;
    }
    __syncthreads();

    float s2 = 0.0f;
    if (tid < Bq) {
        float p = fminf(fmaxf(docs_s[tid], eps), hi);
        float t = (float)tdocs[tid];
        s2 = t * logf(p) + (1.0f - t) * log1pf(-p);
    }
    red[tid] = s2;
    __syncthreads();
    for (int s = 128; s > 0; s >>= 1) {
        if (tid < s) red[tid] += red[tid + s];
        __syncthreads();
    }
    if (tid == 0) {
        float bce2 = -red[0] / (float)Bq;
        out_loss[0] = 0.5f * (bce1 + bce2);
    }
}

// ---------------- host ----------------
extern "C" void kernel_launch(void* const* d_in, const int* in_sizes, int n_in,
                              void* d_out, int out_size) {
    const int *sentences = nullptr, *question = nullptr, *tsents = nullptr, *tdocs = nullptr;
    const float *embeds = nullptr, *filters = nullptr, *W = nullptr, *bias = nullptr;

    for (int i = 0; i < n_in; ++i) {
        switch (in_sizes[i]) {
            case SROWS:        sentences = (const int*)d_in[i];  break;
            case QROWS:        question  = (const int*)d_in[i];  break;
            case Bq * NS:      tsents    = (const int*)d_in[i];  break;
            case Bq:           tdocs     = (const int*)d_in[i];  break;
            case Vv * D:       embeds    = (const float*)d_in[i]; break;
            case F * FS * D:   filters   = (const float*)d_in[i]; break;
            case 6:            W         = (const float*)d_in[i]; break;
            case 1:            bias      = (const float*)d_in[i]; break;
            default: break;
        }
    }

    float* out = (float*)d_out;
    float* out_sent = (out_size >= 1 + Bq * NS)      ? out + 1            : nullptr;
    float* out_doc  = (out_size >= 1 + Bq * NS + Bq) ? out + 1 + Bq * NS  : nullptr;

    cudaFuncSetAttribute(conv_mma_kernel, cudaFuncAttributeMaxDynamicSharedMemorySize, SMEM_CONV);
    cudaFuncSetAttribute(simpool_kernel, cudaFuncAttributeMaxDynamicSharedMemorySize, SMEM_SP);

    // 0: zero sumsq accumulators (graph replays need this every launch)
    zero_cn2_kernel<<<(SROWS + 255) / 256, 256>>>();

    // 1: filters -> e4m3
    filt_convert_kernel<<<(F * FS * D + 255) / 256, 256>>>(filters);

    // 2: unified gather (question + sentences) -> bf16 + e4m3 + norms
    gather_norm_kernel<<<((QROWS + SROWS) * 32 + 255) / 256, 256>>>(embeds, question, sentences);

    // 3: unified conv (3-deep pipeline) + fused row sumsq
    conv_mma_kernel<<<dim3(STILES + QTILES, F / 128), 256, SMEM_CONV>>>();

    // 4: fused sim + pool (3-deep pipeline, parallel pooling)
    simpool_kernel<<<dim3(NS / 2, Bq), 256, SMEM_SP>>>(question, sentences, W, bias, out_sent);

    // 5: doc max + BCE
    final_kernel<<<1, 256>>>(tsents, tdocs, out, out_doc);
}